// round 11
// baseline (speedup 1.0000x reference)
#include <cuda_runtime.h>
#include <cuda_fp16.h>
#include <math.h>
#include <stdint.h>

#define Bb   8
#define LL   4096
#define DIMC 512
#define SS   32
#define KK   8
#define NT   (Bb*LL)      /* 32768 tokens */
#define NC   (DIMC*2)     /* 1024 floats per token (interleaved r,i) */
#define THRv 0.5f
#define EPSv 1e-8f

/* output layout: concat(out, new_keys, new_values, new_mask, salience) */
#define OFF_OUT ((size_t)0)
#define OFF_NK  ((size_t)NT*NC)
#define OFF_NV  (OFF_NK + (size_t)Bb*SS*NC)
#define OFF_NM  (OFF_NV + (size_t)Bb*SS*NC)
#define OFF_SAL (OFF_NM + (size_t)Bb*SS)

/* scratch (device globals; no allocation allowed) */
__device__ float g_avg[NT];
__device__ float g_phase[NT];
__device__ float g_evec[Bb*SS*NC];
__device__ float g_evp[(size_t)Bb*SS*8*NC];  /* evec chunk partials, 8MB */
__device__ float g_denp[Bb*SS*8];
__device__ float g_emask[Bb*SS];
__device__ int   g_rs[Bb*SS];
__device__ int   g_re[Bb*SS];
__device__ float g_kmag[Bb*SS];
__device__ __half g_BhiT[NC*NC];          /* B^T fp16, [n][k], 2MB */
__device__ __half g_Ahi[(size_t)NT*NC];   /* z hi fp16, 64MB */
__device__ __half g_Alo[(size_t)NT*NC];   /* z lo fp16, 64MB */
__device__ float g_WrT[DIMC*DIMC];        /* W_rq_r transposed, 1MB */
__device__ float g_WiT[DIMC*DIMC];        /* W_rq_i transposed, 1MB */
__device__ __half g_uh[Bb*SS*NC];         /* u hi fp16 */
__device__ __half g_ul[Bb*SS*NC];         /* u lo fp16 */
__device__ float g_qp[(size_t)NT*4];      /* qmag^2 partials per N-block */
__device__ float g_dot[(size_t)NT*SS];    /* dot[l,s], 4MB */

__device__ __forceinline__ float wred(float v) {
    #pragma unroll
    for (int o = 16; o; o >>= 1) v += __shfl_xor_sync(0xffffffffu, v, o);
    return v;
}

__device__ __forceinline__ float fsqrt(float x) {
    float y; asm("sqrt.approx.f32 %0, %1;" : "=f"(y) : "f"(x)); return y;
}
__device__ __forceinline__ float frcp(float x) {
    float y; asm("rcp.approx.f32 %0, %1;" : "=f"(y) : "f"(x)); return y;
}
__device__ __forceinline__ float frsqrt(float x) {
    float y; asm("rsqrt.approx.f32 %0, %1;" : "=f"(y) : "f"(x)); return y;
}

__device__ __forceinline__ void hsplit(float x, __half& h, __half& l) {
    h = __float2half_rn(x);
    l = __float2half_rn(x - __half2float(h));
}

__device__ __forceinline__ uint32_t smem_u32(const void* p) {
    uint32_t a;
    asm("{ .reg .u64 t; cvta.to.shared.u64 t, %1; cvt.u32.u64 %0, t; }"
        : "=r"(a) : "l"(p));
    return a;
}

__device__ __forceinline__ void ldsm4(uint32_t* r, uint32_t addr) {
    asm volatile("ldmatrix.sync.aligned.m8n8.x4.shared.b16 {%0,%1,%2,%3}, [%4];"
        : "=r"(r[0]), "=r"(r[1]), "=r"(r[2]), "=r"(r[3]) : "r"(addr));
}

__device__ __forceinline__ void mma16816(float* d, const uint32_t* a,
                                         uint32_t b0, uint32_t b1) {
    asm volatile(
        "mma.sync.aligned.m16n8k16.row.col.f32.f16.f16.f32 "
        "{%0,%1,%2,%3}, {%4,%5,%6,%7}, {%8,%9}, {%0,%1,%2,%3};"
        : "+f"(d[0]), "+f"(d[1]), "+f"(d[2]), "+f"(d[3])
        : "r"(a[0]), "r"(a[1]), "r"(a[2]), "r"(a[3]), "r"(b0), "r"(b1));
}

#define CP16(dst, src) \
    asm volatile("cp.async.cg.shared.global [%0], [%1], 16;" \
                 :: "r"(dst), "l"(src) : "memory")
#define CP_COMMIT() asm volatile("cp.async.commit_group;" ::: "memory")
#define CP_WAIT1()  asm volatile("cp.async.wait_group 1;" ::: "memory")

/* ------------------------------------------------------------------ */
/* per-token stats only (avg mag + salience phase) — critical path */
__global__ void k_statsA(const float* __restrict__ z,
                         const float* __restrict__ Wsr,
                         const float* __restrict__ Wsi) {
    int gw = (blockIdx.x * blockDim.x + threadIdx.x) >> 5;
    int lane = threadIdx.x & 31;
    if (gw >= NT) return;
    const float4* z4 = (const float4*)(z + (size_t)gw * NC);
    float ms = 0.f, pr = 0.f, pi = 0.f;
    #pragma unroll
    for (int i = 0; i < 8; i++) {
        int p = lane + 32 * i;
        float4 v = z4[p];
        int d = 2 * p;
        ms += fsqrt(v.x*v.x + v.y*v.y + EPSv) + fsqrt(v.z*v.z + v.w*v.w + EPSv);
        float wr0 = Wsr[d], wi0 = Wsi[d], wr1 = Wsr[d+1], wi1 = Wsi[d+1];
        pr += v.x*wr0 - v.y*wi0 + v.z*wr1 - v.w*wi1;
        pi += v.x*wi0 + v.y*wr0 + v.z*wi1 + v.w*wr1;
    }
    ms = wred(ms); pr = wred(pr); pi = wred(pi);
    if (lane == 0) {
        g_avg[gw]   = ms * (1.f / DIMC);
        g_phase[gw] = fsqrt(pr*pr + pi*pi + EPSv);
    }
}

/* z -> fp16 hi/lo (runs on side stream; depends only on input z) */
__global__ void k_split(const float* __restrict__ z) {
    size_t i = ((size_t)blockIdx.x * 256 + threadIdx.x) * 8;
    float4 v0 = *(const float4*)(z + i);
    float4 v1 = *(const float4*)(z + i + 4);
    __half h[8], l[8];
    hsplit(v0.x, h[0], l[0]); hsplit(v0.y, h[1], l[1]);
    hsplit(v0.z, h[2], l[2]); hsplit(v0.w, h[3], l[3]);
    hsplit(v1.x, h[4], l[4]); hsplit(v1.y, h[5], l[5]);
    hsplit(v1.z, h[6], l[6]); hsplit(v1.w, h[7], l[7]);
    *(uint4*)(g_Ahi + i) = *(uint4*)h;
    *(uint4*)(g_Alo + i) = *(uint4*)l;
}

/* ------------------------------------------------------------------ */
__global__ void k_build_bt(const float* __restrict__ Wr,
                           const float* __restrict__ Wi) {
    __shared__ float tr[32][33], ti[32][33];
    int tx = threadIdx.x & 31, ty = threadIdx.x >> 5;
    int d0 = blockIdx.x * 32, e0 = blockIdx.y * 32;
    #pragma unroll
    for (int j = 0; j < 4; j++) {
        int d = d0 + ty + 8 * j;
        tr[ty + 8 * j][tx] = Wr[(size_t)d * DIMC + e0 + tx];
        ti[ty + 8 * j][tx] = Wi[(size_t)d * DIMC + e0 + tx];
    }
    __syncthreads();
    #pragma unroll
    for (int j = 0; j < 4; j++) {
        int e = e0 + ty + 8 * j;
        int d = d0 + tx;
        float wr = tr[tx][ty + 8 * j], wi = ti[tx][ty + 8 * j];
        size_t r0 = (size_t)(2 * e) * NC, r1 = (size_t)(2 * e + 1) * NC;
        g_BhiT[r0 + 2*d]     = __float2half_rn(wr);
        g_BhiT[r0 + 2*d + 1] = __float2half_rn(-wi);
        g_BhiT[r1 + 2*d]     = __float2half_rn(wi);
        g_BhiT[r1 + 2*d + 1] = __float2half_rn(wr);
        g_WrT[(size_t)e * DIMC + d] = wr;
        g_WiT[(size_t)e * DIMC + d] = wi;
    }
}

/* ------------------------------------------------------------------ */
/* fused salience + run detection: one block per batch */
__global__ void k_runs(float* __restrict__ out,
                       const float* __restrict__ sb,
                       const float* __restrict__ ns) {
    __shared__ float sal[LL];
    __shared__ int scnt[256];
    int b = blockIdx.x, tid = threadIdx.x;
    float nsv = ns[0], sbv = sb[0];

    int l0 = tid * 16;
    for (int j = 0; j < 16; j++) {
        int l = l0 + j;
        int i = b * LL + l;
        float lm = 0.f;
        #pragma unroll
        for (int o = -2; o <= 2; o++) {
            int ll = l + o;
            if (ll >= 0 && ll < LL) lm += g_avg[i + o];
        }
        lm *= 0.2f;
        float x = g_phase[i] + (g_avg[i] - lm) * nsv + sbv;
        float s = frcp(1.f + __expf(-x));
        sal[l] = s;
        out[OFF_SAL + i] = s;
    }
    if (tid < SS) { g_rs[b*SS+tid] = 0; g_re[b*SS+tid] = 0; g_emask[b*SS+tid] = 0.f; }
    __syncthreads();

    bool prev0 = (l0 > 0) && (sal[l0 - 1] > THRv);
    bool pa = prev0;
    int cnt = 0;
    for (int j = 0; j < 16; j++) {
        bool ab = sal[l0 + j] > THRv;
        cnt += (ab && !pa);
        pa = ab;
    }
    scnt[tid] = cnt;
    __syncthreads();
    if (tid == 0) {
        int a = 0;
        for (int t = 0; t < 256; t++) { int c = scnt[t]; scnt[t] = a; a += c; }
    }
    __syncthreads();
    int e = scnt[tid];
    pa = prev0;
    for (int j = 0; j < 16; j++) {
        int l = l0 + j;
        bool ab = sal[l] > THRv;
        if (ab && !pa) {
            if (e < SS) { g_rs[b*SS + e] = l; g_emask[b*SS + e] = 1.f; }
            e++;
        }
        if (ab && (e - 1) < SS) {
            bool nx = (l + 1 < LL) && (sal[l + 1] > THRv);
            if (!nx) g_re[b*SS + (e - 1)] = l + 1;
        }
        pa = ab;
    }
}

/* event vector partials: 8 chunk-blocks per run (de-straggler) */
__global__ void k_evec1(const float* __restrict__ z,
                        const float* __restrict__ out) {
    int bs = blockIdx.x >> 3, ch = blockIdx.x & 7;
    int b = bs / SS;
    int rs = g_rs[bs], re = g_re[bs];
    int len = re - rs;
    int clen = (len + 7) >> 3;
    int ls = rs + ch * clen;
    int le = min(ls + clen, re);
    const float* sal = out + OFF_SAL + (size_t)b * LL;
    int t = threadIdx.x;
    float a0 = 0.f, a1 = 0.f, a2 = 0.f, a3 = 0.f, den = 0.f;
    for (int l = ls; l < le; l++) {
        float w = sal[l];
        den += w;
        const float* zt = z + ((size_t)b * LL + l) * NC;
        a0 += w * zt[t];       a1 += w * zt[t + 256];
        a2 += w * zt[t + 512]; a3 += w * zt[t + 768];
    }
    float* ev = g_evp + (size_t)(bs * 8 + ch) * NC;
    ev[t] = a0; ev[t + 256] = a1; ev[t + 512] = a2; ev[t + 768] = a3;
    if (t == 0) g_denp[bs * 8 + ch] = den;
}

/* combine chunk partials (deterministic order) */
__global__ void k_evec2() {
    int bs = blockIdx.x, t = threadIdx.x;
    float den = 0.f;
    #pragma unroll
    for (int ch = 0; ch < 8; ch++) den += g_denp[bs * 8 + ch];
    float inv = frcp(fmaxf(den, EPSv));
    #pragma unroll
    for (int q = 0; q < 4; q++) {
        int dim = t + 256 * q;
        float a = 0.f;
        #pragma unroll
        for (int ch = 0; ch < 8; ch++)
            a += g_evp[(size_t)(bs * 8 + ch) * NC + dim];
        g_evec[(size_t)bs * NC + dim] = a * inv;
    }
}

/* event K/V projection + blend + kmag + new_mask (fused) */
__global__ void k_eventkv(const float* __restrict__ Wekr, const float* __restrict__ Weki,
                          const float* __restrict__ Wevr, const float* __restrict__ Wevi,
                          const float* __restrict__ sk,   const float* __restrict__ svv,
                          const float* __restrict__ smk,  float* __restrict__ out) {
    int b = blockIdx.x, sg = blockIdx.y;
    int e = threadIdx.x;
    __shared__ float sv[2][NC];
    __shared__ float wpart[2][16];
    for (int i = threadIdx.x; i < 2 * NC; i += 512)
        ((float*)sv)[i] = g_evec[(size_t)(b * SS + sg * 2) * NC + i];
    __syncthreads();
    float KR[2] = {0.f, 0.f}, KI[2] = {0.f, 0.f};
    float VR[2] = {0.f, 0.f}, VI[2] = {0.f, 0.f};
    for (int d = 0; d < DIMC; d++) {
        float wkr = Wekr[d * DIMC + e], wki = Weki[d * DIMC + e];
        float wvr = Wevr[d * DIMC + e], wvi = Wevi[d * DIMC + e];
        #pragma unroll
        for (int s2 = 0; s2 < 2; s2++) {
            float zr = sv[s2][2 * d], zi = sv[s2][2 * d + 1];
            KR[s2] += zr * wkr - zi * wki;
            KI[s2] += zr * wki + zi * wkr;
            VR[s2] += zr * wvr - zi * wvi;
            VI[s2] += zr * wvi + zi * wvr;
        }
    }
    int lane = e & 31, wid = e >> 5;
    #pragma unroll
    for (int s2 = 0; s2 < 2; s2++) {
        int bs = b * SS + sg * 2 + s2;
        float m = g_emask[bs];
        size_t off = (size_t)bs * NC + 2 * e;
        float nkr = m * KR[s2] + (1.f - m) * sk[off];
        float nki = m * KI[s2] + (1.f - m) * sk[off + 1];
        float nvr = m * VR[s2] + (1.f - m) * svv[off];
        float nvi = m * VI[s2] + (1.f - m) * svv[off + 1];
        out[OFF_NK + off] = nkr; out[OFF_NK + off + 1] = nki;
        out[OFF_NV + off] = nvr; out[OFF_NV + off + 1] = nvi;
        if (e == 0) out[OFF_NM + bs] = fminf(smk[bs] + m, 1.f);
        float p = wred(nkr * nkr + nki * nki);
        if (lane == 0) wpart[s2][wid] = p;
    }
    __syncthreads();
    if (threadIdx.x < 2) {
        float sum = 0.f;
        for (int i = 0; i < 16; i++) sum += wpart[threadIdx.x][i];
        g_kmag[b * SS + sg * 2 + threadIdx.x] = fsqrt(sum + EPSv);
    }
}

/* ------------------------------------------------------------------ */
/* u_{b,s} = B * kappa_{b,s}, output split fp16 hi/lo */
__global__ void k_udot(const float* __restrict__ out) {
    __shared__ float ka[8][NC];
    int b = blockIdx.x, sg = blockIdx.y, eh = blockIdx.z;
    int tid = threadIdx.x;
    const float* ksrc = out + OFF_NK + (size_t)(b * SS + sg * 8) * NC;
    for (int i = tid; i < 8 * NC; i += 256)
        ((float*)ka)[i] = ksrc[i];
    __syncthreads();
    int e = eh * 256 + tid;
    float ur[8], ui[8];
    #pragma unroll
    for (int s = 0; s < 8; s++) { ur[s] = 0.f; ui[s] = 0.f; }
    for (int j = 0; j < DIMC; j++) {
        float wr = g_WrT[(size_t)j * DIMC + e];
        float wi = g_WiT[(size_t)j * DIMC + e];
        #pragma unroll
        for (int s = 0; s < 8; s++) {
            float2 kp = *(const float2*)&ka[s][2 * j];
            ur[s] += wr * kp.x + wi * kp.y;
            ui[s] += wr * kp.y - wi * kp.x;
        }
    }
    #pragma unroll
    for (int s = 0; s < 8; s++) {
        int bs = b * SS + sg * 8 + s;
        __half hr, lr, hi2, li;
        hsplit(ur[s], hr, lr);
        hsplit(ui[s], hi2, li);
        ((__half2*)(g_uh + (size_t)bs * NC))[e] = __halves2half2(hr, hi2);
        ((__half2*)(g_ul + (size_t)bs * NC))[e] = __halves2half2(lr, li);
    }
}

/* ------------------------------------------------------------------ */
/* qmag GEMM: single-term fp16, BM=128 BN=256 BK=32, 512 thr, 3-stage. */
#define BM 128
#define BN 256
#define PITCH 80
#define A_SZ (BM * PITCH)
#define B_SZ (BN * PITCH)
#define STAGE_SZ (A_SZ + B_SZ)
#define QSMEM (3 * STAGE_SZ)
#define NIT (NC / 32)

__global__ void __launch_bounds__(512, 1)
k_qgemm_mma() {
    extern __shared__ unsigned char smq[];
    __shared__ float qp_sm[4][BM];
    int t = threadIdx.x, lane = t & 31, wid = t >> 5;
    int m0 = blockIdx.y * BM, n0 = blockIdx.x * BN;
    int warpM = (wid & 3) * 32, warpN = (wid >> 2) * 64;

    uint32_t sb0 = smem_u32(smq);
    const uint4* srcA = (const uint4*)(g_Ahi  + (size_t)(m0 + (t >> 2)) * NC) + (t & 3);
    int bi0 = t, bi1 = t + 512;
    const uint4* srcB0 = (const uint4*)(g_BhiT + (size_t)(n0 + (bi0 >> 2)) * NC) + (bi0 & 3);
    const uint4* srcB1 = (const uint4*)(g_BhiT + (size_t)(n0 + (bi1 >> 2)) * NC) + (bi1 & 3);
    uint32_t dstA  = sb0 + (uint32_t)((t >> 2) * PITCH + (t & 3) * 16);
    uint32_t dstB0 = sb0 + (uint32_t)(A_SZ + (bi0 >> 2) * PITCH + (bi0 & 3) * 16);
    uint32_t dstB1 = sb0 + (uint32_t)(A_SZ + (bi1 >> 2) * PITCH + (bi1 & 3) * 16);

    uint32_t aoff = (uint32_t)((warpM + (lane & 15)) * PITCH + ((lane >> 4) << 4));
    uint32_t boff = (uint32_t)(A_SZ + (warpN + (lane & 7) + ((lane >> 4) & 1) * 8) * PITCH
                               + (((lane >> 3) & 1) << 4));

    float acc[2][8][4];
    #pragma unroll
    for (int i = 0; i < 2; i++)
        #pragma unroll
        for (int j = 0; j < 8; j++)
            #pragma unroll
            for (int k = 0; k < 4; k++) acc[i][j][k] = 0.f;

    #pragma unroll
    for (int s = 0; s < 2; s++) {
        uint32_t off = (uint32_t)(s * STAGE_SZ);
        CP16(dstA + off,  srcA  + s * 4);
        CP16(dstB0 + off, srcB0 + s * 4);
        CP16(dstB1 + off, srcB1 + s * 4);
        CP_COMMIT();
    }

    for (int it = 0; it < NIT; it++) {
        CP_WAIT1();
        __syncthreads();
        uint32_t st = sb0 + (uint32_t)((it % 3) * STAGE_SZ);
        uint32_t aAh = st + aoff;
        uint32_t aBh = st + boff;

        #pragma unroll
        for (int ko = 0; ko < 2; ko++) {
            uint32_t ah[2][4], bh[4][4];
            #pragma unroll
            for (int mg = 0; mg < 2; mg++)
                ldsm4(ah[mg], aAh + mg * (16 * PITCH) + ko * 32);
            #pragma unroll
            for (int ng = 0; ng < 4; ng++)
                ldsm4(bh[ng], aBh + ng * (16 * PITCH) + ko * 32);
            #pragma unroll
            for (int mg = 0; mg < 2; mg++)
                #pragma unroll
                for (int ng = 0; ng < 4; ng++)
                    #pragma unroll
                    for (int h = 0; h < 2; h++)
                        mma16816(acc[mg][ng * 2 + h], ah[mg],
                                 bh[ng][h*2], bh[ng][h*2+1]);
        }

        if (it + 2 < NIT) {
            uint32_t off = (uint32_t)(((it + 2) % 3) * STAGE_SZ);
            CP16(dstA + off,  srcA  + (it + 2) * 4);
            CP16(dstB0 + off, srcB0 + (it + 2) * 4);
            CP16(dstB1 + off, srcB1 + (it + 2) * 4);
        }
        CP_COMMIT();
    }

    #pragma unroll
    for (int mg = 0; mg < 2; mg++) {
        float rp0 = 0.f, rp1 = 0.f;
        #pragma unroll
        for (int j = 0; j < 8; j++) {
            float* d = acc[mg][j];
            rp0 += d[0]*d[0] + d[1]*d[1];
            rp1 += d[2]*d[2] + d[3]*d[3];
        }
        rp0 += __shfl_xor_sync(0xffffffffu, rp0, 1);
        rp0 += __shfl_xor_sync(0xffffffffu, rp0, 2);
        rp1 += __shfl_xor_sync(0xffffffffu, rp1, 1);
        rp1 += __shfl_xor_sync(0xffffffffu, rp1, 2);
        if ((lane & 3) == 0) {
            int r = warpM + mg * 16 + (lane >> 2);
            qp_sm[wid >> 2][r]     = rp0;
            qp_sm[wid >> 2][r + 8] = rp1;
        }
    }
    __syncthreads();
    if (t < BM)
        g_qp[(size_t)(m0 + t) * 4 + blockIdx.x] =
            qp_sm[0][t] + qp_sm[1][t] + qp_sm[2][t] + qp_sm[3][t];
}

/* ------------------------------------------------------------------ */
/* dot GEMM: dot[l,s] = z_l . u_s, 3-term fp16 (hh+hl+lh). */
#define DM 128
#define DA_SZ (DM * PITCH)
#define DSTG (2 * DA_SZ)
#define PB 2064
#define B_HL (SS * PB)
#define DB_OFF (3 * DSTG)
#define DSMEM (DB_OFF + 2 * B_HL)
#define NITD (NC / 32)

__global__ void __launch_bounds__(256, 1)
k_dotgemm() {
    extern __shared__ unsigned char smd[];
    int t = threadIdx.x, lane = t & 31, wid = t >> 5;
    int m0 = blockIdx.x * DM;
    int batch = blockIdx.x >> 5;
    int warpM = wid * 16;

    uint32_t sb0 = smem_u32(smd);

    #pragma unroll
    for (int u = 0; u < 16; u++) {
        int idx = t + 256 * u;
        int row = idx >> 7, col = idx & 127;
        uint32_t d0 = sb0 + (uint32_t)(DB_OFF + row * PB + col * 16);
        const uint4* sh = (const uint4*)(g_uh + (size_t)(batch * SS + row) * NC) + col;
        const uint4* sl = (const uint4*)(g_ul + (size_t)(batch * SS + row) * NC) + col;
        CP16(d0, sh);
        CP16(d0 + B_HL, sl);
    }
    int ai0 = t, ai1 = t + 256;
    const uint4* sAh0 = (const uint4*)(g_Ahi + (size_t)(m0 + (ai0 >> 2)) * NC) + (ai0 & 3);
    const uint4* sAh1 = (const uint4*)(g_Ahi + (size_t)(m0 + (ai1 >> 2)) * NC) + (ai1 & 3);
    const uint4* sAl0 = (const uint4*)(g_Alo + (size_t)(m0 + (ai0 >> 2)) * NC) + (ai0 & 3);
    const uint4* sAl1 = (const uint4*)(g_Alo + (size_t)(m0 + (ai1 >> 2)) * NC) + (ai1 & 3);
    uint32_t dA0 = sb0 + (uint32_t)((ai0 >> 2) * PITCH + (ai0 & 3) * 16);
    uint32_t dA1 = sb0 + (uint32_t)((ai1 >> 2) * PITCH + (ai1 & 3) * 16);

    #pragma unroll
    for (int s = 0; s < 2; s++) {
        uint32_t off = (uint32_t)(s * DSTG);
        CP16(dA0 + off, sAh0 + s * 4);          CP16(dA1 + off, sAh1 + s * 4);
        CP16(dA0 + off + DA_SZ, sAl0 + s * 4);  CP16(dA1 + off + DA_SZ, sAl1 + s * 4);
        CP_COMMIT();
    }

    uint32_t aoff = (uint32_t)((warpM + (lane & 15)) * PITCH + ((lane >> 4) << 4));
    uint32_t boffB = (uint32_t)(DB_OFF + ((lane & 7) + ((lane >> 4) & 1) * 8) * PB
                                + (((lane >> 3) & 1) << 4));

    float acc[4][4];
    #pragma unroll
    for (int j = 0; j < 4; j++)
        #pragma unroll
        for (int k = 0; k < 4; k++) acc[j][k] = 0.f;

    for (int it = 0; it < NITD; it++) {
        CP_WAIT1();
        __syncthreads();
        uint32_t st = sb0 + (uint32_t)((it % 3) * DSTG);
        #pragma unroll
        for (int ko = 0; ko < 2; ko++) {
            uint32_t ah[4], al[4], bh[2][4], bl[2][4];
            ldsm4(ah, st + aoff + ko * 32);
            ldsm4(al, st + DA_SZ + aoff + ko * 32);
            #pragma unroll
            for (int ng = 0; ng < 2; ng++) {
                uint32_t ba = sb0 + boffB + ng * (16 * PB) + it * 64 + ko * 32;
                ldsm4(bh[ng], ba);
                ldsm4(bl[ng], ba + B_HL);
            }
            #pragma unroll
            for (int ng = 0; ng < 2; ng++)
                #pragma unroll
                for (int h = 0; h < 2; h++) {
                    float* d = acc[ng * 2 + h];
                    mma16816(d, al, bh[ng][h*2], bh[ng][h*2+1]);
                    mma16816(d, ah, bl[ng][h*2], bl[ng][h*2+1]);
                    mma16816(d, ah, bh[ng][h*2], bh[ng][h*2+1]);
                }
        }
        if (it + 2 < NITD) {
            uint32_t off = (uint32_t)(((it + 2) % 3) * DSTG);
            CP16(dA0 + off, sAh0 + (it + 2) * 4);          CP16(dA1 + off, sAh1 + (it + 2) * 4);
            CP16(dA0 + off + DA_SZ, sAl0 + (it + 2) * 4);  CP16(dA1 + off + DA_SZ, sAl1 + (it + 2) * 4);
        }
        CP_COMMIT();
    }

    #pragma unroll
    for (int j = 0; j < 4; j++) {
        float* d = acc[j];
        int r = m0 + warpM + (lane >> 2);
        int c = j * 8 + (lane & 3) * 2;
        *(float2*)&g_dot[(size_t)r * SS + c]       = make_float2(d[0], d[1]);
        *(float2*)&g_dot[(size_t)(r + 8) * SS + c] = make_float2(d[2], d[3]);
    }
}

/* ------------------------------------------------------------------ */
/* attention: warp/token, 32 tokens/block (1024 thr); V staged in smem. */
__global__ void __launch_bounds__(1024, 1)
k_attn(float* __restrict__ out, const float* __restrict__ gain) {
    extern __shared__ float4 sV[];
    __shared__ float sKmag[SS];
    __shared__ float sMask[SS];
    int tid = threadIdx.x, warp = tid >> 5, lane = tid & 31;
    int tok0 = blockIdx.x * 32;
    int b = tok0 / LL;

    const float4* Vsrc = (const float4*)(out + OFF_NV + (size_t)b * SS * NC);
    for (int i = tid; i < SS * NC / 4; i += 1024) sV[i] = Vsrc[i];
    if (tid < SS) {
        sKmag[tid] = g_kmag[b * SS + tid];
        sMask[tid] = out[OFF_NM + b * SS + tid];
    }
    __syncthreads();

    int token = tok0 + warp;
    float qp = (lane < 4) ? g_qp[(size_t)token * 4 + lane] : 0.f;
    qp = wred(qp);
    float qmag = fsqrt(qp + EPSv);

    float dval = g_dot[(size_t)token * SS + lane];
    float myscore = dval * frcp(qmag * sKmag[lane] + EPSv);
    if (sMask[lane] == 0.f) myscore = -1e9f;

    float vcur = myscore;
    float topv[KK]; int topi[KK];
    #pragma unroll
    for (int j = 0; j < KK; j++) {
        float v = vcur; int idx = lane;
        #pragma unroll
        for (int o = 16; o; o >>= 1) {
            float v2 = __shfl_xor_sync(0xffffffffu, v, o);
            int   i2 = __shfl_xor_sync(0xffffffffu, idx, o);
            if (v2 > v || (v2 == v && i2 < idx)) { v = v2; idx = i2; }
        }
        topv[j] = v; topi[j] = idx;
        if (lane == idx) vcur = -INFINITY;
    }
    float w[KK], wsum = 0.f, mx = topv[0];
    #pragma unroll
    for (int j = 0; j < KK; j++) { w[j] = __expf(topv[j] - mx); wsum += w[j]; }
    float winv = frcp(wsum);

    float4 r[8];
    #pragma unroll
    for (int i = 0; i < 8; i++) r[i] = make_float4(0.f, 0.f, 0.f, 0.f);
    #pragma unroll
    for (int j = 0; j < KK; j++) {
        float a = w[j] * winv;
        const float4* Vr = sV + topi[j] * 256;
        #pragma unroll
        for (int i = 0; i < 8; i++) {
            float4 vv = Vr[lane + 32 * i];
            r[i].x += a * vv.x; r[i].y += a * vv.y;
            r[i].z += a * vv.z; r[i].w += a * vv.w;
        }
    }
    float ssum = 0.f;
    #pragma unroll
    for (int i = 0; i < 8; i++)
        ssum += r[i].x*r[i].x + r[i].y*r[i].y + r[i].z*r[i].z + r[i].w*r[i].w;
    ssum = wred(ssum);
    float rinv = frsqrt(ssum * (1.f / DIMC) + EPSv);

    const float2* g2 = (const float2*)gain;
    float4* orow = (float4*)(out + (size_t)token * NC);
    #pragma unroll
    for (int i = 0; i < 8; i++) {
        float2 g = g2[lane + 32 * i];
        float4 o;
        o.x = r[i].x * rinv * g.x; o.y = r[i].y * rinv * g.x;
        o.z = r[i].z * rinv * g.y; o.w = r[i].w * rinv * g.y;
        orow[lane + 32 * i] = o;
    }
}

/* ------------------------------------------------------------------ */
extern "C" void kernel_launch(void* const* d_in, const int* in_sizes, int n_in,
                              void* d_out, int out_size) {
    const float* z    = (const float*)d_in[0];
    const float* sk   = (const float*)d_in[1];
    const float* sv   = (const float*)d_in[2];
    const float* sm   = (const float*)d_in[3];
    const float* Wsr  = (const float*)d_in[4];
    const float* Wsi  = (const float*)d_in[5];
    const float* sb   = (const float*)d_in[6];
    const float* ns   = (const float*)d_in[7];
    const float* Wekr = (const float*)d_in[8];
    const float* Weki = (const float*)d_in[9];
    const float* Wevr = (const float*)d_in[10];
    const float* Wevi = (const float*)d_in[11];
    const float* Wrqr = (const float*)d_in[12];
    const float* Wrqi = (const float*)d_in[13];
    const float* gain = (const float*)d_in[14];
    float* out = (float*)d_out;

    static bool init_done = false;
    static cudaStream_t s1;
    static cudaEvent_t evRoot, evSplit, evQ;
    if (!init_done) {
        cudaFuncSetAttribute(k_attn, cudaFuncAttributeMaxDynamicSharedMemorySize, 131072);
        cudaFuncSetAttribute(k_qgemm_mma, cudaFuncAttributeMaxDynamicSharedMemorySize, QSMEM);
        cudaFuncSetAttribute(k_dotgemm, cudaFuncAttributeMaxDynamicSharedMemorySize, DSMEM);
        cudaStreamCreateWithFlags(&s1, cudaStreamNonBlocking);
        cudaEventCreateWithFlags(&evRoot, cudaEventDisableTiming);
        cudaEventCreateWithFlags(&evSplit, cudaEventDisableTiming);
        cudaEventCreateWithFlags(&evQ, cudaEventDisableTiming);
        init_done = true;
    }

    /* fork at root: s1 = build_bt -> split -> qgemm (independent of s0 chain) */
    cudaEventRecord(evRoot, 0);
    cudaStreamWaitEvent(s1, evRoot, 0);

    /* s0 chain; launch-issue order keeps evec1 at global idx 3 for ncu */
    k_statsA<<<4096, 256>>>(z, Wsr, Wsi);               /* idx 0 */
    k_runs<<<Bb, 256>>>(out, sb, ns);                   /* idx 1 */
    k_build_bt<<<dim3(16, 16), 256, 0, s1>>>(Wrqr, Wrqi);  /* idx 2 (s1) */
    k_evec1<<<Bb * SS * 8, 256>>>(z, out);              /* idx 3: profiled */
    k_split<<<NT * NC / (256 * 8), 256, 0, s1>>>(z);    /* idx 4 (s1) */
    cudaEventRecord(evSplit, s1);
    k_evec2<<<Bb * SS, 256>>>();                        /* idx 5 */
    k_qgemm_mma<<<dim3(NC / BN, NT / BM), 512, QSMEM, s1>>>();  /* idx 6 (s1) */
    cudaEventRecord(evQ, s1);
    k_eventkv<<<dim3(Bb, SS / 2), 512>>>(Wekr, Weki, Wevr, Wevi, sk, sv, sm, out);
    k_udot<<<dim3(Bb, SS / 8, 2), 256>>>(out);
    cudaStreamWaitEvent(0, evSplit, 0);                 /* dotgemm reads Ahi/Alo */
    k_dotgemm<<<NT / DM, 256, DSMEM>>>();
    cudaStreamWaitEvent(0, evQ, 0);                     /* attn reads g_qp */
    k_attn<<<NT / 32, 1024, 131072>>>(out, gain);
}

// round 12
// speedup vs baseline: 1.1645x; 1.1645x over previous
#include <cuda_runtime.h>
#include <cuda_fp16.h>
#include <math.h>
#include <stdint.h>

#define Bb   8
#define LL   4096
#define DIMC 512
#define SS   32
#define KK   8
#define NT   (Bb*LL)      /* 32768 tokens */
#define NC   (DIMC*2)     /* 1024 floats per token (interleaved r,i) */
#define THRv 0.5f
#define EPSv 1e-8f

/* output layout: concat(out, new_keys, new_values, new_mask, salience) */
#define OFF_OUT ((size_t)0)
#define OFF_NK  ((size_t)NT*NC)
#define OFF_NV  (OFF_NK + (size_t)Bb*SS*NC)
#define OFF_NM  (OFF_NV + (size_t)Bb*SS*NC)
#define OFF_SAL (OFF_NM + (size_t)Bb*SS)

/* scratch (device globals; no allocation allowed) */
__device__ float g_avg[NT];
__device__ float g_phase[NT];
__device__ float g_evp[(size_t)Bb*SS*8*NC];  /* evec chunk partials, 8MB */
__device__ float g_denp[Bb*SS*8];
__device__ float g_emask[Bb*SS];
__device__ int   g_rs[Bb*SS];
__device__ int   g_re[Bb*SS];
__device__ float g_kmag[Bb*SS];
__device__ __half g_BhiT[NC*NC];          /* B^T fp16, [n][k], 2MB */
__device__ __half g_Ahi[(size_t)NT*NC];   /* z hi fp16, 64MB */
__device__ __half g_Alo[(size_t)NT*NC];   /* z lo fp16, 64MB */
__device__ float g_WrT[DIMC*DIMC];        /* W_rq_r transposed, 1MB */
__device__ float g_WiT[DIMC*DIMC];        /* W_rq_i transposed, 1MB */
__device__ __half g_uh[Bb*SS*NC];         /* u hi fp16 */
__device__ __half g_ul[Bb*SS*NC];         /* u lo fp16 */
__device__ float g_qp[(size_t)NT*4];      /* qmag^2 partials per N-block */
__device__ float g_dot[(size_t)NT*SS];    /* dot[l,s], 4MB */

__device__ __forceinline__ float wred(float v) {
    #pragma unroll
    for (int o = 16; o; o >>= 1) v += __shfl_xor_sync(0xffffffffu, v, o);
    return v;
}

__device__ __forceinline__ float fsqrt(float x) {
    float y; asm("sqrt.approx.f32 %0, %1;" : "=f"(y) : "f"(x)); return y;
}
__device__ __forceinline__ float frcp(float x) {
    float y; asm("rcp.approx.f32 %0, %1;" : "=f"(y) : "f"(x)); return y;
}
__device__ __forceinline__ float frsqrt(float x) {
    float y; asm("rsqrt.approx.f32 %0, %1;" : "=f"(y) : "f"(x)); return y;
}

__device__ __forceinline__ void hsplit(float x, __half& h, __half& l) {
    h = __float2half_rn(x);
    l = __float2half_rn(x - __half2float(h));
}

__device__ __forceinline__ uint32_t smem_u32(const void* p) {
    uint32_t a;
    asm("{ .reg .u64 t; cvta.to.shared.u64 t, %1; cvt.u32.u64 %0, t; }"
        : "=r"(a) : "l"(p));
    return a;
}

__device__ __forceinline__ void ldsm4(uint32_t* r, uint32_t addr) {
    asm volatile("ldmatrix.sync.aligned.m8n8.x4.shared.b16 {%0,%1,%2,%3}, [%4];"
        : "=r"(r[0]), "=r"(r[1]), "=r"(r[2]), "=r"(r[3]) : "r"(addr));
}

__device__ __forceinline__ void mma16816(float* d, const uint32_t* a,
                                         uint32_t b0, uint32_t b1) {
    asm volatile(
        "mma.sync.aligned.m16n8k16.row.col.f32.f16.f16.f32 "
        "{%0,%1,%2,%3}, {%4,%5,%6,%7}, {%8,%9}, {%0,%1,%2,%3};"
        : "+f"(d[0]), "+f"(d[1]), "+f"(d[2]), "+f"(d[3])
        : "r"(a[0]), "r"(a[1]), "r"(a[2]), "r"(a[3]), "r"(b0), "r"(b1));
}

#define CP16(dst, src) \
    asm volatile("cp.async.cg.shared.global [%0], [%1], 16;" \
                 :: "r"(dst), "l"(src) : "memory")
#define CP_COMMIT() asm volatile("cp.async.commit_group;" ::: "memory")
#define CP_WAIT1()  asm volatile("cp.async.wait_group 1;" ::: "memory")

/* ------------------------------------------------------------------ */
/* per-token stats only (avg mag + salience phase) — critical path */
__global__ void k_statsA(const float* __restrict__ z,
                         const float* __restrict__ Wsr,
                         const float* __restrict__ Wsi) {
    int gw = (blockIdx.x * blockDim.x + threadIdx.x) >> 5;
    int lane = threadIdx.x & 31;
    if (gw >= NT) return;
    const float4* z4 = (const float4*)(z + (size_t)gw * NC);
    float ms = 0.f, pr = 0.f, pi = 0.f;
    #pragma unroll
    for (int i = 0; i < 8; i++) {
        int p = lane + 32 * i;
        float4 v = z4[p];
        int d = 2 * p;
        ms += fsqrt(v.x*v.x + v.y*v.y + EPSv) + fsqrt(v.z*v.z + v.w*v.w + EPSv);
        float wr0 = Wsr[d], wi0 = Wsi[d], wr1 = Wsr[d+1], wi1 = Wsi[d+1];
        pr += v.x*wr0 - v.y*wi0 + v.z*wr1 - v.w*wi1;
        pi += v.x*wi0 + v.y*wr0 + v.z*wi1 + v.w*wr1;
    }
    ms = wred(ms); pr = wred(pr); pi = wred(pi);
    if (lane == 0) {
        g_avg[gw]   = ms * (1.f / DIMC);
        g_phase[gw] = fsqrt(pr*pr + pi*pi + EPSv);
    }
}

/* z -> fp16 hi/lo (side stream s2; depends only on input z) */
__global__ void k_split(const float* __restrict__ z) {
    size_t i = ((size_t)blockIdx.x * 256 + threadIdx.x) * 8;
    float4 v0 = *(const float4*)(z + i);
    float4 v1 = *(const float4*)(z + i + 4);
    __half h[8], l[8];
    hsplit(v0.x, h[0], l[0]); hsplit(v0.y, h[1], l[1]);
    hsplit(v0.z, h[2], l[2]); hsplit(v0.w, h[3], l[3]);
    hsplit(v1.x, h[4], l[4]); hsplit(v1.y, h[5], l[5]);
    hsplit(v1.z, h[6], l[6]); hsplit(v1.w, h[7], l[7]);
    *(uint4*)(g_Ahi + i) = *(uint4*)h;
    *(uint4*)(g_Alo + i) = *(uint4*)l;
}

/* ------------------------------------------------------------------ */
__global__ void k_build_bt(const float* __restrict__ Wr,
                           const float* __restrict__ Wi) {
    __shared__ float tr[32][33], ti[32][33];
    int tx = threadIdx.x & 31, ty = threadIdx.x >> 5;
    int d0 = blockIdx.x * 32, e0 = blockIdx.y * 32;
    #pragma unroll
    for (int j = 0; j < 4; j++) {
        int d = d0 + ty + 8 * j;
        tr[ty + 8 * j][tx] = Wr[(size_t)d * DIMC + e0 + tx];
        ti[ty + 8 * j][tx] = Wi[(size_t)d * DIMC + e0 + tx];
    }
    __syncthreads();
    #pragma unroll
    for (int j = 0; j < 4; j++) {
        int e = e0 + ty + 8 * j;
        int d = d0 + tx;
        float wr = tr[tx][ty + 8 * j], wi = ti[tx][ty + 8 * j];
        size_t r0 = (size_t)(2 * e) * NC, r1 = (size_t)(2 * e + 1) * NC;
        g_BhiT[r0 + 2*d]     = __float2half_rn(wr);
        g_BhiT[r0 + 2*d + 1] = __float2half_rn(-wi);
        g_BhiT[r1 + 2*d]     = __float2half_rn(wi);
        g_BhiT[r1 + 2*d + 1] = __float2half_rn(wr);
        g_WrT[(size_t)e * DIMC + d] = wr;
        g_WiT[(size_t)e * DIMC + d] = wi;
    }
}

/* ------------------------------------------------------------------ */
/* fused salience + run detection; parallel prefix scan */
__global__ void k_runs(float* __restrict__ out,
                       const float* __restrict__ sb,
                       const float* __restrict__ ns) {
    __shared__ float sal[LL];
    __shared__ int scnt[256];
    int b = blockIdx.x, tid = threadIdx.x;
    float nsv = ns[0], sbv = sb[0];

    int l0 = tid * 16;
    for (int j = 0; j < 16; j++) {
        int l = l0 + j;
        int i = b * LL + l;
        float lm = 0.f;
        #pragma unroll
        for (int o = -2; o <= 2; o++) {
            int ll = l + o;
            if (ll >= 0 && ll < LL) lm += g_avg[i + o];
        }
        lm *= 0.2f;
        float x = g_phase[i] + (g_avg[i] - lm) * nsv + sbv;
        float s = frcp(1.f + __expf(-x));
        sal[l] = s;
        out[OFF_SAL + i] = s;
    }
    if (tid < SS) { g_rs[b*SS+tid] = 0; g_re[b*SS+tid] = 0; g_emask[b*SS+tid] = 0.f; }
    __syncthreads();

    bool prev0 = (l0 > 0) && (sal[l0 - 1] > THRv);
    bool pa = prev0;
    int cnt = 0;
    for (int j = 0; j < 16; j++) {
        bool ab = sal[l0 + j] > THRv;
        cnt += (ab && !pa);
        pa = ab;
    }
    scnt[tid] = cnt;
    __syncthreads();
    /* Hillis-Steele inclusive scan over 256 entries */
    #pragma unroll
    for (int off = 1; off < 256; off <<= 1) {
        int add = (tid >= off) ? scnt[tid - off] : 0;
        __syncthreads();
        scnt[tid] += add;
        __syncthreads();
    }
    int e = scnt[tid] - cnt;   /* exclusive prefix */
    pa = prev0;
    for (int j = 0; j < 16; j++) {
        int l = l0 + j;
        bool ab = sal[l] > THRv;
        if (ab && !pa) {
            if (e < SS) { g_rs[b*SS + e] = l; g_emask[b*SS + e] = 1.f; }
            e++;
        }
        if (ab && (e - 1) < SS) {
            bool nx = (l + 1 < LL) && (sal[l + 1] > THRv);
            if (!nx) g_re[b*SS + (e - 1)] = l + 1;
        }
        pa = ab;
    }
}

/* event vector partials: 8 chunk-blocks per run */
__global__ void k_evec1(const float* __restrict__ z,
                        const float* __restrict__ out) {
    int bs = blockIdx.x >> 3, ch = blockIdx.x & 7;
    int b = bs / SS;
    int rs = g_rs[bs], re = g_re[bs];
    int len = re - rs;
    int clen = (len + 7) >> 3;
    int ls = rs + ch * clen;
    int le = min(ls + clen, re);
    const float* sal = out + OFF_SAL + (size_t)b * LL;
    int t = threadIdx.x;
    float a0 = 0.f, a1 = 0.f, a2 = 0.f, a3 = 0.f, den = 0.f;
    for (int l = ls; l < le; l++) {
        float w = sal[l];
        den += w;
        const float* zt = z + ((size_t)b * LL + l) * NC;
        a0 += w * zt[t];       a1 += w * zt[t + 256];
        a2 += w * zt[t + 512]; a3 += w * zt[t + 768];
    }
    float* ev = g_evp + (size_t)(bs * 8 + ch) * NC;
    ev[t] = a0; ev[t + 256] = a1; ev[t + 512] = a2; ev[t + 768] = a3;
    if (t == 0) g_denp[bs * 8 + ch] = den;
}

/* event K/V projection + blend + kmag + new_mask; combines evec partials.
   4 slots per block, grid (Bb, SS/4), 512 threads (thread = output dim e). */
__global__ void __launch_bounds__(512, 2)
k_eventkv(const float* __restrict__ Wekr, const float* __restrict__ Weki,
          const float* __restrict__ Wevr, const float* __restrict__ Wevi,
          const float* __restrict__ sk,   const float* __restrict__ svv,
          const float* __restrict__ smk,  float* __restrict__ out) {
    int b = blockIdx.x, sg = blockIdx.y;
    int e = threadIdx.x;
    int bs0 = b * SS + sg * 4;
    __shared__ float sv[4][NC];      /* 16KB */
    __shared__ float sinv[4];
    __shared__ float wpart[4][16];
    if (e < 4) {
        float den = 0.f;
        #pragma unroll
        for (int ch = 0; ch < 8; ch++) den += g_denp[(bs0 + e) * 8 + ch];
        sinv[e] = frcp(fmaxf(den, EPSv));
    }
    __syncthreads();
    for (int i = e; i < 4 * NC; i += 512) {
        int slot = i >> 10, dim = i & (NC - 1);
        float a = 0.f;
        #pragma unroll
        for (int ch = 0; ch < 8; ch++)
            a += g_evp[(size_t)((bs0 + slot) * 8 + ch) * NC + dim];
        sv[slot][dim] = a * sinv[slot];
    }
    __syncthreads();

    float KR[4] = {0,0,0,0}, KI[4] = {0,0,0,0};
    float VR[4] = {0,0,0,0}, VI[4] = {0,0,0,0};
    for (int d = 0; d < DIMC; d++) {
        float wkr = Wekr[d * DIMC + e], wki = Weki[d * DIMC + e];
        float wvr = Wevr[d * DIMC + e], wvi = Wevi[d * DIMC + e];
        #pragma unroll
        for (int s2 = 0; s2 < 4; s2++) {
            float zr = sv[s2][2 * d], zi = sv[s2][2 * d + 1];
            KR[s2] += zr * wkr - zi * wki;
            KI[s2] += zr * wki + zi * wkr;
            VR[s2] += zr * wvr - zi * wvi;
            VI[s2] += zr * wvi + zi * wvr;
        }
    }
    int lane = e & 31, wid = e >> 5;
    #pragma unroll
    for (int s2 = 0; s2 < 4; s2++) {
        int bs = bs0 + s2;
        float m = g_emask[bs];
        size_t off = (size_t)bs * NC + 2 * e;
        float nkr = m * KR[s2] + (1.f - m) * sk[off];
        float nki = m * KI[s2] + (1.f - m) * sk[off + 1];
        float nvr = m * VR[s2] + (1.f - m) * svv[off];
        float nvi = m * VI[s2] + (1.f - m) * svv[off + 1];
        out[OFF_NK + off] = nkr; out[OFF_NK + off + 1] = nki;
        out[OFF_NV + off] = nvr; out[OFF_NV + off + 1] = nvi;
        if (e == 0) out[OFF_NM + bs] = fminf(smk[bs] + m, 1.f);
        float p = wred(nkr * nkr + nki * nki);
        if (lane == 0) wpart[s2][wid] = p;
    }
    __syncthreads();
    if (e < 4) {
        float sum = 0.f;
        #pragma unroll
        for (int i = 0; i < 16; i++) sum += wpart[e][i];
        g_kmag[bs0 + e] = fsqrt(sum + EPSv);
    }
}

/* ------------------------------------------------------------------ */
/* u_{b,s} = B * kappa_{b,s}; grid (Bb, SS/8), 512 thr (full e range) */
__global__ void __launch_bounds__(512, 2)
k_udot(const float* __restrict__ out) {
    __shared__ float ka[8][NC];      /* 32KB */
    int b = blockIdx.x, sg = blockIdx.y;
    int tid = threadIdx.x;
    const float* ksrc = out + OFF_NK + (size_t)(b * SS + sg * 8) * NC;
    for (int i = tid; i < 8 * NC; i += 512)
        ((float*)ka)[i] = ksrc[i];
    __syncthreads();
    int e = tid;
    float ur[8], ui[8];
    #pragma unroll
    for (int s = 0; s < 8; s++) { ur[s] = 0.f; ui[s] = 0.f; }
    for (int j = 0; j < DIMC; j++) {
        float wr = g_WrT[(size_t)j * DIMC + e];
        float wi = g_WiT[(size_t)j * DIMC + e];
        #pragma unroll
        for (int s = 0; s < 8; s++) {
            float2 kp = *(const float2*)&ka[s][2 * j];
            ur[s] += wr * kp.x + wi * kp.y;
            ui[s] += wr * kp.y - wi * kp.x;
        }
    }
    #pragma unroll
    for (int s = 0; s < 8; s++) {
        int bs = b * SS + sg * 8 + s;
        __half hr, lr, hi2, li;
        hsplit(ur[s], hr, lr);
        hsplit(ui[s], hi2, li);
        ((__half2*)(g_uh + (size_t)bs * NC))[e] = __halves2half2(hr, hi2);
        ((__half2*)(g_ul + (size_t)bs * NC))[e] = __halves2half2(lr, li);
    }
}

/* ------------------------------------------------------------------ */
/* qmag GEMM: single-term fp16, BM=128 BN=256 BK=32, 512 thr, 3-stage. */
#define BM 128
#define BN 256
#define PITCH 80
#define A_SZ (BM * PITCH)
#define B_SZ (BN * PITCH)
#define STAGE_SZ (A_SZ + B_SZ)
#define QSMEM (3 * STAGE_SZ)
#define NIT (NC / 32)

__global__ void __launch_bounds__(512, 1)
k_qgemm_mma() {
    extern __shared__ unsigned char smq[];
    __shared__ float qp_sm[4][BM];
    int t = threadIdx.x, lane = t & 31, wid = t >> 5;
    int m0 = blockIdx.y * BM, n0 = blockIdx.x * BN;
    int warpM = (wid & 3) * 32, warpN = (wid >> 2) * 64;

    uint32_t sb0 = smem_u32(smq);
    const uint4* srcA = (const uint4*)(g_Ahi  + (size_t)(m0 + (t >> 2)) * NC) + (t & 3);
    int bi0 = t, bi1 = t + 512;
    const uint4* srcB0 = (const uint4*)(g_BhiT + (size_t)(n0 + (bi0 >> 2)) * NC) + (bi0 & 3);
    const uint4* srcB1 = (const uint4*)(g_BhiT + (size_t)(n0 + (bi1 >> 2)) * NC) + (bi1 & 3);
    uint32_t dstA  = sb0 + (uint32_t)((t >> 2) * PITCH + (t & 3) * 16);
    uint32_t dstB0 = sb0 + (uint32_t)(A_SZ + (bi0 >> 2) * PITCH + (bi0 & 3) * 16);
    uint32_t dstB1 = sb0 + (uint32_t)(A_SZ + (bi1 >> 2) * PITCH + (bi1 & 3) * 16);

    uint32_t aoff = (uint32_t)((warpM + (lane & 15)) * PITCH + ((lane >> 4) << 4));
    uint32_t boff = (uint32_t)(A_SZ + (warpN + (lane & 7) + ((lane >> 4) & 1) * 8) * PITCH
                               + (((lane >> 3) & 1) << 4));

    float acc[2][8][4];
    #pragma unroll
    for (int i = 0; i < 2; i++)
        #pragma unroll
        for (int j = 0; j < 8; j++)
            #pragma unroll
            for (int k = 0; k < 4; k++) acc[i][j][k] = 0.f;

    #pragma unroll
    for (int s = 0; s < 2; s++) {
        uint32_t off = (uint32_t)(s * STAGE_SZ);
        CP16(dstA + off,  srcA  + s * 4);
        CP16(dstB0 + off, srcB0 + s * 4);
        CP16(dstB1 + off, srcB1 + s * 4);
        CP_COMMIT();
    }

    for (int it = 0; it < NIT; it++) {
        CP_WAIT1();
        __syncthreads();
        uint32_t st = sb0 + (uint32_t)((it % 3) * STAGE_SZ);
        uint32_t aAh = st + aoff;
        uint32_t aBh = st + boff;

        #pragma unroll
        for (int ko = 0; ko < 2; ko++) {
            uint32_t ah[2][4], bh[4][4];
            #pragma unroll
            for (int mg = 0; mg < 2; mg++)
                ldsm4(ah[mg], aAh + mg * (16 * PITCH) + ko * 32);
            #pragma unroll
            for (int ng = 0; ng < 4; ng++)
                ldsm4(bh[ng], aBh + ng * (16 * PITCH) + ko * 32);
            #pragma unroll
            for (int mg = 0; mg < 2; mg++)
                #pragma unroll
                for (int ng = 0; ng < 4; ng++)
                    #pragma unroll
                    for (int h = 0; h < 2; h++)
                        mma16816(acc[mg][ng * 2 + h], ah[mg],
                                 bh[ng][h*2], bh[ng][h*2+1]);
        }

        if (it + 2 < NIT) {
            uint32_t off = (uint32_t)(((it + 2) % 3) * STAGE_SZ);
            CP16(dstA + off,  srcA  + (it + 2) * 4);
            CP16(dstB0 + off, srcB0 + (it + 2) * 4);
            CP16(dstB1 + off, srcB1 + (it + 2) * 4);
        }
        CP_COMMIT();
    }

    #pragma unroll
    for (int mg = 0; mg < 2; mg++) {
        float rp0 = 0.f, rp1 = 0.f;
        #pragma unroll
        for (int j = 0; j < 8; j++) {
            float* d = acc[mg][j];
            rp0 += d[0]*d[0] + d[1]*d[1];
            rp1 += d[2]*d[2] + d[3]*d[3];
        }
        rp0 += __shfl_xor_sync(0xffffffffu, rp0, 1);
        rp0 += __shfl_xor_sync(0xffffffffu, rp0, 2);
        rp1 += __shfl_xor_sync(0xffffffffu, rp1, 1);
        rp1 += __shfl_xor_sync(0xffffffffu, rp1, 2);
        if ((lane & 3) == 0) {
            int r = warpM + mg * 16 + (lane >> 2);
            qp_sm[wid >> 2][r]     = rp0;
            qp_sm[wid >> 2][r + 8] = rp1;
        }
    }
    __syncthreads();
    if (t < BM)
        g_qp[(size_t)(m0 + t) * 4 + blockIdx.x] =
            qp_sm[0][t] + qp_sm[1][t] + qp_sm[2][t] + qp_sm[3][t];
}

/* ------------------------------------------------------------------ */
/* dot GEMM: dot[l,s] = z_l . u_s, 3-term fp16 (hh+hl+lh). */
#define DM 128
#define DA_SZ (DM * PITCH)
#define DSTG (2 * DA_SZ)
#define PB 2064
#define B_HL (SS * PB)
#define DB_OFF (3 * DSTG)
#define DSMEM (DB_OFF + 2 * B_HL)
#define NITD (NC / 32)

__global__ void __launch_bounds__(256, 1)
k_dotgemm() {
    extern __shared__ unsigned char smd[];
    int t = threadIdx.x, lane = t & 31, wid = t >> 5;
    int m0 = blockIdx.x * DM;
    int batch = blockIdx.x >> 5;
    int warpM = wid * 16;

    uint32_t sb0 = smem_u32(smd);

    #pragma unroll
    for (int u = 0; u < 16; u++) {
        int idx = t + 256 * u;
        int row = idx >> 7, col = idx & 127;
        uint32_t d0 = sb0 + (uint32_t)(DB_OFF + row * PB + col * 16);
        const uint4* sh = (const uint4*)(g_uh + (size_t)(batch * SS + row) * NC) + col;
        const uint4* sl = (const uint4*)(g_ul + (size_t)(batch * SS + row) * NC) + col;
        CP16(d0, sh);
        CP16(d0 + B_HL, sl);
    }
    int ai0 = t, ai1 = t + 256;
    const uint4* sAh0 = (const uint4*)(g_Ahi + (size_t)(m0 + (ai0 >> 2)) * NC) + (ai0 & 3);
    const uint4* sAh1 = (const uint4*)(g_Ahi + (size_t)(m0 + (ai1 >> 2)) * NC) + (ai1 & 3);
    const uint4* sAl0 = (const uint4*)(g_Alo + (size_t)(m0 + (ai0 >> 2)) * NC) + (ai0 & 3);
    const uint4* sAl1 = (const uint4*)(g_Alo + (size_t)(m0 + (ai1 >> 2)) * NC) + (ai1 & 3);
    uint32_t dA0 = sb0 + (uint32_t)((ai0 >> 2) * PITCH + (ai0 & 3) * 16);
    uint32_t dA1 = sb0 + (uint32_t)((ai1 >> 2) * PITCH + (ai1 & 3) * 16);

    #pragma unroll
    for (int s = 0; s < 2; s++) {
        uint32_t off = (uint32_t)(s * DSTG);
        CP16(dA0 + off, sAh0 + s * 4);          CP16(dA1 + off, sAh1 + s * 4);
        CP16(dA0 + off + DA_SZ, sAl0 + s * 4);  CP16(dA1 + off + DA_SZ, sAl1 + s * 4);
        CP_COMMIT();
    }

    uint32_t aoff = (uint32_t)((warpM + (lane & 15)) * PITCH + ((lane >> 4) << 4));
    uint32_t boffB = (uint32_t)(DB_OFF + ((lane & 7) + ((lane >> 4) & 1) * 8) * PB
                                + (((lane >> 3) & 1) << 4));

    float acc[4][4];
    #pragma unroll
    for (int j = 0; j < 4; j++)
        #pragma unroll
        for (int k = 0; k < 4; k++) acc[j][k] = 0.f;

    for (int it = 0; it < NITD; it++) {
        CP_WAIT1();
        __syncthreads();
        uint32_t st = sb0 + (uint32_t)((it % 3) * DSTG);
        #pragma unroll
        for (int ko = 0; ko < 2; ko++) {
            uint32_t ah[4], al[4], bh[2][4], bl[2][4];
            ldsm4(ah, st + aoff + ko * 32);
            ldsm4(al, st + DA_SZ + aoff + ko * 32);
            #pragma unroll
            for (int ng = 0; ng < 2; ng++) {
                uint32_t ba = sb0 + boffB + ng * (16 * PB) + it * 64 + ko * 32;
                ldsm4(bh[ng], ba);
                ldsm4(bl[ng], ba + B_HL);
            }
            #pragma unroll
            for (int ng = 0; ng < 2; ng++)
                #pragma unroll
                for (int h = 0; h < 2; h++) {
                    float* d = acc[ng * 2 + h];
                    mma16816(d, al, bh[ng][h*2], bh[ng][h*2+1]);
                    mma16816(d, ah, bl[ng][h*2], bl[ng][h*2+1]);
                    mma16816(d, ah, bh[ng][h*2], bh[ng][h*2+1]);
                }
        }
        if (it + 2 < NITD) {
            uint32_t off = (uint32_t)(((it + 2) % 3) * DSTG);
            CP16(dA0 + off, sAh0 + (it + 2) * 4);          CP16(dA1 + off, sAh1 + (it + 2) * 4);
            CP16(dA0 + off + DA_SZ, sAl0 + (it + 2) * 4);  CP16(dA1 + off + DA_SZ, sAl1 + (it + 2) * 4);
        }
        CP_COMMIT();
    }

    #pragma unroll
    for (int j = 0; j < 4; j++) {
        float* d = acc[j];
        int r = m0 + warpM + (lane >> 2);
        int c = j * 8 + (lane & 3) * 2;
        *(float2*)&g_dot[(size_t)r * SS + c]       = make_float2(d[0], d[1]);
        *(float2*)&g_dot[(size_t)(r + 8) * SS + c] = make_float2(d[2], d[3]);
    }
}

/* ------------------------------------------------------------------ */
/* attention: warp/token, 32 tokens/block (1024 thr); V staged in smem. */
__global__ void __launch_bounds__(1024, 1)
k_attn(float* __restrict__ out, const float* __restrict__ gain) {
    extern __shared__ float4 sV[];
    __shared__ float sKmag[SS];
    __shared__ float sMask[SS];
    int tid = threadIdx.x, warp = tid >> 5, lane = tid & 31;
    int tok0 = blockIdx.x * 32;
    int b = tok0 / LL;

    const float4* Vsrc = (const float4*)(out + OFF_NV + (size_t)b * SS * NC);
    for (int i = tid; i < SS * NC / 4; i += 1024) sV[i] = Vsrc[i];
    if (tid < SS) {
        sKmag[tid] = g_kmag[b * SS + tid];
        sMask[tid] = out[OFF_NM + b * SS + tid];
    }
    __syncthreads();

    int token = tok0 + warp;
    float qp = (lane < 4) ? g_qp[(size_t)token * 4 + lane] : 0.f;
    qp = wred(qp);
    float qmag = fsqrt(qp + EPSv);

    float dval = g_dot[(size_t)token * SS + lane];
    float myscore = dval * frcp(qmag * sKmag[lane] + EPSv);
    if (sMask[lane] == 0.f) myscore = -1e9f;

    float vcur = myscore;
    float topv[KK]; int topi[KK];
    #pragma unroll
    for (int j = 0; j < KK; j++) {
        float v = vcur; int idx = lane;
        #pragma unroll
        for (int o = 16; o; o >>= 1) {
            float v2 = __shfl_xor_sync(0xffffffffu, v, o);
            int   i2 = __shfl_xor_sync(0xffffffffu, idx, o);
            if (v2 > v || (v2 == v && i2 < idx)) { v = v2; idx = i2; }
        }
        topv[j] = v; topi[j] = idx;
        if (lane == idx) vcur = -INFINITY;
    }
    float w[KK], wsum = 0.f, mx = topv[0];
    #pragma unroll
    for (int j = 0; j < KK; j++) { w[j] = __expf(topv[j] - mx); wsum += w[j]; }
    float winv = frcp(wsum);

    float4 r[8];
    #pragma unroll
    for (int i = 0; i < 8; i++) r[i] = make_float4(0.f, 0.f, 0.f, 0.f);
    #pragma unroll
    for (int j = 0; j < KK; j++) {
        float a = w[j] * winv;
        const float4* Vr = sV + topi[j] * 256;
        #pragma unroll
        for (int i = 0; i < 8; i++) {
            float4 vv = Vr[lane + 32 * i];
            r[i].x += a * vv.x; r[i].y += a * vv.y;
            r[i].z += a * vv.z; r[i].w += a * vv.w;
        }
    }
    float ssum = 0.f;
    #pragma unroll
    for (int i = 0; i < 8; i++)
        ssum += r[i].x*r[i].x + r[i].y*r[i].y + r[i].z*r[i].z + r[i].w*r[i].w;
    ssum = wred(ssum);
    float rinv = frsqrt(ssum * (1.f / DIMC) + EPSv);

    const float2* g2 = (const float2*)gain;
    float4* orow = (float4*)(out + (size_t)token * NC);
    #pragma unroll
    for (int i = 0; i < 8; i++) {
        float2 g = g2[lane + 32 * i];
        float4 o;
        o.x = r[i].x * rinv * g.x; o.y = r[i].y * rinv * g.x;
        o.z = r[i].z * rinv * g.y; o.w = r[i].w * rinv * g.y;
        orow[lane + 32 * i] = o;
    }
}

/* ------------------------------------------------------------------ */
extern "C" void kernel_launch(void* const* d_in, const int* in_sizes, int n_in,
                              void* d_out, int out_size) {
    const float* z    = (const float*)d_in[0];
    const float* sk   = (const float*)d_in[1];
    const float* sv   = (const float*)d_in[2];
    const float* sm   = (const float*)d_in[3];
    const float* Wsr  = (const float*)d_in[4];
    const float* Wsi  = (const float*)d_in[5];
    const float* sb   = (const float*)d_in[6];
    const float* ns   = (const float*)d_in[7];
    const float* Wekr = (const float*)d_in[8];
    const float* Weki = (const float*)d_in[9];
    const float* Wevr = (const float*)d_in[10];
    const float* Wevi = (const float*)d_in[11];
    const float* Wrqr = (const float*)d_in[12];
    const float* Wrqi = (const float*)d_in[13];
    const float* gain = (const float*)d_in[14];
    float* out = (float*)d_out;

    static bool init_done = false;
    static cudaStream_t s1, s2;
    static cudaEvent_t evRoot, evSplit, evQ;
    if (!init_done) {
        cudaFuncSetAttribute(k_attn, cudaFuncAttributeMaxDynamicSharedMemorySize, 131072);
        cudaFuncSetAttribute(k_qgemm_mma, cudaFuncAttributeMaxDynamicSharedMemorySize, QSMEM);
        cudaFuncSetAttribute(k_dotgemm, cudaFuncAttributeMaxDynamicSharedMemorySize, DSMEM);
        cudaStreamCreateWithFlags(&s1, cudaStreamNonBlocking);
        cudaStreamCreateWithFlags(&s2, cudaStreamNonBlocking);
        cudaEventCreateWithFlags(&evRoot, cudaEventDisableTiming);
        cudaEventCreateWithFlags(&evSplit, cudaEventDisableTiming);
        cudaEventCreateWithFlags(&evQ, cudaEventDisableTiming);
        init_done = true;
    }

    /* fork at root: s1 = build_bt -> qgemm; s2 = split */
    cudaEventRecord(evRoot, 0);
    cudaStreamWaitEvent(s1, evRoot, 0);
    cudaStreamWaitEvent(s2, evRoot, 0);

    k_statsA<<<4096, 256>>>(z, Wsr, Wsi);               /* idx 0 (s0) */
    k_split<<<NT * NC / (256 * 8), 256, 0, s2>>>(z);    /* idx 1 (s2) */
    cudaEventRecord(evSplit, s2);
    k_runs<<<Bb, 256>>>(out, sb, ns);                   /* idx 2 (s0) */
    k_evec1<<<Bb * SS * 8, 256>>>(z, out);              /* idx 3 (s0): profiled */
    k_build_bt<<<dim3(16, 16), 256, 0, s1>>>(Wrqr, Wrqi);  /* idx 4 (s1) */
    cudaStreamWaitEvent(s1, evSplit, 0);
    k_qgemm_mma<<<dim3(NC / BN, NT / BM), 512, QSMEM, s1>>>();  /* idx 5 (s1) */
    cudaEventRecord(evQ, s1);
    k_eventkv<<<dim3(Bb, SS / 4), 512>>>(Wekr, Weki, Wevr, Wevi, sk, sv, sm, out); /* s0 */
    k_udot<<<dim3(Bb, SS / 8), 512>>>(out);             /* s0 */
    cudaStreamWaitEvent(0, evSplit, 0);                 /* dotgemm reads Ahi/Alo */
    k_dotgemm<<<NT / DM, 256, DSMEM>>>();               /* s0 */
    cudaStreamWaitEvent(0, evQ, 0);                     /* attn reads g_qp */
    k_attn<<<NT / 32, 1024, 131072>>>(out, gain);       /* s0 */
}

// round 13
// speedup vs baseline: 1.1772x; 1.0109x over previous
#include <cuda_runtime.h>
#include <cuda_fp16.h>
#include <math.h>
#include <stdint.h>

#define Bb   8
#define LL   4096
#define DIMC 512
#define SS   32
#define KK   8
#define NT   (Bb*LL)      /* 32768 tokens */
#define NC   (DIMC*2)     /* 1024 floats per token (interleaved r,i) */
#define THRv 0.5f
#define EPSv 1e-8f

/* output layout: concat(out, new_keys, new_values, new_mask, salience) */
#define OFF_OUT ((size_t)0)
#define OFF_NK  ((size_t)NT*NC)
#define OFF_NV  (OFF_NK + (size_t)Bb*SS*NC)
#define OFF_NM  (OFF_NV + (size_t)Bb*SS*NC)
#define OFF_SAL (OFF_NM + (size_t)Bb*SS)

/* scratch (device globals; no allocation allowed) */
__device__ float g_avg[NT];
__device__ float g_phase[NT];
__device__ float g_evp[(size_t)Bb*SS*8*NC];  /* evec chunk partials, 8MB */
__device__ float g_denp[Bb*SS*8];
__device__ float g_emask[Bb*SS];
__device__ int   g_rs[Bb*SS];
__device__ int   g_re[Bb*SS];
__device__ float g_kmag[Bb*SS];
__device__ __half g_BhiT[NC*NC];          /* B^T fp16, [n][k], 2MB */
__device__ __half g_Ahi[(size_t)NT*NC];   /* z hi fp16, 64MB */
__device__ __half g_Alo[(size_t)NT*NC];   /* z lo fp16, 64MB */
__device__ float g_WrT[DIMC*DIMC];        /* W_rq_r transposed, 1MB */
__device__ float g_WiT[DIMC*DIMC];        /* W_rq_i transposed, 1MB */
__device__ __half g_uh[Bb*SS*NC];         /* u hi fp16 */
__device__ __half g_ul[Bb*SS*NC];         /* u lo fp16 */
__device__ float g_qp[(size_t)NT*4];      /* qmag^2 partials per N-block */
__device__ float g_dot[(size_t)NT*SS];    /* dot[l,s], 4MB */

__device__ __forceinline__ float wred(float v) {
    #pragma unroll
    for (int o = 16; o; o >>= 1) v += __shfl_xor_sync(0xffffffffu, v, o);
    return v;
}

__device__ __forceinline__ float fsqrt(float x) {
    float y; asm("sqrt.approx.f32 %0, %1;" : "=f"(y) : "f"(x)); return y;
}
__device__ __forceinline__ float frcp(float x) {
    float y; asm("rcp.approx.f32 %0, %1;" : "=f"(y) : "f"(x)); return y;
}
__device__ __forceinline__ float frsqrt(float x) {
    float y; asm("rsqrt.approx.f32 %0, %1;" : "=f"(y) : "f"(x)); return y;
}

__device__ __forceinline__ void hsplit(float x, __half& h, __half& l) {
    h = __float2half_rn(x);
    l = __float2half_rn(x - __half2float(h));
}

__device__ __forceinline__ uint32_t smem_u32(const void* p) {
    uint32_t a;
    asm("{ .reg .u64 t; cvta.to.shared.u64 t, %1; cvt.u32.u64 %0, t; }"
        : "=r"(a) : "l"(p));
    return a;
}

__device__ __forceinline__ void ldsm4(uint32_t* r, uint32_t addr) {
    asm volatile("ldmatrix.sync.aligned.m8n8.x4.shared.b16 {%0,%1,%2,%3}, [%4];"
        : "=r"(r[0]), "=r"(r[1]), "=r"(r[2]), "=r"(r[3]) : "r"(addr));
}

__device__ __forceinline__ void mma16816(float* d, const uint32_t* a,
                                         uint32_t b0, uint32_t b1) {
    asm volatile(
        "mma.sync.aligned.m16n8k16.row.col.f32.f16.f16.f32 "
        "{%0,%1,%2,%3}, {%4,%5,%6,%7}, {%8,%9}, {%0,%1,%2,%3};"
        : "+f"(d[0]), "+f"(d[1]), "+f"(d[2]), "+f"(d[3])
        : "r"(a[0]), "r"(a[1]), "r"(a[2]), "r"(a[3]), "r"(b0), "r"(b1));
}

#define CP16(dst, src) \
    asm volatile("cp.async.cg.shared.global [%0], [%1], 16;" \
                 :: "r"(dst), "l"(src) : "memory")
#define CP_COMMIT() asm volatile("cp.async.commit_group;" ::: "memory")
#define CP_WAIT1()  asm volatile("cp.async.wait_group 1;" ::: "memory")
#define CP_WAIT2()  asm volatile("cp.async.wait_group 2;" ::: "memory")

/* ------------------------------------------------------------------ */
/* fused: per-token stats (avg/phase) + z -> fp16 hi/lo (one z pass) */
__global__ void k_stats(const float* __restrict__ z,
                        const float* __restrict__ Wsr,
                        const float* __restrict__ Wsi) {
    int gw = (blockIdx.x * blockDim.x + threadIdx.x) >> 5;
    int lane = threadIdx.x & 31;
    if (gw >= NT) return;
    const float4* z4 = (const float4*)(z + (size_t)gw * NC);
    __half2* ah = (__half2*)(g_Ahi + (size_t)gw * NC);
    __half2* al = (__half2*)(g_Alo + (size_t)gw * NC);
    float ms = 0.f, pr = 0.f, pi = 0.f;
    #pragma unroll
    for (int i = 0; i < 8; i++) {
        int p = lane + 32 * i;
        float4 v = z4[p];
        __half h0, l0, h1, l1, h2, l2, h3, l3;
        hsplit(v.x, h0, l0); hsplit(v.y, h1, l1);
        hsplit(v.z, h2, l2); hsplit(v.w, h3, l3);
        ah[2 * p]     = __halves2half2(h0, h1);
        ah[2 * p + 1] = __halves2half2(h2, h3);
        al[2 * p]     = __halves2half2(l0, l1);
        al[2 * p + 1] = __halves2half2(l2, l3);
        int d = 2 * p;
        ms += fsqrt(v.x*v.x + v.y*v.y + EPSv) + fsqrt(v.z*v.z + v.w*v.w + EPSv);
        float wr0 = Wsr[d], wi0 = Wsi[d], wr1 = Wsr[d+1], wi1 = Wsi[d+1];
        pr += v.x*wr0 - v.y*wi0 + v.z*wr1 - v.w*wi1;
        pi += v.x*wi0 + v.y*wr0 + v.z*wi1 + v.w*wr1;
    }
    ms = wred(ms); pr = wred(pr); pi = wred(pi);
    if (lane == 0) {
        g_avg[gw]   = ms * (1.f / DIMC);
        g_phase[gw] = fsqrt(pr*pr + pi*pi + EPSv);
    }
}

/* ------------------------------------------------------------------ */
__global__ void k_build_bt(const float* __restrict__ Wr,
                           const float* __restrict__ Wi) {
    __shared__ float tr[32][33], ti[32][33];
    int tx = threadIdx.x & 31, ty = threadIdx.x >> 5;
    int d0 = blockIdx.x * 32, e0 = blockIdx.y * 32;
    #pragma unroll
    for (int j = 0; j < 4; j++) {
        int d = d0 + ty + 8 * j;
        tr[ty + 8 * j][tx] = Wr[(size_t)d * DIMC + e0 + tx];
        ti[ty + 8 * j][tx] = Wi[(size_t)d * DIMC + e0 + tx];
    }
    __syncthreads();
    #pragma unroll
    for (int j = 0; j < 4; j++) {
        int e = e0 + ty + 8 * j;
        int d = d0 + tx;
        float wr = tr[tx][ty + 8 * j], wi = ti[tx][ty + 8 * j];
        size_t r0 = (size_t)(2 * e) * NC, r1 = (size_t)(2 * e + 1) * NC;
        g_BhiT[r0 + 2*d]     = __float2half_rn(wr);
        g_BhiT[r0 + 2*d + 1] = __float2half_rn(-wi);
        g_BhiT[r1 + 2*d]     = __float2half_rn(wi);
        g_BhiT[r1 + 2*d + 1] = __float2half_rn(wr);
        g_WrT[(size_t)e * DIMC + d] = wr;
        g_WiT[(size_t)e * DIMC + d] = wi;
    }
}

/* ------------------------------------------------------------------ */
/* fused salience + run detection; parallel prefix scan */
__global__ void k_runs(float* __restrict__ out,
                       const float* __restrict__ sb,
                       const float* __restrict__ ns) {
    __shared__ float sal[LL];
    __shared__ int scnt[256];
    int b = blockIdx.x, tid = threadIdx.x;
    float nsv = ns[0], sbv = sb[0];

    int l0 = tid * 16;
    for (int j = 0; j < 16; j++) {
        int l = l0 + j;
        int i = b * LL + l;
        float lm = 0.f;
        #pragma unroll
        for (int o = -2; o <= 2; o++) {
            int ll = l + o;
            if (ll >= 0 && ll < LL) lm += g_avg[i + o];
        }
        lm *= 0.2f;
        float x = g_phase[i] + (g_avg[i] - lm) * nsv + sbv;
        float s = frcp(1.f + __expf(-x));
        sal[l] = s;
        out[OFF_SAL + i] = s;
    }
    if (tid < SS) { g_rs[b*SS+tid] = 0; g_re[b*SS+tid] = 0; g_emask[b*SS+tid] = 0.f; }
    __syncthreads();

    bool prev0 = (l0 > 0) && (sal[l0 - 1] > THRv);
    bool pa = prev0;
    int cnt = 0;
    for (int j = 0; j < 16; j++) {
        bool ab = sal[l0 + j] > THRv;
        cnt += (ab && !pa);
        pa = ab;
    }
    scnt[tid] = cnt;
    __syncthreads();
    #pragma unroll
    for (int off = 1; off < 256; off <<= 1) {
        int add = (tid >= off) ? scnt[tid - off] : 0;
        __syncthreads();
        scnt[tid] += add;
        __syncthreads();
    }
    int e = scnt[tid] - cnt;   /* exclusive prefix */
    pa = prev0;
    for (int j = 0; j < 16; j++) {
        int l = l0 + j;
        bool ab = sal[l] > THRv;
        if (ab && !pa) {
            if (e < SS) { g_rs[b*SS + e] = l; g_emask[b*SS + e] = 1.f; }
            e++;
        }
        if (ab && (e - 1) < SS) {
            bool nx = (l + 1 < LL) && (sal[l + 1] > THRv);
            if (!nx) g_re[b*SS + (e - 1)] = l + 1;
        }
        pa = ab;
    }
}

/* event vector partials: 8 chunk-blocks per run */
__global__ void k_evec1(const float* __restrict__ z,
                        const float* __restrict__ out) {
    int bs = blockIdx.x >> 3, ch = blockIdx.x & 7;
    int b = bs / SS;
    int rs = g_rs[bs], re = g_re[bs];
    int len = re - rs;
    int clen = (len + 7) >> 3;
    int ls = rs + ch * clen;
    int le = min(ls + clen, re);
    const float* sal = out + OFF_SAL + (size_t)b * LL;
    int t = threadIdx.x;
    float a0 = 0.f, a1 = 0.f, a2 = 0.f, a3 = 0.f, den = 0.f;
    for (int l = ls; l < le; l++) {
        float w = sal[l];
        den += w;
        const float* zt = z + ((size_t)b * LL + l) * NC;
        a0 += w * zt[t];       a1 += w * zt[t + 256];
        a2 += w * zt[t + 512]; a3 += w * zt[t + 768];
    }
    float* ev = g_evp + (size_t)(bs * 8 + ch) * NC;
    ev[t] = a0; ev[t + 256] = a1; ev[t + 512] = a2; ev[t + 768] = a3;
    if (t == 0) g_denp[bs * 8 + ch] = den;
}

/* event K/V projection + blend + kmag + new_mask; combines evec partials.
   4 slots per block, grid (Bb, SS/4), 512 threads. */
__global__ void __launch_bounds__(512, 2)
k_eventkv(const float* __restrict__ Wekr, const float* __restrict__ Weki,
          const float* __restrict__ Wevr, const float* __restrict__ Wevi,
          const float* __restrict__ sk,   const float* __restrict__ svv,
          const float* __restrict__ smk,  float* __restrict__ out) {
    int b = blockIdx.x, sg = blockIdx.y;
    int e = threadIdx.x;
    int bs0 = b * SS + sg * 4;
    __shared__ float sv[4][NC];
    __shared__ float sinv[4];
    __shared__ float wpart[4][16];
    if (e < 4) {
        float den = 0.f;
        #pragma unroll
        for (int ch = 0; ch < 8; ch++) den += g_denp[(bs0 + e) * 8 + ch];
        sinv[e] = frcp(fmaxf(den, EPSv));
    }
    __syncthreads();
    for (int i = e; i < 4 * NC; i += 512) {
        int slot = i >> 10, dim = i & (NC - 1);
        float a = 0.f;
        #pragma unroll
        for (int ch = 0; ch < 8; ch++)
            a += g_evp[(size_t)((bs0 + slot) * 8 + ch) * NC + dim];
        sv[slot][dim] = a * sinv[slot];
    }
    __syncthreads();

    float KR[4] = {0,0,0,0}, KI[4] = {0,0,0,0};
    float VR[4] = {0,0,0,0}, VI[4] = {0,0,0,0};
    for (int d = 0; d < DIMC; d++) {
        float wkr = Wekr[d * DIMC + e], wki = Weki[d * DIMC + e];
        float wvr = Wevr[d * DIMC + e], wvi = Wevi[d * DIMC + e];
        #pragma unroll
        for (int s2 = 0; s2 < 4; s2++) {
            float zr = sv[s2][2 * d], zi = sv[s2][2 * d + 1];
            KR[s2] += zr * wkr - zi * wki;
            KI[s2] += zr * wki + zi * wkr;
            VR[s2] += zr * wvr - zi * wvi;
            VI[s2] += zr * wvi + zi * wvr;
        }
    }
    int lane = e & 31, wid = e >> 5;
    #pragma unroll
    for (int s2 = 0; s2 < 4; s2++) {
        int bs = bs0 + s2;
        float m = g_emask[bs];
        size_t off = (size_t)bs * NC + 2 * e;
        float nkr = m * KR[s2] + (1.f - m) * sk[off];
        float nki = m * KI[s2] + (1.f - m) * sk[off + 1];
        float nvr = m * VR[s2] + (1.f - m) * svv[off];
        float nvi = m * VI[s2] + (1.f - m) * svv[off + 1];
        out[OFF_NK + off] = nkr; out[OFF_NK + off + 1] = nki;
        out[OFF_NV + off] = nvr; out[OFF_NV + off + 1] = nvi;
        if (e == 0) out[OFF_NM + bs] = fminf(smk[bs] + m, 1.f);
        float p = wred(nkr * nkr + nki * nki);
        if (lane == 0) wpart[s2][wid] = p;
    }
    __syncthreads();
    if (e < 4) {
        float sum = 0.f;
        #pragma unroll
        for (int i = 0; i < 16; i++) sum += wpart[e][i];
        g_kmag[bs0 + e] = fsqrt(sum + EPSv);
    }
}

/* ------------------------------------------------------------------ */
/* u_{b,s} = B * kappa_{b,s}; grid (Bb, SS/8), 512 thr */
__global__ void __launch_bounds__(512, 2)
k_udot(const float* __restrict__ out) {
    __shared__ float ka[8][NC];
    int b = blockIdx.x, sg = blockIdx.y;
    int tid = threadIdx.x;
    const float* ksrc = out + OFF_NK + (size_t)(b * SS + sg * 8) * NC;
    for (int i = tid; i < 8 * NC; i += 512)
        ((float*)ka)[i] = ksrc[i];
    __syncthreads();
    int e = tid;
    float ur[8], ui[8];
    #pragma unroll
    for (int s = 0; s < 8; s++) { ur[s] = 0.f; ui[s] = 0.f; }
    for (int j = 0; j < DIMC; j++) {
        float wr = g_WrT[(size_t)j * DIMC + e];
        float wi = g_WiT[(size_t)j * DIMC + e];
        #pragma unroll
        for (int s = 0; s < 8; s++) {
            float2 kp = *(const float2*)&ka[s][2 * j];
            ur[s] += wr * kp.x + wi * kp.y;
            ui[s] += wr * kp.y - wi * kp.x;
        }
    }
    #pragma unroll
    for (int s = 0; s < 8; s++) {
        int bs = b * SS + sg * 8 + s;
        __half hr, lr, hi2, li;
        hsplit(ur[s], hr, lr);
        hsplit(ui[s], hi2, li);
        ((__half2*)(g_uh + (size_t)bs * NC))[e] = __halves2half2(hr, hi2);
        ((__half2*)(g_ul + (size_t)bs * NC))[e] = __halves2half2(lr, li);
    }
}

/* ------------------------------------------------------------------ */
/* qmag GEMM: single-term fp16, BM=128 BN=256 BK=32, 512 thr, 4-stage. */
#define BM 128
#define BN 256
#define PITCH 80
#define A_SZ (BM * PITCH)
#define B_SZ (BN * PITCH)
#define STAGE_SZ (A_SZ + B_SZ)
#define NSTGQ 4
#define QSMEM (NSTGQ * STAGE_SZ)      /* 122880 */
#define NIT (NC / 32)

__global__ void __launch_bounds__(512, 1)
k_qgemm_mma() {
    extern __shared__ unsigned char smq[];
    __shared__ float qp_sm[4][BM];
    int t = threadIdx.x, lane = t & 31, wid = t >> 5;
    int m0 = blockIdx.y * BM, n0 = blockIdx.x * BN;
    int warpM = (wid & 3) * 32, warpN = (wid >> 2) * 64;

    uint32_t sb0 = smem_u32(smq);
    const uint4* srcA = (const uint4*)(g_Ahi  + (size_t)(m0 + (t >> 2)) * NC) + (t & 3);
    int bi0 = t, bi1 = t + 512;
    const uint4* srcB0 = (const uint4*)(g_BhiT + (size_t)(n0 + (bi0 >> 2)) * NC) + (bi0 & 3);
    const uint4* srcB1 = (const uint4*)(g_BhiT + (size_t)(n0 + (bi1 >> 2)) * NC) + (bi1 & 3);
    uint32_t dstA  = sb0 + (uint32_t)((t >> 2) * PITCH + (t & 3) * 16);
    uint32_t dstB0 = sb0 + (uint32_t)(A_SZ + (bi0 >> 2) * PITCH + (bi0 & 3) * 16);
    uint32_t dstB1 = sb0 + (uint32_t)(A_SZ + (bi1 >> 2) * PITCH + (bi1 & 3) * 16);

    uint32_t aoff = (uint32_t)((warpM + (lane & 15)) * PITCH + ((lane >> 4) << 4));
    uint32_t boff = (uint32_t)(A_SZ + (warpN + (lane & 7) + ((lane >> 4) & 1) * 8) * PITCH
                               + (((lane >> 3) & 1) << 4));

    float acc[2][8][4];
    #pragma unroll
    for (int i = 0; i < 2; i++)
        #pragma unroll
        for (int j = 0; j < 8; j++)
            #pragma unroll
            for (int k = 0; k < 4; k++) acc[i][j][k] = 0.f;

    #pragma unroll
    for (int s = 0; s < 3; s++) {
        uint32_t off = (uint32_t)(s * STAGE_SZ);
        CP16(dstA + off,  srcA  + s * 4);
        CP16(dstB0 + off, srcB0 + s * 4);
        CP16(dstB1 + off, srcB1 + s * 4);
        CP_COMMIT();
    }

    for (int it = 0; it < NIT; it++) {
        CP_WAIT2();
        __syncthreads();
        uint32_t st = sb0 + (uint32_t)((it % NSTGQ) * STAGE_SZ);
        uint32_t aAh = st + aoff;
        uint32_t aBh = st + boff;

        #pragma unroll
        for (int ko = 0; ko < 2; ko++) {
            uint32_t ah[2][4], bh[4][4];
            #pragma unroll
            for (int mg = 0; mg < 2; mg++)
                ldsm4(ah[mg], aAh + mg * (16 * PITCH) + ko * 32);
            #pragma unroll
            for (int ng = 0; ng < 4; ng++)
                ldsm4(bh[ng], aBh + ng * (16 * PITCH) + ko * 32);
            #pragma unroll
            for (int mg = 0; mg < 2; mg++)
                #pragma unroll
                for (int ng = 0; ng < 4; ng++)
                    #pragma unroll
                    for (int h = 0; h < 2; h++)
                        mma16816(acc[mg][ng * 2 + h], ah[mg],
                                 bh[ng][h*2], bh[ng][h*2+1]);
        }

        if (it + 3 < NIT) {
            uint32_t off = (uint32_t)(((it + 3) % NSTGQ) * STAGE_SZ);
            CP16(dstA + off,  srcA  + (it + 3) * 4);
            CP16(dstB0 + off, srcB0 + (it + 3) * 4);
            CP16(dstB1 + off, srcB1 + (it + 3) * 4);
        }
        CP_COMMIT();
    }

    #pragma unroll
    for (int mg = 0; mg < 2; mg++) {
        float rp0 = 0.f, rp1 = 0.f;
        #pragma unroll
        for (int j = 0; j < 8; j++) {
            float* d = acc[mg][j];
            rp0 += d[0]*d[0] + d[1]*d[1];
            rp1 += d[2]*d[2] + d[3]*d[3];
        }
        rp0 += __shfl_xor_sync(0xffffffffu, rp0, 1);
        rp0 += __shfl_xor_sync(0xffffffffu, rp0, 2);
        rp1 += __shfl_xor_sync(0xffffffffu, rp1, 1);
        rp1 += __shfl_xor_sync(0xffffffffu, rp1, 2);
        if ((lane & 3) == 0) {
            int r = warpM + mg * 16 + (lane >> 2);
            qp_sm[wid >> 2][r]     = rp0;
            qp_sm[wid >> 2][r + 8] = rp1;
        }
    }
    __syncthreads();
    if (t < BM)
        g_qp[(size_t)(m0 + t) * 4 + blockIdx.x] =
            qp_sm[0][t] + qp_sm[1][t] + qp_sm[2][t] + qp_sm[3][t];
}

/* ------------------------------------------------------------------ */
/* dot GEMM: dot[l,s] = z_l . u_s, 3-term fp16 (hh+hl+lh). */
#define DM 128
#define DA_SZ (DM * PITCH)
#define DSTG (2 * DA_SZ)
#define PB 2064
#define B_HL (SS * PB)
#define DB_OFF (3 * DSTG)
#define DSMEM (DB_OFF + 2 * B_HL)
#define NITD (NC / 32)

__global__ void __launch_bounds__(256, 1)
k_dotgemm() {
    extern __shared__ unsigned char smd[];
    int t = threadIdx.x, lane = t & 31, wid = t >> 5;
    int m0 = blockIdx.x * DM;
    int batch = blockIdx.x >> 5;
    int warpM = wid * 16;

    uint32_t sb0 = smem_u32(smd);

    #pragma unroll
    for (int u = 0; u < 16; u++) {
        int idx = t + 256 * u;
        int row = idx >> 7, col = idx & 127;
        uint32_t d0 = sb0 + (uint32_t)(DB_OFF + row * PB + col * 16);
        const uint4* sh = (const uint4*)(g_uh + (size_t)(batch * SS + row) * NC) + col;
        const uint4* sl = (const uint4*)(g_ul + (size_t)(batch * SS + row) * NC) + col;
        CP16(d0, sh);
        CP16(d0 + B_HL, sl);
    }
    int ai0 = t, ai1 = t + 256;
    const uint4* sAh0 = (const uint4*)(g_Ahi + (size_t)(m0 + (ai0 >> 2)) * NC) + (ai0 & 3);
    const uint4* sAh1 = (const uint4*)(g_Ahi + (size_t)(m0 + (ai1 >> 2)) * NC) + (ai1 & 3);
    const uint4* sAl0 = (const uint4*)(g_Alo + (size_t)(m0 + (ai0 >> 2)) * NC) + (ai0 & 3);
    const uint4* sAl1 = (const uint4*)(g_Alo + (size_t)(m0 + (ai1 >> 2)) * NC) + (ai1 & 3);
    uint32_t dA0 = sb0 + (uint32_t)((ai0 >> 2) * PITCH + (ai0 & 3) * 16);
    uint32_t dA1 = sb0 + (uint32_t)((ai1 >> 2) * PITCH + (ai1 & 3) * 16);

    #pragma unroll
    for (int s = 0; s < 2; s++) {
        uint32_t off = (uint32_t)(s * DSTG);
        CP16(dA0 + off, sAh0 + s * 4);          CP16(dA1 + off, sAh1 + s * 4);
        CP16(dA0 + off + DA_SZ, sAl0 + s * 4);  CP16(dA1 + off + DA_SZ, sAl1 + s * 4);
        CP_COMMIT();
    }

    uint32_t aoff = (uint32_t)((warpM + (lane & 15)) * PITCH + ((lane >> 4) << 4));
    uint32_t boffB = (uint32_t)(DB_OFF + ((lane & 7) + ((lane >> 4) & 1) * 8) * PB
                                + (((lane >> 3) & 1) << 4));

    float acc[4][4];
    #pragma unroll
    for (int j = 0; j < 4; j++)
        #pragma unroll
        for (int k = 0; k < 4; k++) acc[j][k] = 0.f;

    for (int it = 0; it < NITD; it++) {
        CP_WAIT1();
        __syncthreads();
        uint32_t st = sb0 + (uint32_t)((it % 3) * DSTG);
        #pragma unroll
        for (int ko = 0; ko < 2; ko++) {
            uint32_t ah[4], al[4], bh[2][4], bl[2][4];
            ldsm4(ah, st + aoff + ko * 32);
            ldsm4(al, st + DA_SZ + aoff + ko * 32);
            #pragma unroll
            for (int ng = 0; ng < 2; ng++) {
                uint32_t ba = sb0 + boffB + ng * (16 * PB) + it * 64 + ko * 32;
                ldsm4(bh[ng], ba);
                ldsm4(bl[ng], ba + B_HL);
            }
            #pragma unroll
            for (int ng = 0; ng < 2; ng++)
                #pragma unroll
                for (int h = 0; h < 2; h++) {
                    float* d = acc[ng * 2 + h];
                    mma16816(d, al, bh[ng][h*2], bh[ng][h*2+1]);
                    mma16816(d, ah, bl[ng][h*2], bl[ng][h*2+1]);
                    mma16816(d, ah, bh[ng][h*2], bh[ng][h*2+1]);
                }
        }
        if (it + 2 < NITD) {
            uint32_t off = (uint32_t)(((it + 2) % 3) * DSTG);
            CP16(dA0 + off, sAh0 + (it + 2) * 4);          CP16(dA1 + off, sAh1 + (it + 2) * 4);
            CP16(dA0 + off + DA_SZ, sAl0 + (it + 2) * 4);  CP16(dA1 + off + DA_SZ, sAl1 + (it + 2) * 4);
        }
        CP_COMMIT();
    }

    #pragma unroll
    for (int j = 0; j < 4; j++) {
        float* d = acc[j];
        int r = m0 + warpM + (lane >> 2);
        int c = j * 8 + (lane & 3) * 2;
        *(float2*)&g_dot[(size_t)r * SS + c]       = make_float2(d[0], d[1]);
        *(float2*)&g_dot[(size_t)(r + 8) * SS + c] = make_float2(d[2], d[3]);
    }
}

/* ------------------------------------------------------------------ */
/* attention: warp/token, 32 tokens/block (1024 thr); V staged in smem. */
__global__ void __launch_bounds__(1024, 1)
k_attn(float* __restrict__ out, const float* __restrict__ gain) {
    extern __shared__ float4 sV[];
    __shared__ float sKmag[SS];
    __shared__ float sMask[SS];
    int tid = threadIdx.x, warp = tid >> 5, lane = tid & 31;
    int tok0 = blockIdx.x * 32;
    int b = tok0 / LL;

    const float4* Vsrc = (const float4*)(out + OFF_NV + (size_t)b * SS * NC);
    for (int i = tid; i < SS * NC / 4; i += 1024) sV[i] = Vsrc[i];
    if (tid < SS) {
        sKmag[tid] = g_kmag[b * SS + tid];
        sMask[tid] = out[OFF_NM + b * SS + tid];
    }
    __syncthreads();

    int token = tok0 + warp;
    float qp = (lane < 4) ? g_qp[(size_t)token * 4 + lane] : 0.f;
    qp = wred(qp);
    float qmag = fsqrt(qp + EPSv);

    float dval = g_dot[(size_t)token * SS + lane];
    float myscore = dval * frcp(qmag * sKmag[lane] + EPSv);
    if (sMask[lane] == 0.f) myscore = -1e9f;

    float vcur = myscore;
    float topv[KK]; int topi[KK];
    #pragma unroll
    for (int j = 0; j < KK; j++) {
        float v = vcur; int idx = lane;
        #pragma unroll
        for (int o = 16; o; o >>= 1) {
            float v2 = __shfl_xor_sync(0xffffffffu, v, o);
            int   i2 = __shfl_xor_sync(0xffffffffu, idx, o);
            if (v2 > v || (v2 == v && i2 < idx)) { v = v2; idx = i2; }
        }
        topv[j] = v; topi[j] = idx;
        if (lane == idx) vcur = -INFINITY;
    }
    float w[KK], wsum = 0.f, mx = topv[0];
    #pragma unroll
    for (int j = 0; j < KK; j++) { w[j] = __expf(topv[j] - mx); wsum += w[j]; }
    float winv = frcp(wsum);

    float4 r[8];
    #pragma unroll
    for (int i = 0; i < 8; i++) r[i] = make_float4(0.f, 0.f, 0.f, 0.f);
    #pragma unroll
    for (int j = 0; j < KK; j++) {
        float a = w[j] * winv;
        const float4* Vr = sV + topi[j] * 256;
        #pragma unroll
        for (int i = 0; i < 8; i++) {
            float4 vv = Vr[lane + 32 * i];
            r[i].x += a * vv.x; r[i].y += a * vv.y;
            r[i].z += a * vv.z; r[i].w += a * vv.w;
        }
    }
    float ssum = 0.f;
    #pragma unroll
    for (int i = 0; i < 8; i++)
        ssum += r[i].x*r[i].x + r[i].y*r[i].y + r[i].z*r[i].z + r[i].w*r[i].w;
    ssum = wred(ssum);
    float rinv = frsqrt(ssum * (1.f / DIMC) + EPSv);

    const float2* g2 = (const float2*)gain;
    float4* orow = (float4*)(out + (size_t)token * NC);
    #pragma unroll
    for (int i = 0; i < 8; i++) {
        float2 g = g2[lane + 32 * i];
        float4 o;
        o.x = r[i].x * rinv * g.x; o.y = r[i].y * rinv * g.x;
        o.z = r[i].z * rinv * g.y; o.w = r[i].w * rinv * g.y;
        orow[lane + 32 * i] = o;
    }
}

/* ------------------------------------------------------------------ */
extern "C" void kernel_launch(void* const* d_in, const int* in_sizes, int n_in,
                              void* d_out, int out_size) {
    const float* z    = (const float*)d_in[0];
    const float* sk   = (const float*)d_in[1];
    const float* sv   = (const float*)d_in[2];
    const float* sm   = (const float*)d_in[3];
    const float* Wsr  = (const float*)d_in[4];
    const float* Wsi  = (const float*)d_in[5];
    const float* sb   = (const float*)d_in[6];
    const float* ns   = (const float*)d_in[7];
    const float* Wekr = (const float*)d_in[8];
    const float* Weki = (const float*)d_in[9];
    const float* Wevr = (const float*)d_in[10];
    const float* Wevi = (const float*)d_in[11];
    const float* Wrqr = (const float*)d_in[12];
    const float* Wrqi = (const float*)d_in[13];
    const float* gain = (const float*)d_in[14];
    float* out = (float*)d_out;

    static bool init_done = false;
    static cudaStream_t s1;
    static cudaEvent_t evRoot, evStats, evQ;
    if (!init_done) {
        cudaFuncSetAttribute(k_attn, cudaFuncAttributeMaxDynamicSharedMemorySize, 131072);
        cudaFuncSetAttribute(k_qgemm_mma, cudaFuncAttributeMaxDynamicSharedMemorySize, QSMEM);
        cudaFuncSetAttribute(k_dotgemm, cudaFuncAttributeMaxDynamicSharedMemorySize, DSMEM);
        cudaStreamCreateWithFlags(&s1, cudaStreamNonBlocking);
        cudaEventCreateWithFlags(&evRoot, cudaEventDisableTiming);
        cudaEventCreateWithFlags(&evStats, cudaEventDisableTiming);
        cudaEventCreateWithFlags(&evQ, cudaEventDisableTiming);
        init_done = true;
    }

    /* fork at root: s1 = build_bt (immediately) -> qgemm (after stats) */
    cudaEventRecord(evRoot, 0);
    cudaStreamWaitEvent(s1, evRoot, 0);

    k_stats<<<4096, 256>>>(z, Wsr, Wsi);                /* idx 0 (s0): one z pass */
    cudaEventRecord(evStats, 0);
    k_runs<<<Bb, 256>>>(out, sb, ns);                   /* idx 1 (s0) */
    k_evec1<<<Bb * SS * 8, 256>>>(z, out);              /* idx 2 (s0) */
    k_eventkv<<<dim3(Bb, SS / 4), 512>>>(Wekr, Weki, Wevr, Wevi, sk, sv, sm, out); /* idx 3: profiled */
    k_build_bt<<<dim3(16, 16), 256, 0, s1>>>(Wrqr, Wrqi);  /* idx 4 (s1) */
    cudaStreamWaitEvent(s1, evStats, 0);
    k_qgemm_mma<<<dim3(NC / BN, NT / BM), 512, QSMEM, s1>>>();  /* idx 5 (s1) */
    cudaEventRecord(evQ, s1);
    k_udot<<<dim3(Bb, SS / 8), 512>>>(out);             /* idx 6 (s0) */
    k_dotgemm<<<NT / DM, 256, DSMEM>>>();               /* idx 7 (s0) */
    cudaStreamWaitEvent(0, evQ, 0);                     /* attn reads g_qp */
    k_attn<<<NT / 32, 1024, 131072>>>(out, gain);       /* idx 8 (s0) */
}

// round 14
// speedup vs baseline: 1.7297x; 1.4693x over previous
#include <cuda_runtime.h>
#include <cuda_fp16.h>
#include <math.h>
#include <stdint.h>

#define Bb   8
#define LL   4096
#define DIMC 512
#define SS   32
#define KK   8
#define NT   (Bb*LL)      /* 32768 tokens */
#define NC   (DIMC*2)     /* 1024 floats per token (interleaved r,i) */
#define THRv 0.5f
#define EPSv 1e-8f

/* output layout: concat(out, new_keys, new_values, new_mask, salience) */
#define OFF_OUT ((size_t)0)
#define OFF_NK  ((size_t)NT*NC)
#define OFF_NV  (OFF_NK + (size_t)Bb*SS*NC)
#define OFF_NM  (OFF_NV + (size_t)Bb*SS*NC)
#define OFF_SAL (OFF_NM + (size_t)Bb*SS)

/* scratch (device globals; no allocation allowed) */
__device__ float g_avg[NT];
__device__ float g_phase[NT];
__device__ float g_evp[(size_t)Bb*SS*8*NC];  /* evec chunk partials, 8MB */
__device__ float g_denp[Bb*SS*8];
__device__ float g_emask[Bb*SS];
__device__ int   g_rs[Bb*SS];
__device__ int   g_re[Bb*SS];
__device__ float g_kmag[Bb*SS];
__device__ float g_kvp[(size_t)Bb*SS*4*4*DIMC]; /* [bs][chunk][KR,KI,VR,VI][e], 8MB */
__device__ float g_up[(size_t)Bb*SS*4*NC];      /* [bs][chunk][ur,ui interleaved], 4MB */
__device__ __half g_BhiT[NC*NC];          /* B^T fp16, [n][k], 2MB */
__device__ __half g_Ahi[(size_t)NT*NC];   /* z hi fp16, 64MB */
__device__ __half g_Alo[(size_t)NT*NC];   /* z lo fp16, 64MB */
__device__ float g_WrT[DIMC*DIMC];        /* W_rq_r transposed, 1MB */
__device__ float g_WiT[DIMC*DIMC];        /* W_rq_i transposed, 1MB */
__device__ __half g_uh[Bb*SS*NC];         /* u hi fp16 */
__device__ __half g_ul[Bb*SS*NC];         /* u lo fp16 */
__device__ float g_qp[(size_t)NT*4];      /* qmag^2 partials per N-block */
__device__ float g_dot[(size_t)NT*SS];    /* dot[l,s], 4MB */

__device__ __forceinline__ float wred(float v) {
    #pragma unroll
    for (int o = 16; o; o >>= 1) v += __shfl_xor_sync(0xffffffffu, v, o);
    return v;
}

__device__ __forceinline__ float fsqrt(float x) {
    float y; asm("sqrt.approx.f32 %0, %1;" : "=f"(y) : "f"(x)); return y;
}
__device__ __forceinline__ float frcp(float x) {
    float y; asm("rcp.approx.f32 %0, %1;" : "=f"(y) : "f"(x)); return y;
}
__device__ __forceinline__ float frsqrt(float x) {
    float y; asm("rsqrt.approx.f32 %0, %1;" : "=f"(y) : "f"(x)); return y;
}

__device__ __forceinline__ void hsplit(float x, __half& h, __half& l) {
    h = __float2half_rn(x);
    l = __float2half_rn(x - __half2float(h));
}

__device__ __forceinline__ uint32_t smem_u32(const void* p) {
    uint32_t a;
    asm("{ .reg .u64 t; cvta.to.shared.u64 t, %1; cvt.u32.u64 %0, t; }"
        : "=r"(a) : "l"(p));
    return a;
}

__device__ __forceinline__ void ldsm4(uint32_t* r, uint32_t addr) {
    asm volatile("ldmatrix.sync.aligned.m8n8.x4.shared.b16 {%0,%1,%2,%3}, [%4];"
        : "=r"(r[0]), "=r"(r[1]), "=r"(r[2]), "=r"(r[3]) : "r"(addr));
}

__device__ __forceinline__ void mma16816(float* d, const uint32_t* a,
                                         uint32_t b0, uint32_t b1) {
    asm volatile(
        "mma.sync.aligned.m16n8k16.row.col.f32.f16.f16.f32 "
        "{%0,%1,%2,%3}, {%4,%5,%6,%7}, {%8,%9}, {%0,%1,%2,%3};"
        : "+f"(d[0]), "+f"(d[1]), "+f"(d[2]), "+f"(d[3])
        : "r"(a[0]), "r"(a[1]), "r"(a[2]), "r"(a[3]), "r"(b0), "r"(b1));
}

#define CP16(dst, src) \
    asm volatile("cp.async.cg.shared.global [%0], [%1], 16;" \
                 :: "r"(dst), "l"(src) : "memory")
#define CP_COMMIT() asm volatile("cp.async.commit_group;" ::: "memory")
#define CP_WAIT1()  asm volatile("cp.async.wait_group 1;" ::: "memory")
#define CP_WAIT2()  asm volatile("cp.async.wait_group 2;" ::: "memory")

/* ------------------------------------------------------------------ */
/* fused: per-token stats (avg/phase) + z -> fp16 hi/lo (one z pass) */
__global__ void k_stats(const float* __restrict__ z,
                        const float* __restrict__ Wsr,
                        const float* __restrict__ Wsi) {
    int gw = (blockIdx.x * blockDim.x + threadIdx.x) >> 5;
    int lane = threadIdx.x & 31;
    if (gw >= NT) return;
    const float4* z4 = (const float4*)(z + (size_t)gw * NC);
    __half2* ah = (__half2*)(g_Ahi + (size_t)gw * NC);
    __half2* al = (__half2*)(g_Alo + (size_t)gw * NC);
    float ms = 0.f, pr = 0.f, pi = 0.f;
    #pragma unroll
    for (int i = 0; i < 8; i++) {
        int p = lane + 32 * i;
        float4 v = z4[p];
        __half h0, l0, h1, l1, h2, l2, h3, l3;
        hsplit(v.x, h0, l0); hsplit(v.y, h1, l1);
        hsplit(v.z, h2, l2); hsplit(v.w, h3, l3);
        ah[2 * p]     = __halves2half2(h0, h1);
        ah[2 * p + 1] = __halves2half2(h2, h3);
        al[2 * p]     = __halves2half2(l0, l1);
        al[2 * p + 1] = __halves2half2(l2, l3);
        int d = 2 * p;
        ms += fsqrt(v.x*v.x + v.y*v.y + EPSv) + fsqrt(v.z*v.z + v.w*v.w + EPSv);
        float wr0 = Wsr[d], wi0 = Wsi[d], wr1 = Wsr[d+1], wi1 = Wsi[d+1];
        pr += v.x*wr0 - v.y*wi0 + v.z*wr1 - v.w*wi1;
        pi += v.x*wi0 + v.y*wr0 + v.z*wi1 + v.w*wr1;
    }
    ms = wred(ms); pr = wred(pr); pi = wred(pi);
    if (lane == 0) {
        g_avg[gw]   = ms * (1.f / DIMC);
        g_phase[gw] = fsqrt(pr*pr + pi*pi + EPSv);
    }
}

/* ------------------------------------------------------------------ */
__global__ void k_build_bt(const float* __restrict__ Wr,
                           const float* __restrict__ Wi) {
    __shared__ float tr[32][33], ti[32][33];
    int tx = threadIdx.x & 31, ty = threadIdx.x >> 5;
    int d0 = blockIdx.x * 32, e0 = blockIdx.y * 32;
    #pragma unroll
    for (int j = 0; j < 4; j++) {
        int d = d0 + ty + 8 * j;
        tr[ty + 8 * j][tx] = Wr[(size_t)d * DIMC + e0 + tx];
        ti[ty + 8 * j][tx] = Wi[(size_t)d * DIMC + e0 + tx];
    }
    __syncthreads();
    #pragma unroll
    for (int j = 0; j < 4; j++) {
        int e = e0 + ty + 8 * j;
        int d = d0 + tx;
        float wr = tr[tx][ty + 8 * j], wi = ti[tx][ty + 8 * j];
        size_t r0 = (size_t)(2 * e) * NC, r1 = (size_t)(2 * e + 1) * NC;
        g_BhiT[r0 + 2*d]     = __float2half_rn(wr);
        g_BhiT[r0 + 2*d + 1] = __float2half_rn(-wi);
        g_BhiT[r1 + 2*d]     = __float2half_rn(wi);
        g_BhiT[r1 + 2*d + 1] = __float2half_rn(wr);
        g_WrT[(size_t)e * DIMC + d] = wr;
        g_WiT[(size_t)e * DIMC + d] = wi;
    }
}

/* ------------------------------------------------------------------ */
/* fused salience + run detection; parallel prefix scan */
__global__ void k_runs(float* __restrict__ out,
                       const float* __restrict__ sb,
                       const float* __restrict__ ns) {
    __shared__ float sal[LL];
    __shared__ int scnt[256];
    int b = blockIdx.x, tid = threadIdx.x;
    float nsv = ns[0], sbv = sb[0];

    int l0 = tid * 16;
    for (int j = 0; j < 16; j++) {
        int l = l0 + j;
        int i = b * LL + l;
        float lm = 0.f;
        #pragma unroll
        for (int o = -2; o <= 2; o++) {
            int ll = l + o;
            if (ll >= 0 && ll < LL) lm += g_avg[i + o];
        }
        lm *= 0.2f;
        float x = g_phase[i] + (g_avg[i] - lm) * nsv + sbv;
        float s = frcp(1.f + __expf(-x));
        sal[l] = s;
        out[OFF_SAL + i] = s;
    }
    if (tid < SS) { g_rs[b*SS+tid] = 0; g_re[b*SS+tid] = 0; g_emask[b*SS+tid] = 0.f; }
    __syncthreads();

    bool prev0 = (l0 > 0) && (sal[l0 - 1] > THRv);
    bool pa = prev0;
    int cnt = 0;
    for (int j = 0; j < 16; j++) {
        bool ab = sal[l0 + j] > THRv;
        cnt += (ab && !pa);
        pa = ab;
    }
    scnt[tid] = cnt;
    __syncthreads();
    #pragma unroll
    for (int off = 1; off < 256; off <<= 1) {
        int add = (tid >= off) ? scnt[tid - off] : 0;
        __syncthreads();
        scnt[tid] += add;
        __syncthreads();
    }
    int e = scnt[tid] - cnt;
    pa = prev0;
    for (int j = 0; j < 16; j++) {
        int l = l0 + j;
        bool ab = sal[l] > THRv;
        if (ab && !pa) {
            if (e < SS) { g_rs[b*SS + e] = l; g_emask[b*SS + e] = 1.f; }
            e++;
        }
        if (ab && (e - 1) < SS) {
            bool nx = (l + 1 < LL) && (sal[l + 1] > THRv);
            if (!nx) g_re[b*SS + (e - 1)] = l + 1;
        }
        pa = ab;
    }
}

/* event vector partials: 8 chunk-blocks per run */
__global__ void k_evec1(const float* __restrict__ z,
                        const float* __restrict__ out) {
    int bs = blockIdx.x >> 3, ch = blockIdx.x & 7;
    int b = bs / SS;
    int rs = g_rs[bs], re = g_re[bs];
    int len = re - rs;
    int clen = (len + 7) >> 3;
    int ls = rs + ch * clen;
    int le = min(ls + clen, re);
    const float* sal = out + OFF_SAL + (size_t)b * LL;
    int t = threadIdx.x;
    float a0 = 0.f, a1 = 0.f, a2 = 0.f, a3 = 0.f, den = 0.f;
    for (int l = ls; l < le; l++) {
        float w = sal[l];
        den += w;
        const float* zt = z + ((size_t)b * LL + l) * NC;
        a0 += w * zt[t];       a1 += w * zt[t + 256];
        a2 += w * zt[t + 512]; a3 += w * zt[t + 768];
    }
    float* ev = g_evp + (size_t)(bs * 8 + ch) * NC;
    ev[t] = a0; ev[t + 256] = a1; ev[t + 512] = a2; ev[t + 768] = a3;
    if (t == 0) g_denp[bs * 8 + ch] = den;
}

/* ------------------------------------------------------------------ */
/* event K/V projection partials: grid (Bb, SS/4, 4 d-chunks), 512 thr.
   Each block: 4 slots, d in [128*dc, 128*dc+128). */
__global__ void __launch_bounds__(512, 2)
k_ekv1(const float* __restrict__ Wekr, const float* __restrict__ Weki,
       const float* __restrict__ Wevr, const float* __restrict__ Wevi) {
    int b = blockIdx.x, sg = blockIdx.y, dc = blockIdx.z;
    int e = threadIdx.x;
    int bs0 = b * SS + sg * 4;
    int d0 = dc * 128;
    __shared__ float sv[4][256];    /* evec dims [2*d0, 2*d0+256) */
    __shared__ float sinv[4];
    if (e < 4) {
        float den = 0.f;
        #pragma unroll
        for (int ch = 0; ch < 8; ch++) den += g_denp[(bs0 + e) * 8 + ch];
        sinv[e] = frcp(fmaxf(den, EPSv));
    }
    __syncthreads();
    for (int i = e; i < 4 * 256; i += 512) {
        int slot = i >> 8, dim = i & 255;
        float a = 0.f;
        #pragma unroll
        for (int ch = 0; ch < 8; ch++)
            a += g_evp[(size_t)((bs0 + slot) * 8 + ch) * NC + 2 * d0 + dim];
        sv[slot][dim] = a * sinv[slot];
    }
    __syncthreads();

    float KR[4] = {0,0,0,0}, KI[4] = {0,0,0,0};
    float VR[4] = {0,0,0,0}, VI[4] = {0,0,0,0};
    #pragma unroll 4
    for (int dd = 0; dd < 128; dd++) {
        int d = d0 + dd;
        float wkr = Wekr[(size_t)d * DIMC + e], wki = Weki[(size_t)d * DIMC + e];
        float wvr = Wevr[(size_t)d * DIMC + e], wvi = Wevi[(size_t)d * DIMC + e];
        #pragma unroll
        for (int s2 = 0; s2 < 4; s2++) {
            float zr = sv[s2][2 * dd], zi = sv[s2][2 * dd + 1];
            KR[s2] += zr * wkr - zi * wki;
            KI[s2] += zr * wki + zi * wkr;
            VR[s2] += zr * wvr - zi * wvi;
            VI[s2] += zr * wvi + zi * wvr;
        }
    }
    #pragma unroll
    for (int s2 = 0; s2 < 4; s2++) {
        float* p = g_kvp + (size_t)((bs0 + s2) * 4 + dc) * (4 * DIMC);
        p[e]            = KR[s2];
        p[DIMC + e]     = KI[s2];
        p[2 * DIMC + e] = VR[s2];
        p[3 * DIMC + e] = VI[s2];
    }
}

/* combine + blend + kmag + mask: grid (Bb*SS), 512 thr (thread = e) */
__global__ void __launch_bounds__(512, 2)
k_ekv2(const float* __restrict__ sk, const float* __restrict__ svv,
       const float* __restrict__ smk, float* __restrict__ out) {
    __shared__ float wpart[16];
    int bs = blockIdx.x, e = threadIdx.x;
    float kr = 0.f, ki = 0.f, vr = 0.f, vi = 0.f;
    #pragma unroll
    for (int dc = 0; dc < 4; dc++) {
        const float* p = g_kvp + (size_t)(bs * 4 + dc) * (4 * DIMC);
        kr += p[e]; ki += p[DIMC + e]; vr += p[2*DIMC + e]; vi += p[3*DIMC + e];
    }
    float m = g_emask[bs];
    size_t off = (size_t)bs * NC + 2 * e;
    float nkr = m * kr + (1.f - m) * sk[off];
    float nki = m * ki + (1.f - m) * sk[off + 1];
    float nvr = m * vr + (1.f - m) * svv[off];
    float nvi = m * vi + (1.f - m) * svv[off + 1];
    out[OFF_NK + off] = nkr; out[OFF_NK + off + 1] = nki;
    out[OFF_NV + off] = nvr; out[OFF_NV + off + 1] = nvi;
    if (e == 0) out[OFF_NM + bs] = fminf(smk[bs] + m, 1.f);
    float p = wred(nkr * nkr + nki * nki);
    int lane = e & 31, wid = e >> 5;
    if (lane == 0) wpart[wid] = p;
    __syncthreads();
    if (e == 0) {
        float sum = 0.f;
        #pragma unroll
        for (int i = 0; i < 16; i++) sum += wpart[i];
        g_kmag[bs] = fsqrt(sum + EPSv);
    }
}

/* ------------------------------------------------------------------ */
/* u partials: grid (Bb, SS/8, 4 j-chunks), 512 thr */
__global__ void __launch_bounds__(512, 2)
k_udot1(const float* __restrict__ out) {
    __shared__ float ka[8][256];    /* kappa dims [2*j0, 2*j0+256) */
    int b = blockIdx.x, sg = blockIdx.y, jc = blockIdx.z;
    int tid = threadIdx.x;
    int j0 = jc * 128;
    const float* ksrc = out + OFF_NK + (size_t)(b * SS + sg * 8) * NC + 2 * j0;
    for (int i = tid; i < 8 * 256; i += 512) {
        int row = i >> 8, col = i & 255;
        ka[row][col] = ksrc[(size_t)row * NC + col];
    }
    __syncthreads();
    int e = tid;
    float ur[8], ui[8];
    #pragma unroll
    for (int s = 0; s < 8; s++) { ur[s] = 0.f; ui[s] = 0.f; }
    #pragma unroll 4
    for (int jj = 0; jj < 128; jj++) {
        int j = j0 + jj;
        float wr = g_WrT[(size_t)j * DIMC + e];
        float wi = g_WiT[(size_t)j * DIMC + e];
        #pragma unroll
        for (int s = 0; s < 8; s++) {
            float2 kp = *(const float2*)&ka[s][2 * jj];
            ur[s] += wr * kp.x + wi * kp.y;
            ui[s] += wr * kp.y - wi * kp.x;
        }
    }
    #pragma unroll
    for (int s = 0; s < 8; s++) {
        int bs = b * SS + sg * 8 + s;
        float* p = g_up + (size_t)(bs * 4 + jc) * NC;
        p[2 * e]     = ur[s];
        p[2 * e + 1] = ui[s];
    }
}

/* combine u partials + hsplit to fp16: grid (Bb*SS), 512 thr */
__global__ void k_udot2() {
    int bs = blockIdx.x, e = threadIdx.x;
    float ur = 0.f, ui = 0.f;
    #pragma unroll
    for (int jc = 0; jc < 4; jc++) {
        const float* p = g_up + (size_t)(bs * 4 + jc) * NC;
        ur += p[2 * e]; ui += p[2 * e + 1];
    }
    __half hr, lr, hi2, li;
    hsplit(ur, hr, lr);
    hsplit(ui, hi2, li);
    ((__half2*)(g_uh + (size_t)bs * NC))[e] = __halves2half2(hr, hi2);
    ((__half2*)(g_ul + (size_t)bs * NC))[e] = __halves2half2(lr, li);
}

/* ------------------------------------------------------------------ */
/* qmag GEMM: single-term fp16, BM=128 BN=256 BK=32, 512 thr, 4-stage. */
#define BM 128
#define BN 256
#define PITCH 80
#define A_SZ (BM * PITCH)
#define B_SZ (BN * PITCH)
#define STAGE_SZ (A_SZ + B_SZ)
#define NSTGQ 4
#define QSMEM (NSTGQ * STAGE_SZ)
#define NIT (NC / 32)

__global__ void __launch_bounds__(512, 1)
k_qgemm_mma() {
    extern __shared__ unsigned char smq[];
    __shared__ float qp_sm[4][BM];
    int t = threadIdx.x, lane = t & 31, wid = t >> 5;
    int m0 = blockIdx.y * BM, n0 = blockIdx.x * BN;
    int warpM = (wid & 3) * 32, warpN = (wid >> 2) * 64;

    uint32_t sb0 = smem_u32(smq);
    const uint4* srcA = (const uint4*)(g_Ahi  + (size_t)(m0 + (t >> 2)) * NC) + (t & 3);
    int bi0 = t, bi1 = t + 512;
    const uint4* srcB0 = (const uint4*)(g_BhiT + (size_t)(n0 + (bi0 >> 2)) * NC) + (bi0 & 3);
    const uint4* srcB1 = (const uint4*)(g_BhiT + (size_t)(n0 + (bi1 >> 2)) * NC) + (bi1 & 3);
    uint32_t dstA  = sb0 + (uint32_t)((t >> 2) * PITCH + (t & 3) * 16);
    uint32_t dstB0 = sb0 + (uint32_t)(A_SZ + (bi0 >> 2) * PITCH + (bi0 & 3) * 16);
    uint32_t dstB1 = sb0 + (uint32_t)(A_SZ + (bi1 >> 2) * PITCH + (bi1 & 3) * 16);

    uint32_t aoff = (uint32_t)((warpM + (lane & 15)) * PITCH + ((lane >> 4) << 4));
    uint32_t boff = (uint32_t)(A_SZ + (warpN + (lane & 7) + ((lane >> 4) & 1) * 8) * PITCH
                               + (((lane >> 3) & 1) << 4));

    float acc[2][8][4];
    #pragma unroll
    for (int i = 0; i < 2; i++)
        #pragma unroll
        for (int j = 0; j < 8; j++)
            #pragma unroll
            for (int k = 0; k < 4; k++) acc[i][j][k] = 0.f;

    #pragma unroll
    for (int s = 0; s < 3; s++) {
        uint32_t off = (uint32_t)(s * STAGE_SZ);
        CP16(dstA + off,  srcA  + s * 4);
        CP16(dstB0 + off, srcB0 + s * 4);
        CP16(dstB1 + off, srcB1 + s * 4);
        CP_COMMIT();
    }

    for (int it = 0; it < NIT; it++) {
        CP_WAIT2();
        __syncthreads();
        uint32_t st = sb0 + (uint32_t)((it % NSTGQ) * STAGE_SZ);
        uint32_t aAh = st + aoff;
        uint32_t aBh = st + boff;

        #pragma unroll
        for (int ko = 0; ko < 2; ko++) {
            uint32_t ah[2][4], bh[4][4];
            #pragma unroll
            for (int mg = 0; mg < 2; mg++)
                ldsm4(ah[mg], aAh + mg * (16 * PITCH) + ko * 32);
            #pragma unroll
            for (int ng = 0; ng < 4; ng++)
                ldsm4(bh[ng], aBh + ng * (16 * PITCH) + ko * 32);
            #pragma unroll
            for (int mg = 0; mg < 2; mg++)
                #pragma unroll
                for (int ng = 0; ng < 4; ng++)
                    #pragma unroll
                    for (int h = 0; h < 2; h++)
                        mma16816(acc[mg][ng * 2 + h], ah[mg],
                                 bh[ng][h*2], bh[ng][h*2+1]);
        }

        if (it + 3 < NIT) {
            uint32_t off = (uint32_t)(((it + 3) % NSTGQ) * STAGE_SZ);
            CP16(dstA + off,  srcA  + (it + 3) * 4);
            CP16(dstB0 + off, srcB0 + (it + 3) * 4);
            CP16(dstB1 + off, srcB1 + (it + 3) * 4);
        }
        CP_COMMIT();
    }

    #pragma unroll
    for (int mg = 0; mg < 2; mg++) {
        float rp0 = 0.f, rp1 = 0.f;
        #pragma unroll
        for (int j = 0; j < 8; j++) {
            float* d = acc[mg][j];
            rp0 += d[0]*d[0] + d[1]*d[1];
            rp1 += d[2]*d[2] + d[3]*d[3];
        }
        rp0 += __shfl_xor_sync(0xffffffffu, rp0, 1);
        rp0 += __shfl_xor_sync(0xffffffffu, rp0, 2);
        rp1 += __shfl_xor_sync(0xffffffffu, rp1, 1);
        rp1 += __shfl_xor_sync(0xffffffffu, rp1, 2);
        if ((lane & 3) == 0) {
            int r = warpM + mg * 16 + (lane >> 2);
            qp_sm[wid >> 2][r]     = rp0;
            qp_sm[wid >> 2][r + 8] = rp1;
        }
    }
    __syncthreads();
    if (t < BM)
        g_qp[(size_t)(m0 + t) * 4 + blockIdx.x] =
            qp_sm[0][t] + qp_sm[1][t] + qp_sm[2][t] + qp_sm[3][t];
}

/* ------------------------------------------------------------------ */
/* dot GEMM: dot[l,s] = z_l . u_s, 3-term fp16 (hh+hl+lh). */
#define DM 128
#define DA_SZ (DM * PITCH)
#define DSTG (2 * DA_SZ)
#define PB 2064
#define B_HL (SS * PB)
#define DB_OFF (3 * DSTG)
#define DSMEM (DB_OFF + 2 * B_HL)
#define NITD (NC / 32)

__global__ void __launch_bounds__(256, 1)
k_dotgemm() {
    extern __shared__ unsigned char smd[];
    int t = threadIdx.x, lane = t & 31, wid = t >> 5;
    int m0 = blockIdx.x * DM;
    int batch = blockIdx.x >> 5;
    int warpM = wid * 16;

    uint32_t sb0 = smem_u32(smd);

    #pragma unroll
    for (int u = 0; u < 16; u++) {
        int idx = t + 256 * u;
        int row = idx >> 7, col = idx & 127;
        uint32_t d0 = sb0 + (uint32_t)(DB_OFF + row * PB + col * 16);
        const uint4* sh = (const uint4*)(g_uh + (size_t)(batch * SS + row) * NC) + col;
        const uint4* sl = (const uint4*)(g_ul + (size_t)(batch * SS + row) * NC) + col;
        CP16(d0, sh);
        CP16(d0 + B_HL, sl);
    }
    int ai0 = t, ai1 = t + 256;
    const uint4* sAh0 = (const uint4*)(g_Ahi + (size_t)(m0 + (ai0 >> 2)) * NC) + (ai0 & 3);
    const uint4* sAh1 = (const uint4*)(g_Ahi + (size_t)(m0 + (ai1 >> 2)) * NC) + (ai1 & 3);
    const uint4* sAl0 = (const uint4*)(g_Alo + (size_t)(m0 + (ai0 >> 2)) * NC) + (ai0 & 3);
    const uint4* sAl1 = (const uint4*)(g_Alo + (size_t)(m0 + (ai1 >> 2)) * NC) + (ai1 & 3);
    uint32_t dA0 = sb0 + (uint32_t)((ai0 >> 2) * PITCH + (ai0 & 3) * 16);
    uint32_t dA1 = sb0 + (uint32_t)((ai1 >> 2) * PITCH + (ai1 & 3) * 16);

    #pragma unroll
    for (int s = 0; s < 2; s++) {
        uint32_t off = (uint32_t)(s * DSTG);
        CP16(dA0 + off, sAh0 + s * 4);          CP16(dA1 + off, sAh1 + s * 4);
        CP16(dA0 + off + DA_SZ, sAl0 + s * 4);  CP16(dA1 + off + DA_SZ, sAl1 + s * 4);
        CP_COMMIT();
    }

    uint32_t aoff = (uint32_t)((warpM + (lane & 15)) * PITCH + ((lane >> 4) << 4));
    uint32_t boffB = (uint32_t)(DB_OFF + ((lane & 7) + ((lane >> 4) & 1) * 8) * PB
                                + (((lane >> 3) & 1) << 4));

    float acc[4][4];
    #pragma unroll
    for (int j = 0; j < 4; j++)
        #pragma unroll
        for (int k = 0; k < 4; k++) acc[j][k] = 0.f;

    for (int it = 0; it < NITD; it++) {
        CP_WAIT1();
        __syncthreads();
        uint32_t st = sb0 + (uint32_t)((it % 3) * DSTG);
        #pragma unroll
        for (int ko = 0; ko < 2; ko++) {
            uint32_t ah[4], al[4], bh[2][4], bl[2][4];
            ldsm4(ah, st + aoff + ko * 32);
            ldsm4(al, st + DA_SZ + aoff + ko * 32);
            #pragma unroll
            for (int ng = 0; ng < 2; ng++) {
                uint32_t ba = sb0 + boffB + ng * (16 * PB) + it * 64 + ko * 32;
                ldsm4(bh[ng], ba);
                ldsm4(bl[ng], ba + B_HL);
            }
            #pragma unroll
            for (int ng = 0; ng < 2; ng++)
                #pragma unroll
                for (int h = 0; h < 2; h++) {
                    float* d = acc[ng * 2 + h];
                    mma16816(d, al, bh[ng][h*2], bh[ng][h*2+1]);
                    mma16816(d, ah, bl[ng][h*2], bl[ng][h*2+1]);
                    mma16816(d, ah, bh[ng][h*2], bh[ng][h*2+1]);
                }
        }
        if (it + 2 < NITD) {
            uint32_t off = (uint32_t)(((it + 2) % 3) * DSTG);
            CP16(dA0 + off, sAh0 + (it + 2) * 4);          CP16(dA1 + off, sAh1 + (it + 2) * 4);
            CP16(dA0 + off + DA_SZ, sAl0 + (it + 2) * 4);  CP16(dA1 + off + DA_SZ, sAl1 + (it + 2) * 4);
        }
        CP_COMMIT();
    }

    #pragma unroll
    for (int j = 0; j < 4; j++) {
        float* d = acc[j];
        int r = m0 + warpM + (lane >> 2);
        int c = j * 8 + (lane & 3) * 2;
        *(float2*)&g_dot[(size_t)r * SS + c]       = make_float2(d[0], d[1]);
        *(float2*)&g_dot[(size_t)(r + 8) * SS + c] = make_float2(d[2], d[3]);
    }
}

/* ------------------------------------------------------------------ */
/* attention: warp/token, 32 tokens/block (1024 thr); V staged in smem. */
__global__ void __launch_bounds__(1024, 1)
k_attn(float* __restrict__ out, const float* __restrict__ gain) {
    extern __shared__ float4 sV[];
    __shared__ float sKmag[SS];
    __shared__ float sMask[SS];
    int tid = threadIdx.x, warp = tid >> 5, lane = tid & 31;
    int tok0 = blockIdx.x * 32;
    int b = tok0 / LL;

    const float4* Vsrc = (const float4*)(out + OFF_NV + (size_t)b * SS * NC);
    for (int i = tid; i < SS * NC / 4; i += 1024) sV[i] = Vsrc[i];
    if (tid < SS) {
        sKmag[tid] = g_kmag[b * SS + tid];
        sMask[tid] = out[OFF_NM + b * SS + tid];
    }
    __syncthreads();

    int token = tok0 + warp;
    float qp = (lane < 4) ? g_qp[(size_t)token * 4 + lane] : 0.f;
    qp = wred(qp);
    float qmag = fsqrt(qp + EPSv);

    float dval = g_dot[(size_t)token * SS + lane];
    float myscore = dval * frcp(qmag * sKmag[lane] + EPSv);
    if (sMask[lane] == 0.f) myscore = -1e9f;

    float vcur = myscore;
    float topv[KK]; int topi[KK];
    #pragma unroll
    for (int j = 0; j < KK; j++) {
        float v = vcur; int idx = lane;
        #pragma unroll
        for (int o = 16; o; o >>= 1) {
            float v2 = __shfl_xor_sync(0xffffffffu, v, o);
            int   i2 = __shfl_xor_sync(0xffffffffu, idx, o);
            if (v2 > v || (v2 == v && i2 < idx)) { v = v2; idx = i2; }
        }
        topv[j] = v; topi[j] = idx;
        if (lane == idx) vcur = -INFINITY;
    }
    float w[KK], wsum = 0.f, mx = topv[0];
    #pragma unroll
    for (int j = 0; j < KK; j++) { w[j] = __expf(topv[j] - mx); wsum += w[j]; }
    float winv = frcp(wsum);

    float4 r[8];
    #pragma unroll
    for (int i = 0; i < 8; i++) r[i] = make_float4(0.f, 0.f, 0.f, 0.f);
    #pragma unroll
    for (int j = 0; j < KK; j++) {
        float a = w[j] * winv;
        const float4* Vr = sV + topi[j] * 256;
        #pragma unroll
        for (int i = 0; i < 8; i++) {
            float4 vv = Vr[lane + 32 * i];
            r[i].x += a * vv.x; r[i].y += a * vv.y;
            r[i].z += a * vv.z; r[i].w += a * vv.w;
        }
    }
    float ssum = 0.f;
    #pragma unroll
    for (int i = 0; i < 8; i++)
        ssum += r[i].x*r[i].x + r[i].y*r[i].y + r[i].z*r[i].z + r[i].w*r[i].w;
    ssum = wred(ssum);
    float rinv = frsqrt(ssum * (1.f / DIMC) + EPSv);

    const float2* g2 = (const float2*)gain;
    float4* orow = (float4*)(out + (size_t)token * NC);
    #pragma unroll
    for (int i = 0; i < 8; i++) {
        float2 g = g2[lane + 32 * i];
        float4 o;
        o.x = r[i].x * rinv * g.x; o.y = r[i].y * rinv * g.x;
        o.z = r[i].z * rinv * g.y; o.w = r[i].w * rinv * g.y;
        orow[lane + 32 * i] = o;
    }
}

/* ------------------------------------------------------------------ */
extern "C" void kernel_launch(void* const* d_in, const int* in_sizes, int n_in,
                              void* d_out, int out_size) {
    const float* z    = (const float*)d_in[0];
    const float* sk   = (const float*)d_in[1];
    const float* sv   = (const float*)d_in[2];
    const float* sm   = (const float*)d_in[3];
    const float* Wsr  = (const float*)d_in[4];
    const float* Wsi  = (const float*)d_in[5];
    const float* sb   = (const float*)d_in[6];
    const float* ns   = (const float*)d_in[7];
    const float* Wekr = (const float*)d_in[8];
    const float* Weki = (const float*)d_in[9];
    const float* Wevr = (const float*)d_in[10];
    const float* Wevi = (const float*)d_in[11];
    const float* Wrqr = (const float*)d_in[12];
    const float* Wrqi = (const float*)d_in[13];
    const float* gain = (const float*)d_in[14];
    float* out = (float*)d_out;

    static bool init_done = false;
    static cudaStream_t s1;
    static cudaEvent_t evRoot, evStats, evQ;
    if (!init_done) {
        cudaFuncSetAttribute(k_attn, cudaFuncAttributeMaxDynamicSharedMemorySize, 131072);
        cudaFuncSetAttribute(k_qgemm_mma, cudaFuncAttributeMaxDynamicSharedMemorySize, QSMEM);
        cudaFuncSetAttribute(k_dotgemm, cudaFuncAttributeMaxDynamicSharedMemorySize, DSMEM);
        cudaStreamCreateWithFlags(&s1, cudaStreamNonBlocking);
        cudaEventCreateWithFlags(&evRoot, cudaEventDisableTiming);
        cudaEventCreateWithFlags(&evStats, cudaEventDisableTiming);
        cudaEventCreateWithFlags(&evQ, cudaEventDisableTiming);
        init_done = true;
    }

    cudaEventRecord(evRoot, 0);
    cudaStreamWaitEvent(s1, evRoot, 0);

    k_stats<<<4096, 256>>>(z, Wsr, Wsi);                /* idx 0 (s0) */
    cudaEventRecord(evStats, 0);
    k_runs<<<Bb, 256>>>(out, sb, ns);                   /* idx 1 (s0) */
    k_evec1<<<Bb * SS * 8, 256>>>(z, out);              /* idx 2 (s0) */
    k_ekv1<<<dim3(Bb, SS / 4, 4), 512>>>(Wekr, Weki, Wevr, Wevi); /* idx 3: profiled */
    k_build_bt<<<dim3(16, 16), 256, 0, s1>>>(Wrqr, Wrqi);  /* idx 4 (s1) */
    cudaStreamWaitEvent(s1, evStats, 0);
    k_qgemm_mma<<<dim3(NC / BN, NT / BM), 512, QSMEM, s1>>>();  /* idx 5 (s1) */
    cudaEventRecord(evQ, s1);
    k_ekv2<<<Bb * SS, 512>>>(sk, sv, sm, out);          /* idx 6 (s0) */
    k_udot1<<<dim3(Bb, SS / 8, 4), 512>>>(out);         /* idx 7 (s0) */
    k_udot2<<<Bb * SS, 512>>>();                        /* idx 8 (s0) */
    k_dotgemm<<<NT / DM, 256, DSMEM>>>();               /* idx 9 (s0) */
    cudaStreamWaitEvent(0, evQ, 0);                     /* attn reads g_qp */
    k_attn<<<NT / 32, 1024, 131072>>>(out, gain);       /* idx 10 (s0) */
}

// round 15
// speedup vs baseline: 1.7582x; 1.0165x over previous
#include <cuda_runtime.h>
#include <cuda_fp16.h>
#include <math.h>
#include <stdint.h>

#define Bb   8
#define LL   4096
#define DIMC 512
#define SS   32
#define KK   8
#define NT   (Bb*LL)      /* 32768 tokens */
#define NC   (DIMC*2)     /* 1024 floats per token (interleaved r,i) */
#define THRv 0.5f
#define EPSv 1e-8f

/* output layout: concat(out, new_keys, new_values, new_mask, salience) */
#define OFF_OUT ((size_t)0)
#define OFF_NK  ((size_t)NT*NC)
#define OFF_NV  (OFF_NK + (size_t)Bb*SS*NC)
#define OFF_NM  (OFF_NV + (size_t)Bb*SS*NC)
#define OFF_SAL (OFF_NM + (size_t)Bb*SS)

/* scratch (device globals; no allocation allowed) */
__device__ float g_avg[NT];
__device__ float g_phase[NT];
__device__ float g_evp[(size_t)Bb*SS*8*NC];     /* evec chunk partials, 8MB */
__device__ float g_denp[Bb*SS*8];
__device__ float g_emask[Bb*SS];
__device__ int   g_rs[Bb*SS];
__device__ int   g_re[Bb*SS];
__device__ float g_kmag[Bb*SS];
__device__ float g_kvp[(size_t)Bb*SS*8*4*DIMC]; /* [bs][chunk8][KR,KI,VR,VI][e], 16MB */
__device__ float g_up[(size_t)Bb*SS*8*NC];      /* [bs][chunk8][ur,ui], 8MB */
__device__ __half g_BhiT[NC*NC];          /* B^T fp16, [n][k], 2MB */
__device__ __half g_Ahi[(size_t)NT*NC];   /* z hi fp16, 64MB */
__device__ __half g_Alo[(size_t)NT*NC];   /* z lo fp16, 64MB */
__device__ float g_WrT[DIMC*DIMC];        /* W_rq_r transposed, 1MB */
__device__ float g_WiT[DIMC*DIMC];        /* W_rq_i transposed, 1MB */
__device__ __half g_uh[Bb*SS*NC];         /* u hi fp16 */
__device__ __half g_ul[Bb*SS*NC];         /* u lo fp16 */
__device__ float g_qp[(size_t)NT*4];      /* qmag^2 partials per N-block */
__device__ float g_dot[(size_t)NT*SS];    /* dot[l,s], 4MB */

__device__ __forceinline__ float wred(float v) {
    #pragma unroll
    for (int o = 16; o; o >>= 1) v += __shfl_xor_sync(0xffffffffu, v, o);
    return v;
}

__device__ __forceinline__ float fsqrt(float x) {
    float y; asm("sqrt.approx.f32 %0, %1;" : "=f"(y) : "f"(x)); return y;
}
__device__ __forceinline__ float frcp(float x) {
    float y; asm("rcp.approx.f32 %0, %1;" : "=f"(y) : "f"(x)); return y;
}
__device__ __forceinline__ float frsqrt(float x) {
    float y; asm("rsqrt.approx.f32 %0, %1;" : "=f"(y) : "f"(x)); return y;
}

__device__ __forceinline__ void hsplit(float x, __half& h, __half& l) {
    h = __float2half_rn(x);
    l = __float2half_rn(x - __half2float(h));
}

__device__ __forceinline__ uint32_t smem_u32(const void* p) {
    uint32_t a;
    asm("{ .reg .u64 t; cvta.to.shared.u64 t, %1; cvt.u32.u64 %0, t; }"
        : "=r"(a) : "l"(p));
    return a;
}

__device__ __forceinline__ void ldsm4(uint32_t* r, uint32_t addr) {
    asm volatile("ldmatrix.sync.aligned.m8n8.x4.shared.b16 {%0,%1,%2,%3}, [%4];"
        : "=r"(r[0]), "=r"(r[1]), "=r"(r[2]), "=r"(r[3]) : "r"(addr));
}

__device__ __forceinline__ void mma16816(float* d, const uint32_t* a,
                                         uint32_t b0, uint32_t b1) {
    asm volatile(
        "mma.sync.aligned.m16n8k16.row.col.f32.f16.f16.f32 "
        "{%0,%1,%2,%3}, {%4,%5,%6,%7}, {%8,%9}, {%0,%1,%2,%3};"
        : "+f"(d[0]), "+f"(d[1]), "+f"(d[2]), "+f"(d[3])
        : "r"(a[0]), "r"(a[1]), "r"(a[2]), "r"(a[3]), "r"(b0), "r"(b1));
}

#define CP16(dst, src) \
    asm volatile("cp.async.cg.shared.global [%0], [%1], 16;" \
                 :: "r"(dst), "l"(src) : "memory")
#define CP_COMMIT() asm volatile("cp.async.commit_group;" ::: "memory")
#define CP_WAIT1()  asm volatile("cp.async.wait_group 1;" ::: "memory")
#define CP_WAIT2()  asm volatile("cp.async.wait_group 2;" ::: "memory")

/* ------------------------------------------------------------------ */
/* per-token stats (avg mag + phase) — s0 critical path */
__global__ void k_statsA(const float* __restrict__ z,
                         const float* __restrict__ Wsr,
                         const float* __restrict__ Wsi) {
    int gw = (blockIdx.x * blockDim.x + threadIdx.x) >> 5;
    int lane = threadIdx.x & 31;
    if (gw >= NT) return;
    const float4* z4 = (const float4*)(z + (size_t)gw * NC);
    float ms = 0.f, pr = 0.f, pi = 0.f;
    #pragma unroll
    for (int i = 0; i < 8; i++) {
        int p = lane + 32 * i;
        float4 v = z4[p];
        int d = 2 * p;
        ms += fsqrt(v.x*v.x + v.y*v.y + EPSv) + fsqrt(v.z*v.z + v.w*v.w + EPSv);
        float wr0 = Wsr[d], wi0 = Wsi[d], wr1 = Wsr[d+1], wi1 = Wsi[d+1];
        pr += v.x*wr0 - v.y*wi0 + v.z*wr1 - v.w*wi1;
        pi += v.x*wi0 + v.y*wr0 + v.z*wi1 + v.w*wr1;
    }
    ms = wred(ms); pr = wred(pr); pi = wred(pi);
    if (lane == 0) {
        g_avg[gw]   = ms * (1.f / DIMC);
        g_phase[gw] = fsqrt(pr*pr + pi*pi + EPSv);
    }
}

/* z -> fp16 hi/lo (stream s2; depends only on input z) */
__global__ void k_split(const float* __restrict__ z) {
    size_t i = ((size_t)blockIdx.x * 256 + threadIdx.x) * 8;
    float4 v0 = *(const float4*)(z + i);
    float4 v1 = *(const float4*)(z + i + 4);
    __half h[8], l[8];
    hsplit(v0.x, h[0], l[0]); hsplit(v0.y, h[1], l[1]);
    hsplit(v0.z, h[2], l[2]); hsplit(v0.w, h[3], l[3]);
    hsplit(v1.x, h[4], l[4]); hsplit(v1.y, h[5], l[5]);
    hsplit(v1.z, h[6], l[6]); hsplit(v1.w, h[7], l[7]);
    *(uint4*)(g_Ahi + i) = *(uint4*)h;
    *(uint4*)(g_Alo + i) = *(uint4*)l;
}

/* ------------------------------------------------------------------ */
__global__ void k_build_bt(const float* __restrict__ Wr,
                           const float* __restrict__ Wi) {
    __shared__ float tr[32][33], ti[32][33];
    int tx = threadIdx.x & 31, ty = threadIdx.x >> 5;
    int d0 = blockIdx.x * 32, e0 = blockIdx.y * 32;
    #pragma unroll
    for (int j = 0; j < 4; j++) {
        int d = d0 + ty + 8 * j;
        tr[ty + 8 * j][tx] = Wr[(size_t)d * DIMC + e0 + tx];
        ti[ty + 8 * j][tx] = Wi[(size_t)d * DIMC + e0 + tx];
    }
    __syncthreads();
    #pragma unroll
    for (int j = 0; j < 4; j++) {
        int e = e0 + ty + 8 * j;
        int d = d0 + tx;
        float wr = tr[tx][ty + 8 * j], wi = ti[tx][ty + 8 * j];
        size_t r0 = (size_t)(2 * e) * NC, r1 = (size_t)(2 * e + 1) * NC;
        g_BhiT[r0 + 2*d]     = __float2half_rn(wr);
        g_BhiT[r0 + 2*d + 1] = __float2half_rn(-wi);
        g_BhiT[r1 + 2*d]     = __float2half_rn(wi);
        g_BhiT[r1 + 2*d + 1] = __float2half_rn(wr);
        g_WrT[(size_t)e * DIMC + d] = wr;
        g_WiT[(size_t)e * DIMC + d] = wi;
    }
}

/* ------------------------------------------------------------------ */
/* fused salience + run detection; parallel prefix scan */
__global__ void k_runs(float* __restrict__ out,
                       const float* __restrict__ sb,
                       const float* __restrict__ ns) {
    __shared__ float sal[LL];
    __shared__ int scnt[256];
    int b = blockIdx.x, tid = threadIdx.x;
    float nsv = ns[0], sbv = sb[0];

    int l0 = tid * 16;
    for (int j = 0; j < 16; j++) {
        int l = l0 + j;
        int i = b * LL + l;
        float lm = 0.f;
        #pragma unroll
        for (int o = -2; o <= 2; o++) {
            int ll = l + o;
            if (ll >= 0 && ll < LL) lm += g_avg[i + o];
        }
        lm *= 0.2f;
        float x = g_phase[i] + (g_avg[i] - lm) * nsv + sbv;
        float s = frcp(1.f + __expf(-x));
        sal[l] = s;
        out[OFF_SAL + i] = s;
    }
    if (tid < SS) { g_rs[b*SS+tid] = 0; g_re[b*SS+tid] = 0; g_emask[b*SS+tid] = 0.f; }
    __syncthreads();

    bool prev0 = (l0 > 0) && (sal[l0 - 1] > THRv);
    bool pa = prev0;
    int cnt = 0;
    for (int j = 0; j < 16; j++) {
        bool ab = sal[l0 + j] > THRv;
        cnt += (ab && !pa);
        pa = ab;
    }
    scnt[tid] = cnt;
    __syncthreads();
    #pragma unroll
    for (int off = 1; off < 256; off <<= 1) {
        int add = (tid >= off) ? scnt[tid - off] : 0;
        __syncthreads();
        scnt[tid] += add;
        __syncthreads();
    }
    int e = scnt[tid] - cnt;
    pa = prev0;
    for (int j = 0; j < 16; j++) {
        int l = l0 + j;
        bool ab = sal[l] > THRv;
        if (ab && !pa) {
            if (e < SS) { g_rs[b*SS + e] = l; g_emask[b*SS + e] = 1.f; }
            e++;
        }
        if (ab && (e - 1) < SS) {
            bool nx = (l + 1 < LL) && (sal[l + 1] > THRv);
            if (!nx) g_re[b*SS + (e - 1)] = l + 1;
        }
        pa = ab;
    }
}

/* event vector partials: 8 chunk-blocks per run */
__global__ void k_evec1(const float* __restrict__ z,
                        const float* __restrict__ out) {
    int bs = blockIdx.x >> 3, ch = blockIdx.x & 7;
    int b = bs / SS;
    int rs = g_rs[bs], re = g_re[bs];
    int len = re - rs;
    int clen = (len + 7) >> 3;
    int ls = rs + ch * clen;
    int le = min(ls + clen, re);
    const float* sal = out + OFF_SAL + (size_t)b * LL;
    int t = threadIdx.x;
    float a0 = 0.f, a1 = 0.f, a2 = 0.f, a3 = 0.f, den = 0.f;
    for (int l = ls; l < le; l++) {
        float w = sal[l];
        den += w;
        const float* zt = z + ((size_t)b * LL + l) * NC;
        a0 += w * zt[t];       a1 += w * zt[t + 256];
        a2 += w * zt[t + 512]; a3 += w * zt[t + 768];
    }
    float* ev = g_evp + (size_t)(bs * 8 + ch) * NC;
    ev[t] = a0; ev[t + 256] = a1; ev[t + 512] = a2; ev[t + 768] = a3;
    if (t == 0) g_denp[bs * 8 + ch] = den;
}

/* ------------------------------------------------------------------ */
/* event K/V projection partials: grid (Bb, SS/4, 8 d-chunks), 512 thr. */
__global__ void __launch_bounds__(512, 2)
k_ekv1(const float* __restrict__ Wekr, const float* __restrict__ Weki,
       const float* __restrict__ Wevr, const float* __restrict__ Wevi) {
    int b = blockIdx.x, sg = blockIdx.y, dc = blockIdx.z;
    int e = threadIdx.x;
    int bs0 = b * SS + sg * 4;
    int d0 = dc * 64;
    __shared__ float sv[4][128];    /* evec dims [2*d0, 2*d0+128) */
    __shared__ float sinv[4];
    if (e < 4) {
        float den = 0.f;
        #pragma unroll
        for (int ch = 0; ch < 8; ch++) den += g_denp[(bs0 + e) * 8 + ch];
        sinv[e] = frcp(fmaxf(den, EPSv));
    }
    __syncthreads();
    if (e < 4 * 128) {
        int slot = e >> 7, dim = e & 127;
        float a = 0.f;
        #pragma unroll
        for (int ch = 0; ch < 8; ch++)
            a += g_evp[(size_t)((bs0 + slot) * 8 + ch) * NC + 2 * d0 + dim];
        sv[slot][dim] = a * sinv[slot];
    }
    __syncthreads();

    float KR[4] = {0,0,0,0}, KI[4] = {0,0,0,0};
    float VR[4] = {0,0,0,0}, VI[4] = {0,0,0,0};
    #pragma unroll 4
    for (int dd = 0; dd < 64; dd++) {
        int d = d0 + dd;
        float wkr = Wekr[(size_t)d * DIMC + e], wki = Weki[(size_t)d * DIMC + e];
        float wvr = Wevr[(size_t)d * DIMC + e], wvi = Wevi[(size_t)d * DIMC + e];
        #pragma unroll
        for (int s2 = 0; s2 < 4; s2++) {
            float zr = sv[s2][2 * dd], zi = sv[s2][2 * dd + 1];
            KR[s2] += zr * wkr - zi * wki;
            KI[s2] += zr * wki + zi * wkr;
            VR[s2] += zr * wvr - zi * wvi;
            VI[s2] += zr * wvi + zi * wvr;
        }
    }
    #pragma unroll
    for (int s2 = 0; s2 < 4; s2++) {
        float* p = g_kvp + (size_t)((bs0 + s2) * 8 + dc) * (4 * DIMC);
        p[e]            = KR[s2];
        p[DIMC + e]     = KI[s2];
        p[2 * DIMC + e] = VR[s2];
        p[3 * DIMC + e] = VI[s2];
    }
}

/* combine + blend + kmag + mask: grid (Bb*SS), 512 thr (thread = e) */
__global__ void __launch_bounds__(512, 2)
k_ekv2(const float* __restrict__ sk, const float* __restrict__ svv,
       const float* __restrict__ smk, float* __restrict__ out) {
    __shared__ float wpart[16];
    int bs = blockIdx.x, e = threadIdx.x;
    float kr = 0.f, ki = 0.f, vr = 0.f, vi = 0.f;
    #pragma unroll
    for (int dc = 0; dc < 8; dc++) {
        const float* p = g_kvp + (size_t)(bs * 8 + dc) * (4 * DIMC);
        kr += p[e]; ki += p[DIMC + e]; vr += p[2*DIMC + e]; vi += p[3*DIMC + e];
    }
    float m = g_emask[bs];
    size_t off = (size_t)bs * NC + 2 * e;
    float nkr = m * kr + (1.f - m) * sk[off];
    float nki = m * ki + (1.f - m) * sk[off + 1];
    float nvr = m * vr + (1.f - m) * svv[off];
    float nvi = m * vi + (1.f - m) * svv[off + 1];
    out[OFF_NK + off] = nkr; out[OFF_NK + off + 1] = nki;
    out[OFF_NV + off] = nvr; out[OFF_NV + off + 1] = nvi;
    if (e == 0) out[OFF_NM + bs] = fminf(smk[bs] + m, 1.f);
    float p = wred(nkr * nkr + nki * nki);
    int lane = e & 31, wid = e >> 5;
    if (lane == 0) wpart[wid] = p;
    __syncthreads();
    if (e == 0) {
        float sum = 0.f;
        #pragma unroll
        for (int i = 0; i < 16; i++) sum += wpart[i];
        g_kmag[bs] = fsqrt(sum + EPSv);
    }
}

/* ------------------------------------------------------------------ */
/* u partials: grid (Bb, SS/8, 8 j-chunks), 512 thr */
__global__ void __launch_bounds__(512, 2)
k_udot1(const float* __restrict__ out) {
    __shared__ float ka[8][128];    /* kappa dims [2*j0, 2*j0+128) */
    int b = blockIdx.x, sg = blockIdx.y, jc = blockIdx.z;
    int tid = threadIdx.x;
    int j0 = jc * 64;
    const float* ksrc = out + OFF_NK + (size_t)(b * SS + sg * 8) * NC + 2 * j0;
    for (int i = tid; i < 8 * 128; i += 512) {
        int row = i >> 7, col = i & 127;
        ka[row][col] = ksrc[(size_t)row * NC + col];
    }
    __syncthreads();
    int e = tid;
    float ur[8], ui[8];
    #pragma unroll
    for (int s = 0; s < 8; s++) { ur[s] = 0.f; ui[s] = 0.f; }
    #pragma unroll 4
    for (int jj = 0; jj < 64; jj++) {
        int j = j0 + jj;
        float wr = g_WrT[(size_t)j * DIMC + e];
        float wi = g_WiT[(size_t)j * DIMC + e];
        #pragma unroll
        for (int s = 0; s < 8; s++) {
            float2 kp = *(const float2*)&ka[s][2 * jj];
            ur[s] += wr * kp.x + wi * kp.y;
            ui[s] += wr * kp.y - wi * kp.x;
        }
    }
    #pragma unroll
    for (int s = 0; s < 8; s++) {
        int bs = b * SS + sg * 8 + s;
        float* p = g_up + (size_t)(bs * 8 + jc) * NC;
        p[2 * e]     = ur[s];
        p[2 * e + 1] = ui[s];
    }
}

/* combine u partials + hsplit to fp16: grid (Bb*SS), 512 thr */
__global__ void k_udot2() {
    int bs = blockIdx.x, e = threadIdx.x;
    float ur = 0.f, ui = 0.f;
    #pragma unroll
    for (int jc = 0; jc < 8; jc++) {
        const float* p = g_up + (size_t)(bs * 8 + jc) * NC;
        ur += p[2 * e]; ui += p[2 * e + 1];
    }
    __half hr, lr, hi2, li;
    hsplit(ur, hr, lr);
    hsplit(ui, hi2, li);
    ((__half2*)(g_uh + (size_t)bs * NC))[e] = __halves2half2(hr, hi2);
    ((__half2*)(g_ul + (size_t)bs * NC))[e] = __halves2half2(lr, li);
}

/* ------------------------------------------------------------------ */
/* qmag GEMM: single-term fp16, BM=128 BN=256 BK=32, 512 thr, 4-stage. */
#define BM 128
#define BN 256
#define PITCH 80
#define A_SZ (BM * PITCH)
#define B_SZ (BN * PITCH)
#define STAGE_SZ (A_SZ + B_SZ)
#define NSTGQ 4
#define QSMEM (NSTGQ * STAGE_SZ)
#define NIT (NC / 32)

__global__ void __launch_bounds__(512, 1)
k_qgemm_mma() {
    extern __shared__ unsigned char smq[];
    __shared__ float qp_sm[4][BM];
    int t = threadIdx.x, lane = t & 31, wid = t >> 5;
    int m0 = blockIdx.y * BM, n0 = blockIdx.x * BN;
    int warpM = (wid & 3) * 32, warpN = (wid >> 2) * 64;

    uint32_t sb0 = smem_u32(smq);
    const uint4* srcA = (const uint4*)(g_Ahi  + (size_t)(m0 + (t >> 2)) * NC) + (t & 3);
    int bi0 = t, bi1 = t + 512;
    const uint4* srcB0 = (const uint4*)(g_BhiT + (size_t)(n0 + (bi0 >> 2)) * NC) + (bi0 & 3);
    const uint4* srcB1 = (const uint4*)(g_BhiT + (size_t)(n0 + (bi1 >> 2)) * NC) + (bi1 & 3);
    uint32_t dstA  = sb0 + (uint32_t)((t >> 2) * PITCH + (t & 3) * 16);
    uint32_t dstB0 = sb0 + (uint32_t)(A_SZ + (bi0 >> 2) * PITCH + (bi0 & 3) * 16);
    uint32_t dstB1 = sb0 + (uint32_t)(A_SZ + (bi1 >> 2) * PITCH + (bi1 & 3) * 16);

    uint32_t aoff = (uint32_t)((warpM + (lane & 15)) * PITCH + ((lane >> 4) << 4));
    uint32_t boff = (uint32_t)(A_SZ + (warpN + (lane & 7) + ((lane >> 4) & 1) * 8) * PITCH
                               + (((lane >> 3) & 1) << 4));

    float acc[2][8][4];
    #pragma unroll
    for (int i = 0; i < 2; i++)
        #pragma unroll
        for (int j = 0; j < 8; j++)
            #pragma unroll
            for (int k = 0; k < 4; k++) acc[i][j][k] = 0.f;

    #pragma unroll
    for (int s = 0; s < 3; s++) {
        uint32_t off = (uint32_t)(s * STAGE_SZ);
        CP16(dstA + off,  srcA  + s * 4);
        CP16(dstB0 + off, srcB0 + s * 4);
        CP16(dstB1 + off, srcB1 + s * 4);
        CP_COMMIT();
    }

    for (int it = 0; it < NIT; it++) {
        CP_WAIT2();
        __syncthreads();
        uint32_t st = sb0 + (uint32_t)((it % NSTGQ) * STAGE_SZ);
        uint32_t aAh = st + aoff;
        uint32_t aBh = st + boff;

        #pragma unroll
        for (int ko = 0; ko < 2; ko++) {
            uint32_t ah[2][4], bh[4][4];
            #pragma unroll
            for (int mg = 0; mg < 2; mg++)
                ldsm4(ah[mg], aAh + mg * (16 * PITCH) + ko * 32);
            #pragma unroll
            for (int ng = 0; ng < 4; ng++)
                ldsm4(bh[ng], aBh + ng * (16 * PITCH) + ko * 32);
            #pragma unroll
            for (int mg = 0; mg < 2; mg++)
                #pragma unroll
                for (int ng = 0; ng < 4; ng++)
                    #pragma unroll
                    for (int h = 0; h < 2; h++)
                        mma16816(acc[mg][ng * 2 + h], ah[mg],
                                 bh[ng][h*2], bh[ng][h*2+1]);
        }

        if (it + 3 < NIT) {
            uint32_t off = (uint32_t)(((it + 3) % NSTGQ) * STAGE_SZ);
            CP16(dstA + off,  srcA  + (it + 3) * 4);
            CP16(dstB0 + off, srcB0 + (it + 3) * 4);
            CP16(dstB1 + off, srcB1 + (it + 3) * 4);
        }
        CP_COMMIT();
    }

    #pragma unroll
    for (int mg = 0; mg < 2; mg++) {
        float rp0 = 0.f, rp1 = 0.f;
        #pragma unroll
        for (int j = 0; j < 8; j++) {
            float* d = acc[mg][j];
            rp0 += d[0]*d[0] + d[1]*d[1];
            rp1 += d[2]*d[2] + d[3]*d[3];
        }
        rp0 += __shfl_xor_sync(0xffffffffu, rp0, 1);
        rp0 += __shfl_xor_sync(0xffffffffu, rp0, 2);
        rp1 += __shfl_xor_sync(0xffffffffu, rp1, 1);
        rp1 += __shfl_xor_sync(0xffffffffu, rp1, 2);
        if ((lane & 3) == 0) {
            int r = warpM + mg * 16 + (lane >> 2);
            qp_sm[wid >> 2][r]     = rp0;
            qp_sm[wid >> 2][r + 8] = rp1;
        }
    }
    __syncthreads();
    if (t < BM)
        g_qp[(size_t)(m0 + t) * 4 + blockIdx.x] =
            qp_sm[0][t] + qp_sm[1][t] + qp_sm[2][t] + qp_sm[3][t];
}

/* ------------------------------------------------------------------ */
/* dot GEMM: dot[l,s] = z_l . u_s, 3-term fp16 (hh+hl+lh). */
#define DM 128
#define DA_SZ (DM * PITCH)
#define DSTG (2 * DA_SZ)
#define PB 2064
#define B_HL (SS * PB)
#define DB_OFF (3 * DSTG)
#define DSMEM (DB_OFF + 2 * B_HL)
#define NITD (NC / 32)

__global__ void __launch_bounds__(256, 1)
k_dotgemm() {
    extern __shared__ unsigned char smd[];
    int t = threadIdx.x, lane = t & 31, wid = t >> 5;
    int m0 = blockIdx.x * DM;
    int batch = blockIdx.x >> 5;
    int warpM = wid * 16;

    uint32_t sb0 = smem_u32(smd);

    #pragma unroll
    for (int u = 0; u < 16; u++) {
        int idx = t + 256 * u;
        int row = idx >> 7, col = idx & 127;
        uint32_t d0 = sb0 + (uint32_t)(DB_OFF + row * PB + col * 16);
        const uint4* sh = (const uint4*)(g_uh + (size_t)(batch * SS + row) * NC) + col;
        const uint4* sl = (const uint4*)(g_ul + (size_t)(batch * SS + row) * NC) + col;
        CP16(d0, sh);
        CP16(d0 + B_HL, sl);
    }
    int ai0 = t, ai1 = t + 256;
    const uint4* sAh0 = (const uint4*)(g_Ahi + (size_t)(m0 + (ai0 >> 2)) * NC) + (ai0 & 3);
    const uint4* sAh1 = (const uint4*)(g_Ahi + (size_t)(m0 + (ai1 >> 2)) * NC) + (ai1 & 3);
    const uint4* sAl0 = (const uint4*)(g_Alo + (size_t)(m0 + (ai0 >> 2)) * NC) + (ai0 & 3);
    const uint4* sAl1 = (const uint4*)(g_Alo + (size_t)(m0 + (ai1 >> 2)) * NC) + (ai1 & 3);
    uint32_t dA0 = sb0 + (uint32_t)((ai0 >> 2) * PITCH + (ai0 & 3) * 16);
    uint32_t dA1 = sb0 + (uint32_t)((ai1 >> 2) * PITCH + (ai1 & 3) * 16);

    #pragma unroll
    for (int s = 0; s < 2; s++) {
        uint32_t off = (uint32_t)(s * DSTG);
        CP16(dA0 + off, sAh0 + s * 4);          CP16(dA1 + off, sAh1 + s * 4);
        CP16(dA0 + off + DA_SZ, sAl0 + s * 4);  CP16(dA1 + off + DA_SZ, sAl1 + s * 4);
        CP_COMMIT();
    }

    uint32_t aoff = (uint32_t)((warpM + (lane & 15)) * PITCH + ((lane >> 4) << 4));
    uint32_t boffB = (uint32_t)(DB_OFF + ((lane & 7) + ((lane >> 4) & 1) * 8) * PB
                                + (((lane >> 3) & 1) << 4));

    float acc[4][4];
    #pragma unroll
    for (int j = 0; j < 4; j++)
        #pragma unroll
        for (int k = 0; k < 4; k++) acc[j][k] = 0.f;

    for (int it = 0; it < NITD; it++) {
        CP_WAIT1();
        __syncthreads();
        uint32_t st = sb0 + (uint32_t)((it % 3) * DSTG);
        #pragma unroll
        for (int ko = 0; ko < 2; ko++) {
            uint32_t ah[4], al[4], bh[2][4], bl[2][4];
            ldsm4(ah, st + aoff + ko * 32);
            ldsm4(al, st + DA_SZ + aoff + ko * 32);
            #pragma unroll
            for (int ng = 0; ng < 2; ng++) {
                uint32_t ba = sb0 + boffB + ng * (16 * PB) + it * 64 + ko * 32;
                ldsm4(bh[ng], ba);
                ldsm4(bl[ng], ba + B_HL);
            }
            #pragma unroll
            for (int ng = 0; ng < 2; ng++)
                #pragma unroll
                for (int h = 0; h < 2; h++) {
                    float* d = acc[ng * 2 + h];
                    mma16816(d, al, bh[ng][h*2], bh[ng][h*2+1]);
                    mma16816(d, ah, bl[ng][h*2], bl[ng][h*2+1]);
                    mma16816(d, ah, bh[ng][h*2], bh[ng][h*2+1]);
                }
        }
        if (it + 2 < NITD) {
            uint32_t off = (uint32_t)(((it + 2) % 3) * DSTG);
            CP16(dA0 + off, sAh0 + (it + 2) * 4);          CP16(dA1 + off, sAh1 + (it + 2) * 4);
            CP16(dA0 + off + DA_SZ, sAl0 + (it + 2) * 4);  CP16(dA1 + off + DA_SZ, sAl1 + (it + 2) * 4);
        }
        CP_COMMIT();
    }

    #pragma unroll
    for (int j = 0; j < 4; j++) {
        float* d = acc[j];
        int r = m0 + warpM + (lane >> 2);
        int c = j * 8 + (lane & 3) * 2;
        *(float2*)&g_dot[(size_t)r * SS + c]       = make_float2(d[0], d[1]);
        *(float2*)&g_dot[(size_t)(r + 8) * SS + c] = make_float2(d[2], d[3]);
    }
}

/* ------------------------------------------------------------------ */
/* attention: warp/token, 32 tokens/block (1024 thr); V staged in smem. */
__global__ void __launch_bounds__(1024, 1)
k_attn(float* __restrict__ out, const float* __restrict__ gain) {
    extern __shared__ float4 sV[];
    __shared__ float sKmag[SS];
    __shared__ float sMask[SS];
    int tid = threadIdx.x, warp = tid >> 5, lane = tid & 31;
    int tok0 = blockIdx.x * 32;
    int b = tok0 / LL;

    const float4* Vsrc = (const float4*)(out + OFF_NV + (size_t)b * SS * NC);
    for (int i = tid; i < SS * NC / 4; i += 1024) sV[i] = Vsrc[i];
    if (tid < SS) {
        sKmag[tid] = g_kmag[b * SS + tid];
        sMask[tid] = out[OFF_NM + b * SS + tid];
    }
    __syncthreads();

    int token = tok0 + warp;
    float qp = (lane < 4) ? g_qp[(size_t)token * 4 + lane] : 0.f;
    qp = wred(qp);
    float qmag = fsqrt(qp + EPSv);

    float dval = g_dot[(size_t)token * SS + lane];
    float myscore = dval * frcp(qmag * sKmag[lane] + EPSv);
    if (sMask[lane] == 0.f) myscore = -1e9f;

    float vcur = myscore;
    float topv[KK]; int topi[KK];
    #pragma unroll
    for (int j = 0; j < KK; j++) {
        float v = vcur; int idx = lane;
        #pragma unroll
        for (int o = 16; o; o >>= 1) {
            float v2 = __shfl_xor_sync(0xffffffffu, v, o);
            int   i2 = __shfl_xor_sync(0xffffffffu, idx, o);
            if (v2 > v || (v2 == v && i2 < idx)) { v = v2; idx = i2; }
        }
        topv[j] = v; topi[j] = idx;
        if (lane == idx) vcur = -INFINITY;
    }
    float w[KK], wsum = 0.f, mx = topv[0];
    #pragma unroll
    for (int j = 0; j < KK; j++) { w[j] = __expf(topv[j] - mx); wsum += w[j]; }
    float winv = frcp(wsum);

    float4 r[8];
    #pragma unroll
    for (int i = 0; i < 8; i++) r[i] = make_float4(0.f, 0.f, 0.f, 0.f);
    #pragma unroll
    for (int j = 0; j < KK; j++) {
        float a = w[j] * winv;
        const float4* Vr = sV + topi[j] * 256;
        #pragma unroll
        for (int i = 0; i < 8; i++) {
            float4 vv = Vr[lane + 32 * i];
            r[i].x += a * vv.x; r[i].y += a * vv.y;
            r[i].z += a * vv.z; r[i].w += a * vv.w;
        }
    }
    float ssum = 0.f;
    #pragma unroll
    for (int i = 0; i < 8; i++)
        ssum += r[i].x*r[i].x + r[i].y*r[i].y + r[i].z*r[i].z + r[i].w*r[i].w;
    ssum = wred(ssum);
    float rinv = frsqrt(ssum * (1.f / DIMC) + EPSv);

    const float2* g2 = (const float2*)gain;
    float4* orow = (float4*)(out + (size_t)token * NC);
    #pragma unroll
    for (int i = 0; i < 8; i++) {
        float2 g = g2[lane + 32 * i];
        float4 o;
        o.x = r[i].x * rinv * g.x; o.y = r[i].y * rinv * g.x;
        o.z = r[i].z * rinv * g.y; o.w = r[i].w * rinv * g.y;
        orow[lane + 32 * i] = o;
    }
}

/* ------------------------------------------------------------------ */
extern "C" void kernel_launch(void* const* d_in, const int* in_sizes, int n_in,
                              void* d_out, int out_size) {
    const float* z    = (const float*)d_in[0];
    const float* sk   = (const float*)d_in[1];
    const float* sv   = (const float*)d_in[2];
    const float* sm   = (const float*)d_in[3];
    const float* Wsr  = (const float*)d_in[4];
    const float* Wsi  = (const float*)d_in[5];
    const float* sb   = (const float*)d_in[6];
    const float* ns   = (const float*)d_in[7];
    const float* Wekr = (const float*)d_in[8];
    const float* Weki = (const float*)d_in[9];
    const float* Wevr = (const float*)d_in[10];
    const float* Wevi = (const float*)d_in[11];
    const float* Wrqr = (const float*)d_in[12];
    const float* Wrqi = (const float*)d_in[13];
    const float* gain = (const float*)d_in[14];
    float* out = (float*)d_out;

    static bool init_done = false;
    static cudaStream_t s1, s2;
    static cudaEvent_t evRoot, evSplit, evQ;
    if (!init_done) {
        cudaFuncSetAttribute(k_attn, cudaFuncAttributeMaxDynamicSharedMemorySize, 131072);
        cudaFuncSetAttribute(k_qgemm_mma, cudaFuncAttributeMaxDynamicSharedMemorySize, QSMEM);
        cudaFuncSetAttribute(k_dotgemm, cudaFuncAttributeMaxDynamicSharedMemorySize, DSMEM);
        cudaStreamCreateWithFlags(&s1, cudaStreamNonBlocking);
        cudaStreamCreateWithFlags(&s2, cudaStreamNonBlocking);
        cudaEventCreateWithFlags(&evRoot, cudaEventDisableTiming);
        cudaEventCreateWithFlags(&evSplit, cudaEventDisableTiming);
        cudaEventCreateWithFlags(&evQ, cudaEventDisableTiming);
        init_done = true;
    }

    cudaEventRecord(evRoot, 0);
    cudaStreamWaitEvent(s1, evRoot, 0);
    cudaStreamWaitEvent(s2, evRoot, 0);

    k_statsA<<<4096, 256>>>(z, Wsr, Wsi);               /* idx 0 (s0) */
    k_split<<<NT * NC / (256 * 8), 256, 0, s2>>>(z);    /* idx 1 (s2) */
    cudaEventRecord(evSplit, s2);
    k_build_bt<<<dim3(16, 16), 256, 0, s1>>>(Wrqr, Wrqi);  /* idx 2 (s1) */
    cudaStreamWaitEvent(s1, evSplit, 0);
    k_qgemm_mma<<<dim3(NC / BN, NT / BM), 512, QSMEM, s1>>>();  /* idx 3: profiled */
    cudaEventRecord(evQ, s1);
    k_runs<<<Bb, 256>>>(out, sb, ns);                   /* idx 4 (s0) */
    k_evec1<<<Bb * SS * 8, 256>>>(z, out);              /* idx 5 (s0) */
    k_ekv1<<<dim3(Bb, SS / 4, 8), 512>>>(Wekr, Weki, Wevr, Wevi);  /* idx 6 (s0) */
    k_ekv2<<<Bb * SS, 512>>>(sk, sv, sm, out);          /* idx 7 (s0) */
    k_udot1<<<dim3(Bb, SS / 8, 8), 512>>>(out);         /* idx 8 (s0) */
    k_udot2<<<Bb * SS, 512>>>();                        /* idx 9 (s0) */
    cudaStreamWaitEvent(0, evSplit, 0);                 /* dotgemm reads Ahi/Alo */
    k_dotgemm<<<NT / DM, 256, DSMEM>>>();               /* idx 10 (s0) */
    cudaStreamWaitEvent(0, evQ, 0);                     /* attn reads g_qp */
    k_attn<<<NT / 32, 1024, 131072>>>(out, gain);       /* idx 11 (s0) */
}

// round 16
// speedup vs baseline: 1.8332x; 1.0426x over previous
#include <cuda_runtime.h>
#include <cuda_fp16.h>
#include <math.h>
#include <stdint.h>

#define Bb   8
#define LL   4096
#define DIMC 512
#define SS   32
#define KK   8
#define NT   (Bb*LL)      /* 32768 tokens */
#define NC   (DIMC*2)     /* 1024 floats per token (interleaved r,i) */
#define THRv 0.5f
#define EPSv 1e-8f

/* output layout: concat(out, new_keys, new_values, new_mask, salience) */
#define OFF_OUT ((size_t)0)
#define OFF_NK  ((size_t)NT*NC)
#define OFF_NV  (OFF_NK + (size_t)Bb*SS*NC)
#define OFF_NM  (OFF_NV + (size_t)Bb*SS*NC)
#define OFF_SAL (OFF_NM + (size_t)Bb*SS)

/* scratch (device globals; no allocation allowed) */
__device__ float g_avg[NT];
__device__ float g_phase[NT];
__device__ float g_evp[(size_t)Bb*SS*8*NC];     /* evec chunk partials, 8MB */
__device__ float g_denp[Bb*SS*8];
__device__ float g_emask[Bb*SS];
__device__ int   g_rs[Bb*SS];
__device__ int   g_re[Bb*SS];
__device__ float g_kmag[Bb*SS];
__device__ float g_kvp[(size_t)Bb*SS*8*4*DIMC]; /* [bs][chunk8][KR,KI,VR,VI][e], 16MB */
__device__ float g_up[(size_t)Bb*SS*8*NC];      /* [bs][chunk8][ur,ui], 8MB */
__device__ __half g_BhiT[NC*NC];          /* B^T fp16, [n][k], 2MB */
__device__ __half g_Ahi[(size_t)NT*NC];   /* z hi fp16, 64MB */
__device__ __half g_Alo[(size_t)NT*NC];   /* z lo fp16, 64MB */
__device__ float g_WrT[DIMC*DIMC];        /* W_rq_r transposed, 1MB */
__device__ float g_WiT[DIMC*DIMC];        /* W_rq_i transposed, 1MB */
__device__ __half g_uh[Bb*SS*NC];         /* u hi fp16 */
__device__ __half g_ul[Bb*SS*NC];         /* u lo fp16 */
__device__ float g_qp[(size_t)NT*4];      /* qmag^2 partials per N-block */
__device__ float g_dot[(size_t)NT*SS];    /* dot[l,s], 4MB */

__device__ __forceinline__ float wred(float v) {
    #pragma unroll
    for (int o = 16; o; o >>= 1) v += __shfl_xor_sync(0xffffffffu, v, o);
    return v;
}

__device__ __forceinline__ float fsqrt(float x) {
    float y; asm("sqrt.approx.f32 %0, %1;" : "=f"(y) : "f"(x)); return y;
}
__device__ __forceinline__ float frcp(float x) {
    float y; asm("rcp.approx.f32 %0, %1;" : "=f"(y) : "f"(x)); return y;
}
__device__ __forceinline__ float frsqrt(float x) {
    float y; asm("rsqrt.approx.f32 %0, %1;" : "=f"(y) : "f"(x)); return y;
}

__device__ __forceinline__ void hsplit(float x, __half& h, __half& l) {
    h = __float2half_rn(x);
    l = __float2half_rn(x - __half2float(h));
}

__device__ __forceinline__ uint32_t smem_u32(const void* p) {
    uint32_t a;
    asm("{ .reg .u64 t; cvta.to.shared.u64 t, %1; cvt.u32.u64 %0, t; }"
        : "=r"(a) : "l"(p));
    return a;
}

__device__ __forceinline__ void ldsm4(uint32_t* r, uint32_t addr) {
    asm volatile("ldmatrix.sync.aligned.m8n8.x4.shared.b16 {%0,%1,%2,%3}, [%4];"
        : "=r"(r[0]), "=r"(r[1]), "=r"(r[2]), "=r"(r[3]) : "r"(addr));
}

__device__ __forceinline__ void mma16816(float* d, const uint32_t* a,
                                         uint32_t b0, uint32_t b1) {
    asm volatile(
        "mma.sync.aligned.m16n8k16.row.col.f32.f16.f16.f32 "
        "{%0,%1,%2,%3}, {%4,%5,%6,%7}, {%8,%9}, {%0,%1,%2,%3};"
        : "+f"(d[0]), "+f"(d[1]), "+f"(d[2]), "+f"(d[3])
        : "r"(a[0]), "r"(a[1]), "r"(a[2]), "r"(a[3]), "r"(b0), "r"(b1));
}

#define CP16(dst, src) \
    asm volatile("cp.async.cg.shared.global [%0], [%1], 16;" \
                 :: "r"(dst), "l"(src) : "memory")
#define CP_COMMIT() asm volatile("cp.async.commit_group;" ::: "memory")
#define CP_WAIT1()  asm volatile("cp.async.wait_group 1;" ::: "memory")

/* ------------------------------------------------------------------ */
/* per-token stats (avg mag + phase) — s0 critical path */
__global__ void k_statsA(const float* __restrict__ z,
                         const float* __restrict__ Wsr,
                         const float* __restrict__ Wsi) {
    int gw = (blockIdx.x * blockDim.x + threadIdx.x) >> 5;
    int lane = threadIdx.x & 31;
    if (gw >= NT) return;
    const float4* z4 = (const float4*)(z + (size_t)gw * NC);
    float ms = 0.f, pr = 0.f, pi = 0.f;
    #pragma unroll
    for (int i = 0; i < 8; i++) {
        int p = lane + 32 * i;
        float4 v = z4[p];
        int d = 2 * p;
        ms += fsqrt(v.x*v.x + v.y*v.y + EPSv) + fsqrt(v.z*v.z + v.w*v.w + EPSv);
        float wr0 = Wsr[d], wi0 = Wsi[d], wr1 = Wsr[d+1], wi1 = Wsi[d+1];
        pr += v.x*wr0 - v.y*wi0 + v.z*wr1 - v.w*wi1;
        pi += v.x*wi0 + v.y*wr0 + v.z*wi1 + v.w*wr1;
    }
    ms = wred(ms); pr = wred(pr); pi = wred(pi);
    if (lane == 0) {
        g_avg[gw]   = ms * (1.f / DIMC);
        g_phase[gw] = fsqrt(pr*pr + pi*pi + EPSv);
    }
}

/* z -> fp16 hi/lo (stream s2; depends only on input z) */
__global__ void k_split(const float* __restrict__ z) {
    size_t i = ((size_t)blockIdx.x * 256 + threadIdx.x) * 8;
    float4 v0 = *(const float4*)(z + i);
    float4 v1 = *(const float4*)(z + i + 4);
    __half h[8], l[8];
    hsplit(v0.x, h[0], l[0]); hsplit(v0.y, h[1], l[1]);
    hsplit(v0.z, h[2], l[2]); hsplit(v0.w, h[3], l[3]);
    hsplit(v1.x, h[4], l[4]); hsplit(v1.y, h[5], l[5]);
    hsplit(v1.z, h[6], l[6]); hsplit(v1.w, h[7], l[7]);
    *(uint4*)(g_Ahi + i) = *(uint4*)h;
    *(uint4*)(g_Alo + i) = *(uint4*)l;
}

/* ------------------------------------------------------------------ */
__global__ void k_build_bt(const float* __restrict__ Wr,
                           const float* __restrict__ Wi) {
    __shared__ float tr[32][33], ti[32][33];
    int tx = threadIdx.x & 31, ty = threadIdx.x >> 5;
    int d0 = blockIdx.x * 32, e0 = blockIdx.y * 32;
    #pragma unroll
    for (int j = 0; j < 4; j++) {
        int d = d0 + ty + 8 * j;
        tr[ty + 8 * j][tx] = Wr[(size_t)d * DIMC + e0 + tx];
        ti[ty + 8 * j][tx] = Wi[(size_t)d * DIMC + e0 + tx];
    }
    __syncthreads();
    #pragma unroll
    for (int j = 0; j < 4; j++) {
        int e = e0 + ty + 8 * j;
        int d = d0 + tx;
        float wr = tr[tx][ty + 8 * j], wi = ti[tx][ty + 8 * j];
        size_t r0 = (size_t)(2 * e) * NC, r1 = (size_t)(2 * e + 1) * NC;
        g_BhiT[r0 + 2*d]     = __float2half_rn(wr);
        g_BhiT[r0 + 2*d + 1] = __float2half_rn(-wi);
        g_BhiT[r1 + 2*d]     = __float2half_rn(wi);
        g_BhiT[r1 + 2*d + 1] = __float2half_rn(wr);
        g_WrT[(size_t)e * DIMC + d] = wr;
        g_WiT[(size_t)e * DIMC + d] = wi;
    }
}

/* ------------------------------------------------------------------ */
/* fused salience + run detection; parallel prefix scan */
__global__ void k_runs(float* __restrict__ out,
                       const float* __restrict__ sb,
                       const float* __restrict__ ns) {
    __shared__ float sal[LL];
    __shared__ int scnt[256];
    int b = blockIdx.x, tid = threadIdx.x;
    float nsv = ns[0], sbv = sb[0];

    int l0 = tid * 16;
    for (int j = 0; j < 16; j++) {
        int l = l0 + j;
        int i = b * LL + l;
        float lm = 0.f;
        #pragma unroll
        for (int o = -2; o <= 2; o++) {
            int ll = l + o;
            if (ll >= 0 && ll < LL) lm += g_avg[i + o];
        }
        lm *= 0.2f;
        float x = g_phase[i] + (g_avg[i] - lm) * nsv + sbv;
        float s = frcp(1.f + __expf(-x));
        sal[l] = s;
        out[OFF_SAL + i] = s;
    }
    if (tid < SS) { g_rs[b*SS+tid] = 0; g_re[b*SS+tid] = 0; g_emask[b*SS+tid] = 0.f; }
    __syncthreads();

    bool prev0 = (l0 > 0) && (sal[l0 - 1] > THRv);
    bool pa = prev0;
    int cnt = 0;
    for (int j = 0; j < 16; j++) {
        bool ab = sal[l0 + j] > THRv;
        cnt += (ab && !pa);
        pa = ab;
    }
    scnt[tid] = cnt;
    __syncthreads();
    #pragma unroll
    for (int off = 1; off < 256; off <<= 1) {
        int add = (tid >= off) ? scnt[tid - off] : 0;
        __syncthreads();
        scnt[tid] += add;
        __syncthreads();
    }
    int e = scnt[tid] - cnt;
    pa = prev0;
    for (int j = 0; j < 16; j++) {
        int l = l0 + j;
        bool ab = sal[l] > THRv;
        if (ab && !pa) {
            if (e < SS) { g_rs[b*SS + e] = l; g_emask[b*SS + e] = 1.f; }
            e++;
        }
        if (ab && (e - 1) < SS) {
            bool nx = (l + 1 < LL) && (sal[l + 1] > THRv);
            if (!nx) g_re[b*SS + (e - 1)] = l + 1;
        }
        pa = ab;
    }
}

/* event vector partials: 8 chunk-blocks per run */
__global__ void k_evec1(const float* __restrict__ z,
                        const float* __restrict__ out) {
    int bs = blockIdx.x >> 3, ch = blockIdx.x & 7;
    int b = bs / SS;
    int rs = g_rs[bs], re = g_re[bs];
    int len = re - rs;
    int clen = (len + 7) >> 3;
    int ls = rs + ch * clen;
    int le = min(ls + clen, re);
    const float* sal = out + OFF_SAL + (size_t)b * LL;
    int t = threadIdx.x;
    float a0 = 0.f, a1 = 0.f, a2 = 0.f, a3 = 0.f, den = 0.f;
    for (int l = ls; l < le; l++) {
        float w = sal[l];
        den += w;
        const float* zt = z + ((size_t)b * LL + l) * NC;
        a0 += w * zt[t];       a1 += w * zt[t + 256];
        a2 += w * zt[t + 512]; a3 += w * zt[t + 768];
    }
    float* ev = g_evp + (size_t)(bs * 8 + ch) * NC;
    ev[t] = a0; ev[t + 256] = a1; ev[t + 512] = a2; ev[t + 768] = a3;
    if (t == 0) g_denp[bs * 8 + ch] = den;
}

/* ------------------------------------------------------------------ */
/* event K/V projection partials: grid (Bb, SS/4, 8 d-chunks), 512 thr. */
__global__ void __launch_bounds__(512, 2)
k_ekv1(const float* __restrict__ Wekr, const float* __restrict__ Weki,
       const float* __restrict__ Wevr, const float* __restrict__ Wevi) {
    int b = blockIdx.x, sg = blockIdx.y, dc = blockIdx.z;
    int e = threadIdx.x;
    int bs0 = b * SS + sg * 4;
    int d0 = dc * 64;
    __shared__ float sv[4][128];    /* evec dims [2*d0, 2*d0+128) */
    __shared__ float sinv[4];
    if (e < 4) {
        float den = 0.f;
        #pragma unroll
        for (int ch = 0; ch < 8; ch++) den += g_denp[(bs0 + e) * 8 + ch];
        sinv[e] = frcp(fmaxf(den, EPSv));
    }
    __syncthreads();
    if (e < 4 * 128) {
        int slot = e >> 7, dim = e & 127;
        float a = 0.f;
        #pragma unroll
        for (int ch = 0; ch < 8; ch++)
            a += g_evp[(size_t)((bs0 + slot) * 8 + ch) * NC + 2 * d0 + dim];
        sv[slot][dim] = a * sinv[slot];
    }
    __syncthreads();

    float KR[4] = {0,0,0,0}, KI[4] = {0,0,0,0};
    float VR[4] = {0,0,0,0}, VI[4] = {0,0,0,0};
    #pragma unroll 4
    for (int dd = 0; dd < 64; dd++) {
        int d = d0 + dd;
        float wkr = Wekr[(size_t)d * DIMC + e], wki = Weki[(size_t)d * DIMC + e];
        float wvr = Wevr[(size_t)d * DIMC + e], wvi = Wevi[(size_t)d * DIMC + e];
        #pragma unroll
        for (int s2 = 0; s2 < 4; s2++) {
            float zr = sv[s2][2 * dd], zi = sv[s2][2 * dd + 1];
            KR[s2] += zr * wkr - zi * wki;
            KI[s2] += zr * wki + zi * wkr;
            VR[s2] += zr * wvr - zi * wvi;
            VI[s2] += zr * wvi + zi * wvr;
        }
    }
    #pragma unroll
    for (int s2 = 0; s2 < 4; s2++) {
        float* p = g_kvp + (size_t)((bs0 + s2) * 8 + dc) * (4 * DIMC);
        p[e]            = KR[s2];
        p[DIMC + e]     = KI[s2];
        p[2 * DIMC + e] = VR[s2];
        p[3 * DIMC + e] = VI[s2];
    }
}

/* combine + blend + kmag + mask: grid (Bb*SS), 512 thr (thread = e) */
__global__ void __launch_bounds__(512, 2)
k_ekv2(const float* __restrict__ sk, const float* __restrict__ svv,
       const float* __restrict__ smk, float* __restrict__ out) {
    __shared__ float wpart[16];
    int bs = blockIdx.x, e = threadIdx.x;
    float kr = 0.f, ki = 0.f, vr = 0.f, vi = 0.f;
    #pragma unroll
    for (int dc = 0; dc < 8; dc++) {
        const float* p = g_kvp + (size_t)(bs * 8 + dc) * (4 * DIMC);
        kr += p[e]; ki += p[DIMC + e]; vr += p[2*DIMC + e]; vi += p[3*DIMC + e];
    }
    float m = g_emask[bs];
    size_t off = (size_t)bs * NC + 2 * e;
    float nkr = m * kr + (1.f - m) * sk[off];
    float nki = m * ki + (1.f - m) * sk[off + 1];
    float nvr = m * vr + (1.f - m) * svv[off];
    float nvi = m * vi + (1.f - m) * svv[off + 1];
    out[OFF_NK + off] = nkr; out[OFF_NK + off + 1] = nki;
    out[OFF_NV + off] = nvr; out[OFF_NV + off + 1] = nvi;
    if (e == 0) out[OFF_NM + bs] = fminf(smk[bs] + m, 1.f);
    float p = wred(nkr * nkr + nki * nki);
    int lane = e & 31, wid = e >> 5;
    if (lane == 0) wpart[wid] = p;
    __syncthreads();
    if (e == 0) {
        float sum = 0.f;
        #pragma unroll
        for (int i = 0; i < 16; i++) sum += wpart[i];
        g_kmag[bs] = fsqrt(sum + EPSv);
    }
}

/* ------------------------------------------------------------------ */
/* u partials: grid (Bb, SS/8, 8 j-chunks), 512 thr */
__global__ void __launch_bounds__(512, 2)
k_udot1(const float* __restrict__ out) {
    __shared__ float ka[8][128];
    int b = blockIdx.x, sg = blockIdx.y, jc = blockIdx.z;
    int tid = threadIdx.x;
    int j0 = jc * 64;
    const float* ksrc = out + OFF_NK + (size_t)(b * SS + sg * 8) * NC + 2 * j0;
    for (int i = tid; i < 8 * 128; i += 512) {
        int row = i >> 7, col = i & 127;
        ka[row][col] = ksrc[(size_t)row * NC + col];
    }
    __syncthreads();
    int e = tid;
    float ur[8], ui[8];
    #pragma unroll
    for (int s = 0; s < 8; s++) { ur[s] = 0.f; ui[s] = 0.f; }
    #pragma unroll 4
    for (int jj = 0; jj < 64; jj++) {
        int j = j0 + jj;
        float wr = g_WrT[(size_t)j * DIMC + e];
        float wi = g_WiT[(size_t)j * DIMC + e];
        #pragma unroll
        for (int s = 0; s < 8; s++) {
            float2 kp = *(const float2*)&ka[s][2 * jj];
            ur[s] += wr * kp.x + wi * kp.y;
            ui[s] += wr * kp.y - wi * kp.x;
        }
    }
    #pragma unroll
    for (int s = 0; s < 8; s++) {
        int bs = b * SS + sg * 8 + s;
        float* p = g_up + (size_t)(bs * 8 + jc) * NC;
        p[2 * e]     = ur[s];
        p[2 * e + 1] = ui[s];
    }
}

/* combine u partials + hsplit to fp16: grid (Bb*SS), 512 thr */
__global__ void k_udot2() {
    int bs = blockIdx.x, e = threadIdx.x;
    float ur = 0.f, ui = 0.f;
    #pragma unroll
    for (int jc = 0; jc < 8; jc++) {
        const float* p = g_up + (size_t)(bs * 8 + jc) * NC;
        ur += p[2 * e]; ui += p[2 * e + 1];
    }
    __half hr, lr, hi2, li;
    hsplit(ur, hr, lr);
    hsplit(ui, hi2, li);
    ((__half2*)(g_uh + (size_t)bs * NC))[e] = __halves2half2(hr, hi2);
    ((__half2*)(g_ul + (size_t)bs * NC))[e] = __halves2half2(lr, li);
}

/* ------------------------------------------------------------------ */
/* qmag GEMM: single-term fp16, BM=128 BN=256 BK=32, 512 thr, 3-stage
   (reverted to R9-R13 configuration: 164us, tensor 69.5%). */
#define BM 128
#define BN 256
#define PITCH 80
#define A_SZ (BM * PITCH)
#define B_SZ (BN * PITCH)
#define STAGE_SZ (A_SZ + B_SZ)
#define QSMEM (3 * STAGE_SZ)          /* 92160 */
#define NIT (NC / 32)

__global__ void __launch_bounds__(512, 1)
k_qgemm_mma() {
    extern __shared__ unsigned char smq[];
    __shared__ float qp_sm[4][BM];
    int t = threadIdx.x, lane = t & 31, wid = t >> 5;
    int m0 = blockIdx.y * BM, n0 = blockIdx.x * BN;
    int warpM = (wid & 3) * 32, warpN = (wid >> 2) * 64;

    uint32_t sb0 = smem_u32(smq);
    const uint4* srcA = (const uint4*)(g_Ahi  + (size_t)(m0 + (t >> 2)) * NC) + (t & 3);
    int bi0 = t, bi1 = t + 512;
    const uint4* srcB0 = (const uint4*)(g_BhiT + (size_t)(n0 + (bi0 >> 2)) * NC) + (bi0 & 3);
    const uint4* srcB1 = (const uint4*)(g_BhiT + (size_t)(n0 + (bi1 >> 2)) * NC) + (bi1 & 3);
    uint32_t dstA  = sb0 + (uint32_t)((t >> 2) * PITCH + (t & 3) * 16);
    uint32_t dstB0 = sb0 + (uint32_t)(A_SZ + (bi0 >> 2) * PITCH + (bi0 & 3) * 16);
    uint32_t dstB1 = sb0 + (uint32_t)(A_SZ + (bi1 >> 2) * PITCH + (bi1 & 3) * 16);

    uint32_t aoff = (uint32_t)((warpM + (lane & 15)) * PITCH + ((lane >> 4) << 4));
    uint32_t boff = (uint32_t)(A_SZ + (warpN + (lane & 7) + ((lane >> 4) & 1) * 8) * PITCH
                               + (((lane >> 3) & 1) << 4));

    float acc[2][8][4];
    #pragma unroll
    for (int i = 0; i < 2; i++)
        #pragma unroll
        for (int j = 0; j < 8; j++)
            #pragma unroll
            for (int k = 0; k < 4; k++) acc[i][j][k] = 0.f;

    #pragma unroll
    for (int s = 0; s < 2; s++) {
        uint32_t off = (uint32_t)(s * STAGE_SZ);
        CP16(dstA + off,  srcA  + s * 4);
        CP16(dstB0 + off, srcB0 + s * 4);
        CP16(dstB1 + off, srcB1 + s * 4);
        CP_COMMIT();
    }

    for (int it = 0; it < NIT; it++) {
        CP_WAIT1();
        __syncthreads();
        uint32_t st = sb0 + (uint32_t)((it % 3) * STAGE_SZ);
        uint32_t aAh = st + aoff;
        uint32_t aBh = st + boff;

        #pragma unroll
        for (int ko = 0; ko < 2; ko++) {
            uint32_t ah[2][4], bh[4][4];
            #pragma unroll
            for (int mg = 0; mg < 2; mg++)
                ldsm4(ah[mg], aAh + mg * (16 * PITCH) + ko * 32);
            #pragma unroll
            for (int ng = 0; ng < 4; ng++)
                ldsm4(bh[ng], aBh + ng * (16 * PITCH) + ko * 32);
            #pragma unroll
            for (int mg = 0; mg < 2; mg++)
                #pragma unroll
                for (int ng = 0; ng < 4; ng++)
                    #pragma unroll
                    for (int h = 0; h < 2; h++)
                        mma16816(acc[mg][ng * 2 + h], ah[mg],
                                 bh[ng][h*2], bh[ng][h*2+1]);
        }

        if (it + 2 < NIT) {
            uint32_t off = (uint32_t)(((it + 2) % 3) * STAGE_SZ);
            CP16(dstA + off,  srcA  + (it + 2) * 4);
            CP16(dstB0 + off, srcB0 + (it + 2) * 4);
            CP16(dstB1 + off, srcB1 + (it + 2) * 4);
        }
        CP_COMMIT();
    }

    #pragma unroll
    for (int mg = 0; mg < 2; mg++) {
        float rp0 = 0.f, rp1 = 0.f;
        #pragma unroll
        for (int j = 0; j < 8; j++) {
            float* d = acc[mg][j];
            rp0 += d[0]*d[0] + d[1]*d[1];
            rp1 += d[2]*d[2] + d[3]*d[3];
        }
        rp0 += __shfl_xor_sync(0xffffffffu, rp0, 1);
        rp0 += __shfl_xor_sync(0xffffffffu, rp0, 2);
        rp1 += __shfl_xor_sync(0xffffffffu, rp1, 1);
        rp1 += __shfl_xor_sync(0xffffffffu, rp1, 2);
        if ((lane & 3) == 0) {
            int r = warpM + mg * 16 + (lane >> 2);
            qp_sm[wid >> 2][r]     = rp0;
            qp_sm[wid >> 2][r + 8] = rp1;
        }
    }
    __syncthreads();
    if (t < BM)
        g_qp[(size_t)(m0 + t) * 4 + blockIdx.x] =
            qp_sm[0][t] + qp_sm[1][t] + qp_sm[2][t] + qp_sm[3][t];
}

/* ------------------------------------------------------------------ */
/* dot GEMM: dot[l,s] = z_l . u_s, 3-term fp16 (hh+hl+lh). */
#define DM 128
#define DA_SZ (DM * PITCH)
#define DSTG (2 * DA_SZ)
#define PB 2064
#define B_HL (SS * PB)
#define DB_OFF (3 * DSTG)
#define DSMEM (DB_OFF + 2 * B_HL)
#define NITD (NC / 32)

__global__ void __launch_bounds__(256, 1)
k_dotgemm() {
    extern __shared__ unsigned char smd[];
    int t = threadIdx.x, lane = t & 31, wid = t >> 5;
    int m0 = blockIdx.x * DM;
    int batch = blockIdx.x >> 5;
    int warpM = wid * 16;

    uint32_t sb0 = smem_u32(smd);

    #pragma unroll
    for (int u = 0; u < 16; u++) {
        int idx = t + 256 * u;
        int row = idx >> 7, col = idx & 127;
        uint32_t d0 = sb0 + (uint32_t)(DB_OFF + row * PB + col * 16);
        const uint4* sh = (const uint4*)(g_uh + (size_t)(batch * SS + row) * NC) + col;
        const uint4* sl = (const uint4*)(g_ul + (size_t)(batch * SS + row) * NC) + col;
        CP16(d0, sh);
        CP16(d0 + B_HL, sl);
    }
    int ai0 = t, ai1 = t + 256;
    const uint4* sAh0 = (const uint4*)(g_Ahi + (size_t)(m0 + (ai0 >> 2)) * NC) + (ai0 & 3);
    const uint4* sAh1 = (const uint4*)(g_Ahi + (size_t)(m0 + (ai1 >> 2)) * NC) + (ai1 & 3);
    const uint4* sAl0 = (const uint4*)(g_Alo + (size_t)(m0 + (ai0 >> 2)) * NC) + (ai0 & 3);
    const uint4* sAl1 = (const uint4*)(g_Alo + (size_t)(m0 + (ai1 >> 2)) * NC) + (ai1 & 3);
    uint32_t dA0 = sb0 + (uint32_t)((ai0 >> 2) * PITCH + (ai0 & 3) * 16);
    uint32_t dA1 = sb0 + (uint32_t)((ai1 >> 2) * PITCH + (ai1 & 3) * 16);

    #pragma unroll
    for (int s = 0; s < 2; s++) {
        uint32_t off = (uint32_t)(s * DSTG);
        CP16(dA0 + off, sAh0 + s * 4);          CP16(dA1 + off, sAh1 + s * 4);
        CP16(dA0 + off + DA_SZ, sAl0 + s * 4);  CP16(dA1 + off + DA_SZ, sAl1 + s * 4);
        CP_COMMIT();
    }

    uint32_t aoff = (uint32_t)((warpM + (lane & 15)) * PITCH + ((lane >> 4) << 4));
    uint32_t boffB = (uint32_t)(DB_OFF + ((lane & 7) + ((lane >> 4) & 1) * 8) * PB
                                + (((lane >> 3) & 1) << 4));

    float acc[4][4];
    #pragma unroll
    for (int j = 0; j < 4; j++)
        #pragma unroll
        for (int k = 0; k < 4; k++) acc[j][k] = 0.f;

    for (int it = 0; it < NITD; it++) {
        CP_WAIT1();
        __syncthreads();
        uint32_t st = sb0 + (uint32_t)((it % 3) * DSTG);
        #pragma unroll
        for (int ko = 0; ko < 2; ko++) {
            uint32_t ah[4], al[4], bh[2][4], bl[2][4];
            ldsm4(ah, st + aoff + ko * 32);
            ldsm4(al, st + DA_SZ + aoff + ko * 32);
            #pragma unroll
            for (int ng = 0; ng < 2; ng++) {
                uint32_t ba = sb0 + boffB + ng * (16 * PB) + it * 64 + ko * 32;
                ldsm4(bh[ng], ba);
                ldsm4(bl[ng], ba + B_HL);
            }
            #pragma unroll
            for (int ng = 0; ng < 2; ng++)
                #pragma unroll
                for (int h = 0; h < 2; h++) {
                    float* d = acc[ng * 2 + h];
                    mma16816(d, al, bh[ng][h*2], bh[ng][h*2+1]);
                    mma16816(d, ah, bl[ng][h*2], bl[ng][h*2+1]);
                    mma16816(d, ah, bh[ng][h*2], bh[ng][h*2+1]);
                }
        }
        if (it + 2 < NITD) {
            uint32_t off = (uint32_t)(((it + 2) % 3) * DSTG);
            CP16(dA0 + off, sAh0 + (it + 2) * 4);          CP16(dA1 + off, sAh1 + (it + 2) * 4);
            CP16(dA0 + off + DA_SZ, sAl0 + (it + 2) * 4);  CP16(dA1 + off + DA_SZ, sAl1 + (it + 2) * 4);
        }
        CP_COMMIT();
    }

    #pragma unroll
    for (int j = 0; j < 4; j++) {
        float* d = acc[j];
        int r = m0 + warpM + (lane >> 2);
        int c = j * 8 + (lane & 3) * 2;
        *(float2*)&g_dot[(size_t)r * SS + c]       = make_float2(d[0], d[1]);
        *(float2*)&g_dot[(size_t)(r + 8) * SS + c] = make_float2(d[2], d[3]);
    }
}

/* ------------------------------------------------------------------ */
/* attention: warp/token, 32 tokens/block (1024 thr); V staged in smem. */
__global__ void __launch_bounds__(1024, 1)
k_attn(float* __restrict__ out, const float* __restrict__ gain) {
    extern __shared__ float4 sV[];
    __shared__ float sKmag[SS];
    __shared__ float sMask[SS];
    int tid = threadIdx.x, warp = tid >> 5, lane = tid & 31;
    int tok0 = blockIdx.x * 32;
    int b = tok0 / LL;

    const float4* Vsrc = (const float4*)(out + OFF_NV + (size_t)b * SS * NC);
    for (int i = tid; i < SS * NC / 4; i += 1024) sV[i] = Vsrc[i];
    if (tid < SS) {
        sKmag[tid] = g_kmag[b * SS + tid];
        sMask[tid] = out[OFF_NM + b * SS + tid];
    }
    __syncthreads();

    int token = tok0 + warp;
    float qp = (lane < 4) ? g_qp[(size_t)token * 4 + lane] : 0.f;
    qp = wred(qp);
    float qmag = fsqrt(qp + EPSv);

    float dval = g_dot[(size_t)token * SS + lane];
    float myscore = dval * frcp(qmag * sKmag[lane] + EPSv);
    if (sMask[lane] == 0.f) myscore = -1e9f;

    float vcur = myscore;
    float topv[KK]; int topi[KK];
    #pragma unroll
    for (int j = 0; j < KK; j++) {
        float v = vcur; int idx = lane;
        #pragma unroll
        for (int o = 16; o; o >>= 1) {
            float v2 = __shfl_xor_sync(0xffffffffu, v, o);
            int   i2 = __shfl_xor_sync(0xffffffffu, idx, o);
            if (v2 > v || (v2 == v && i2 < idx)) { v = v2; idx = i2; }
        }
        topv[j] = v; topi[j] = idx;
        if (lane == idx) vcur = -INFINITY;
    }
    float w[KK], wsum = 0.f, mx = topv[0];
    #pragma unroll
    for (int j = 0; j < KK; j++) { w[j] = __expf(topv[j] - mx); wsum += w[j]; }
    float winv = frcp(wsum);

    float4 r[8];
    #pragma unroll
    for (int i = 0; i < 8; i++) r[i] = make_float4(0.f, 0.f, 0.f, 0.f);
    #pragma unroll
    for (int j = 0; j < KK; j++) {
        float a = w[j] * winv;
        const float4* Vr = sV + topi[j] * 256;
        #pragma unroll
        for (int i = 0; i < 8; i++) {
            float4 vv = Vr[lane + 32 * i];
            r[i].x += a * vv.x; r[i].y += a * vv.y;
            r[i].z += a * vv.z; r[i].w += a * vv.w;
        }
    }
    float ssum = 0.f;
    #pragma unroll
    for (int i = 0; i < 8; i++)
        ssum += r[i].x*r[i].x + r[i].y*r[i].y + r[i].z*r[i].z + r[i].w*r[i].w;
    ssum = wred(ssum);
    float rinv = frsqrt(ssum * (1.f / DIMC) + EPSv);

    const float2* g2 = (const float2*)gain;
    float4* orow = (float4*)(out + (size_t)token * NC);
    #pragma unroll
    for (int i = 0; i < 8; i++) {
        float2 g = g2[lane + 32 * i];
        float4 o;
        o.x = r[i].x * rinv * g.x; o.y = r[i].y * rinv * g.x;
        o.z = r[i].z * rinv * g.y; o.w = r[i].w * rinv * g.y;
        orow[lane + 32 * i] = o;
    }
}

/* ------------------------------------------------------------------ */
extern "C" void kernel_launch(void* const* d_in, const int* in_sizes, int n_in,
                              void* d_out, int out_size) {
    const float* z    = (const float*)d_in[0];
    const float* sk   = (const float*)d_in[1];
    const float* sv   = (const float*)d_in[2];
    const float* sm   = (const float*)d_in[3];
    const float* Wsr  = (const float*)d_in[4];
    const float* Wsi  = (const float*)d_in[5];
    const float* sb   = (const float*)d_in[6];
    const float* ns   = (const float*)d_in[7];
    const float* Wekr = (const float*)d_in[8];
    const float* Weki = (const float*)d_in[9];
    const float* Wevr = (const float*)d_in[10];
    const float* Wevi = (const float*)d_in[11];
    const float* Wrqr = (const float*)d_in[12];
    const float* Wrqi = (const float*)d_in[13];
    const float* gain = (const float*)d_in[14];
    float* out = (float*)d_out;

    static bool init_done = false;
    static cudaStream_t s1, s2;
    static cudaEvent_t evRoot, evSplit, evQ;
    if (!init_done) {
        cudaFuncSetAttribute(k_attn, cudaFuncAttributeMaxDynamicSharedMemorySize, 131072);
        cudaFuncSetAttribute(k_qgemm_mma, cudaFuncAttributeMaxDynamicSharedMemorySize, QSMEM);
        cudaFuncSetAttribute(k_dotgemm, cudaFuncAttributeMaxDynamicSharedMemorySize, DSMEM);
        cudaStreamCreateWithFlags(&s1, cudaStreamNonBlocking);
        cudaStreamCreateWithFlags(&s2, cudaStreamNonBlocking);
        cudaEventCreateWithFlags(&evRoot, cudaEventDisableTiming);
        cudaEventCreateWithFlags(&evSplit, cudaEventDisableTiming);
        cudaEventCreateWithFlags(&evQ, cudaEventDisableTiming);
        init_done = true;
    }

    cudaEventRecord(evRoot, 0);
    cudaStreamWaitEvent(s1, evRoot, 0);
    cudaStreamWaitEvent(s2, evRoot, 0);

    k_statsA<<<4096, 256>>>(z, Wsr, Wsi);               /* idx 0 (s0) */
    k_split<<<NT * NC / (256 * 8), 256, 0, s2>>>(z);    /* idx 1 (s2) */
    cudaEventRecord(evSplit, s2);
    k_build_bt<<<dim3(16, 16), 256, 0, s1>>>(Wrqr, Wrqi);  /* idx 2 (s1) */
    cudaStreamWaitEvent(s1, evSplit, 0);
    k_qgemm_mma<<<dim3(NC / BN, NT / BM), 512, QSMEM, s1>>>();  /* idx 3: profiled */
    cudaEventRecord(evQ, s1);
    k_runs<<<Bb, 256>>>(out, sb, ns);                   /* idx 4 (s0) */
    k_evec1<<<Bb * SS * 8, 256>>>(z, out);              /* idx 5 (s0) */
    k_ekv1<<<dim3(Bb, SS / 4, 8), 512>>>(Wekr, Weki, Wevr, Wevi);  /* idx 6 (s0) */
    k_ekv2<<<Bb * SS, 512>>>(sk, sv, sm, out);          /* idx 7 (s0) */
    k_udot1<<<dim3(Bb, SS / 8, 8), 512>>>(out);         /* idx 8 (s0) */
    k_udot2<<<Bb * SS, 512>>>();                        /* idx 9 (s0) */
    cudaStreamWaitEvent(0, evSplit, 0);                 /* dotgemm reads Ahi/Alo */
    k_dotgemm<<<NT / DM, 256, DSMEM>>>();               /* idx 10 (s0) */
    cudaStreamWaitEvent(0, evQ, 0);                     /* attn reads g_qp */
    k_attn<<<NT / 32, 1024, 131072>>>(out, gain);       /* idx 11 (s0) */
}